// round 10
// baseline (speedup 1.0000x reference)
#include <cuda_runtime.h>
#include <cuda_bf16.h>
#include <cstdint>

// Problem constants
#define B_ 4
#define T_ 2048
#define C_ 1024
#define H_ 16
#define D_ 64
#define M_ (B_ * T_)   // 8192 rows

// ---------------------------------------------------------------------------
// Scratch (allocation-free rule: __device__ globals)
// ---------------------------------------------------------------------------
__device__ __align__(16) __nv_bfloat16 g_Xhi[(size_t)M_ * C_];
__device__ __align__(16) __nv_bfloat16 g_Xlo[(size_t)M_ * C_];
__device__ __align__(16) __nv_bfloat16 g_Wh[(size_t)3 * C_ * C_];
__device__ __align__(16) __nv_bfloat16 g_Wl[(size_t)3 * C_ * C_];
__device__ __align__(16) __nv_bfloat16 g_Wohi[(size_t)C_ * C_];
__device__ __align__(16) __nv_bfloat16 g_Wolo[(size_t)C_ * C_];
__device__ __align__(16) __nv_bfloat16 g_Yhi[(size_t)M_ * C_];
__device__ __align__(16) __nv_bfloat16 g_Ylo[(size_t)M_ * C_];
__device__ __align__(16) __nv_bfloat16 g_Qhi[(size_t)B_ * H_ * T_ * D_];
__device__ __align__(16) __nv_bfloat16 g_Qlo[(size_t)B_ * H_ * T_ * D_];
__device__ __align__(16) __nv_bfloat16 g_Khi[(size_t)B_ * H_ * T_ * D_];
__device__ __align__(16) __nv_bfloat16 g_Klo[(size_t)B_ * H_ * T_ * D_];
__device__ __align__(16) __nv_bfloat16 g_Vhi[(size_t)B_ * H_ * T_ * D_];
__device__ __align__(16) __nv_bfloat16 g_Vlo[(size_t)B_ * H_ * T_ * D_];

// ---------------------------------------------------------------------------
// Helpers
// ---------------------------------------------------------------------------
__device__ __forceinline__ uint32_t smem_u32(const void* p) {
    uint32_t a;
    asm("{ .reg .u64 t; cvta.to.shared.u64 t, %1; cvt.u32.u64 %0, t; }"
        : "=r"(a) : "l"(p));
    return a;
}

#define CP_ASYNC16(dst, src) \
    asm volatile("cp.async.cg.shared.global [%0], [%1], 16;" \
                 :: "r"(dst), "l"(src) : "memory")
#define CP_COMMIT()  asm volatile("cp.async.commit_group;" ::: "memory")
#define CP_WAIT(n)   asm volatile("cp.async.wait_group %0;" :: "n"(n) : "memory")

#define LDSM_X4(r0, r1, r2, r3, addr) \
    asm volatile("ldmatrix.sync.aligned.m8n8.x4.shared.b16 {%0,%1,%2,%3}, [%4];" \
                 : "=r"(r0), "=r"(r1), "=r"(r2), "=r"(r3) : "r"(addr))

#define LDSM_X4_T(r0, r1, r2, r3, addr) \
    asm volatile("ldmatrix.sync.aligned.m8n8.x4.trans.shared.b16 {%0,%1,%2,%3}, [%4];" \
                 : "=r"(r0), "=r"(r1), "=r"(r2), "=r"(r3) : "r"(addr))

#define MMA16816(d, a, b0, b1) \
    asm volatile("mma.sync.aligned.m16n8k16.row.col.f32.bf16.bf16.f32 " \
                 "{%0,%1,%2,%3}, {%4,%5,%6,%7}, {%8,%9}, {%0,%1,%2,%3};" \
                 : "+f"((d)[0]), "+f"((d)[1]), "+f"((d)[2]), "+f"((d)[3]) \
                 : "r"((a)[0]), "r"((a)[1]), "r"((a)[2]), "r"((a)[3]), \
                   "r"(b0), "r"(b1))

__device__ __forceinline__ uint32_t pack2(__nv_bfloat16 a, __nv_bfloat16 b) {
    __nv_bfloat162 v = __halves2bfloat162(a, b);
    return *reinterpret_cast<uint32_t*>(&v);
}

__device__ __forceinline__ __nv_bfloat162 split_hi2(float x, float y,
                                                    __nv_bfloat162* lo) {
    __nv_bfloat16 h0 = __float2bfloat16_rn(x);
    __nv_bfloat16 h1 = __float2bfloat16_rn(y);
    *lo = __halves2bfloat162(__float2bfloat16_rn(x - __bfloat162float(h0)),
                             __float2bfloat16_rn(y - __bfloat162float(h1)));
    return __halves2bfloat162(h0, h1);
}

// ---------------------------------------------------------------------------
// fp32 -> bf16 hi/lo split
// ---------------------------------------------------------------------------
__global__ __launch_bounds__(256)
void cvt_kernel(const float* __restrict__ in, __nv_bfloat16* __restrict__ hi,
                __nv_bfloat16* __restrict__ lo, int n4)
{
    int i = blockIdx.x * 256 + threadIdx.x;
    if (i >= n4) return;
    float4 v = ((const float4*)in)[i];
    __nv_bfloat162 l01, l23;
    __nv_bfloat162 h01 = split_hi2(v.x, v.y, &l01);
    __nv_bfloat162 h23 = split_hi2(v.z, v.w, &l23);
    ((__nv_bfloat162*)hi)[2 * i]     = h01;
    ((__nv_bfloat162*)hi)[2 * i + 1] = h23;
    ((__nv_bfloat162*)lo)[2 * i]     = l01;
    ((__nv_bfloat162*)lo)[2 * i + 1] = l23;
}

// ---------------------------------------------------------------------------
// HMMA bf16 GEMM v2 (extended-K hi/lo split), BM=128, BN=256, BK=64,
// 3-stage cp.async pipeline. 8 warps: 4(M) x 2(N), warp tile 32x128.
// MODE 0: fp32 [M,N] + bias.   MODE 1: bf16 hi/lo split-head [b,h,t,d].
// smem/stage: A 16KB + B 32KB = 48KB;  3 stages = 144KB.
// ---------------------------------------------------------------------------
#define NKCH 48
#define G_STAGE 49152
#define G_SMEM  (3 * G_STAGE)

__device__ __forceinline__
void issue_chunk(uint32_t sbase, const __nv_bfloat16* __restrict__ Aseg,
                 const __nv_bfloat16* __restrict__ Bseg,
                 int m0, int n0, int k_in, int t)
{
#pragma unroll
    for (int rep = 0; rep < 4; rep++) {          // A: 128 rows x 8 slots
        int idx = t + rep * 256;
        int r = idx >> 3, s = idx & 7;
        uint32_t dst = sbase + r * 128 + ((s ^ (r & 7)) << 4);
        CP_ASYNC16(dst, (const void*)(Aseg + (size_t)(m0 + r) * C_ + k_in + s * 8));
    }
#pragma unroll
    for (int rep = 0; rep < 8; rep++) {          // B: 256 rows x 8 slots
        int idx = t + rep * 256;
        int r = idx >> 3, s = idx & 7;
        uint32_t dst = sbase + 16384 + r * 128 + ((s ^ (r & 7)) << 4);
        CP_ASYNC16(dst, (const void*)(Bseg + (size_t)(n0 + r) * C_ + k_in + s * 8));
    }
}

__device__ __forceinline__
void seg_sel(int kn, const __nv_bfloat16* Ahi, const __nv_bfloat16* Alo,
             const __nv_bfloat16* Whi, const __nv_bfloat16* Wlo,
             const __nv_bfloat16** Aseg, const __nv_bfloat16** Bseg)
{
    *Aseg = (kn < 32) ? Ahi : Alo;
    *Bseg = (kn < 16) ? Whi : (kn < 32 ? Wlo : Whi);
}

template <int MODE>
__device__ __forceinline__
void hmma_gemm_body(const __nv_bfloat16* __restrict__ Ahi,
                    const __nv_bfloat16* __restrict__ Alo,
                    const __nv_bfloat16* __restrict__ Whi,
                    const __nv_bfloat16* __restrict__ Wlo,
                    const float* __restrict__ bias, float* __restrict__ out,
                    __nv_bfloat16* __restrict__ ohi, __nv_bfloat16* __restrict__ olo)
{
    extern __shared__ __align__(128) char sm[];
    const uint32_t sm0 = smem_u32(sm);
    const int t    = threadIdx.x;
    const int lane = t & 31;
    const int w    = t >> 5;
    const int wm   = w & 3;             // m offset 32*wm
    const int wn   = w >> 2;            // n offset 128*wn
    const int m0   = blockIdx.y * 128;
    const int n0   = blockIdx.x * 256;

    const int l4 = lane >> 4;
    uint32_t baseA[2], baseB[8];
#pragma unroll
    for (int mt = 0; mt < 2; mt++) {
        int m_l = wm * 32 + mt * 16 + ((lane >> 3) & 1) * 8 + (lane & 7);
        baseA[mt] = m_l * 128 + (((m_l & 7) ^ l4) << 4);
    }
#pragma unroll
    for (int jp = 0; jp < 8; jp++) {
        int n_l = wn * 128 + jp * 16 + ((lane >> 3) & 1) * 8 + (lane & 7);
        baseB[jp] = 16384 + n_l * 128 + (((n_l & 7) ^ l4) << 4);
    }

    float acc[2][16][4];
#pragma unroll
    for (int mt = 0; mt < 2; mt++)
#pragma unroll
        for (int nt = 0; nt < 16; nt++)
#pragma unroll
            for (int e = 0; e < 4; e++) acc[mt][nt][e] = 0.0f;

    // Prologue: chunks 0,1
    {
        const __nv_bfloat16 *As, *Bs;
        seg_sel(0, Ahi, Alo, Whi, Wlo, &As, &Bs);
        issue_chunk(sm0, As, Bs, m0, n0, 0, t);
        CP_COMMIT();
        seg_sel(1, Ahi, Alo, Whi, Wlo, &As, &Bs);
        issue_chunk(sm0 + G_STAGE, As, Bs, m0, n0, 64, t);
        CP_COMMIT();
    }

    for (int kc = 0; kc < NKCH; kc++) {
        if (kc + 2 < NKCH) {
            const int kn = kc + 2;
            const __nv_bfloat16 *As, *Bs;
            seg_sel(kn, Ahi, Alo, Whi, Wlo, &As, &Bs);
            issue_chunk(sm0 + (kn % 3) * G_STAGE, As, Bs, m0, n0, (kn & 15) * 64, t);
            CP_COMMIT();
            CP_WAIT(2);
        } else if (kc + 1 < NKCH) {
            CP_WAIT(1);
        } else {
            CP_WAIT(0);
        }
        __syncthreads();

        const uint32_t sbase = sm0 + (kc % 3) * G_STAGE;
#pragma unroll
        for (int kk = 0; kk < 4; kk++) {
            uint32_t a[2][4], b[8][4];
#pragma unroll
            for (int mt = 0; mt < 2; mt++)
                LDSM_X4(a[mt][0], a[mt][1], a[mt][2], a[mt][3],
                        sbase + (baseA[mt] ^ (kk << 5)));
#pragma unroll
            for (int jp = 0; jp < 8; jp++)
                LDSM_X4(b[jp][0], b[jp][1], b[jp][2], b[jp][3],
                        sbase + (baseB[jp] ^ (kk << 5)));
#pragma unroll
            for (int mt = 0; mt < 2; mt++)
#pragma unroll
                for (int nt = 0; nt < 16; nt++)
                    MMA16816(acc[mt][nt], a[mt],
                             b[nt >> 1][nt & 1], b[nt >> 1][(nt & 1) + 2]);
        }
        __syncthreads();
    }

    // Epilogue
    const int qrow = lane >> 2;
    const int qcol = (lane & 3) * 2;
#pragma unroll
    for (int mt = 0; mt < 2; mt++) {
#pragma unroll
        for (int half = 0; half < 2; half++) {
            const int grow = m0 + wm * 32 + mt * 16 + half * 8 + qrow;
#pragma unroll
            for (int nt = 0; nt < 16; nt++) {
                const int gcol = n0 + wn * 128 + nt * 8 + qcol;
                float2 v = make_float2(acc[mt][nt][half * 2],
                                       acc[mt][nt][half * 2 + 1]);
                if (MODE == 0) {
                    v.x += bias[gcol];
                    v.y += bias[gcol + 1];
                    *(float2*)&out[(size_t)grow * C_ + gcol] = v;
                } else {
                    const int head = gcol >> 6, d = gcol & 63;
                    const int bb = grow >> 11, tt = grow & (T_ - 1);
                    size_t idx = (((size_t)bb * H_ + head) * T_ + tt) * D_ + d;
                    __nv_bfloat162 lo;
                    __nv_bfloat162 hi = split_hi2(v.x, v.y, &lo);
                    *(__nv_bfloat162*)&ohi[idx] = hi;
                    *(__nv_bfloat162*)&olo[idx] = lo;
                }
            }
        }
    }
}

__global__ __launch_bounds__(256)
void tc_gemm_qkv(const __nv_bfloat16* __restrict__ Xhi,
                 const __nv_bfloat16* __restrict__ Xlo,
                 const __nv_bfloat16* __restrict__ Wh,
                 const __nv_bfloat16* __restrict__ Wl,
                 __nv_bfloat16* __restrict__ Qh, __nv_bfloat16* __restrict__ Ql,
                 __nv_bfloat16* __restrict__ Kh, __nv_bfloat16* __restrict__ Kl,
                 __nv_bfloat16* __restrict__ Vh, __nv_bfloat16* __restrict__ Vl)
{
    const int z = blockIdx.z;
    const __nv_bfloat16* wh = Wh + (size_t)z * C_ * C_;
    const __nv_bfloat16* wl = Wl + (size_t)z * C_ * C_;
    __nv_bfloat16* oh = (z == 0) ? Qh : (z == 1) ? Kh : Vh;
    __nv_bfloat16* ol = (z == 0) ? Ql : (z == 1) ? Kl : Vl;
    hmma_gemm_body<1>(Xhi, Xlo, wh, wl, nullptr, nullptr, oh, ol);
}

__global__ __launch_bounds__(256)
void tc_gemm_out(const __nv_bfloat16* __restrict__ Yhi,
                 const __nv_bfloat16* __restrict__ Ylo,
                 const __nv_bfloat16* __restrict__ Wh,
                 const __nv_bfloat16* __restrict__ Wl,
                 const float* __restrict__ bias, float* __restrict__ out)
{
    hmma_gemm_body<0>(Yhi, Ylo, Wh, Wl, bias, out, nullptr, nullptr);
}

// ---------------------------------------------------------------------------
// HMMA flash attention (causal). Same math as the 968us R8 kernel; epilogue
// emits bf16 hi/lo Y directly (deletes fp32 Y buffer + its convert kernel).
// ---------------------------------------------------------------------------
#define ATT_SMEM 98304

__device__ __forceinline__
void issue_kv(uint32_t dstbase,
              const __nv_bfloat16* __restrict__ Kh, const __nv_bfloat16* __restrict__ Kl,
              const __nv_bfloat16* __restrict__ Vh, const __nv_bfloat16* __restrict__ Vl,
              int kbase, int t)
{
#pragma unroll
    for (int rep = 0; rep < 2; rep++) {
        int idx = t + rep * 256;
        int r = idx >> 3, c = idx & 7;
        uint32_t dst = dstbase + r * 128 + ((c ^ (r & 7)) << 4);
        size_t g = (size_t)(kbase + r) * D_ + c * 8;
        CP_ASYNC16(dst,          (const void*)(Kh + g));
        CP_ASYNC16(dst + 8192,   (const void*)(Kl + g));
        CP_ASYNC16(dst + 16384,  (const void*)(Vh + g));
        CP_ASYNC16(dst + 24576,  (const void*)(Vl + g));
    }
}

__global__ __launch_bounds__(256)
void attn_hmma(const __nv_bfloat16* __restrict__ Qhi, const __nv_bfloat16* __restrict__ Qlo,
               const __nv_bfloat16* __restrict__ Khi, const __nv_bfloat16* __restrict__ Klo,
               const __nv_bfloat16* __restrict__ Vhi, const __nv_bfloat16* __restrict__ Vlo,
               __nv_bfloat16* __restrict__ Yh, __nv_bfloat16* __restrict__ Yl)
{
    extern __shared__ __align__(128) char sm[];
    const uint32_t s0 = smem_u32(sm);
    const int t = threadIdx.x, lane = t & 31, w = t >> 5;
    const int bh = blockIdx.y;
    const int qi = (int)(gridDim.x - 1 - blockIdx.x);
    const int qbase = qi * 128;
    const size_t base = (size_t)bh * T_ * D_;
    const __nv_bfloat16* Qh = Qhi + base + (size_t)qbase * D_;
    const __nv_bfloat16* Ql = Qlo + base + (size_t)qbase * D_;
    const __nv_bfloat16* Kh = Khi + base;
    const __nv_bfloat16* Kl = Klo + base;
    const __nv_bfloat16* Vh = Vhi + base;
    const __nv_bfloat16* Vl = Vlo + base;

#pragma unroll
    for (int rep = 0; rep < 4; rep++) {
        int idx = t + rep * 256;
        int r = idx >> 3, c = idx & 7;
        uint32_t dst = s0 + r * 128 + ((c ^ (r & 7)) << 4);
        size_t g = (size_t)r * D_ + c * 8;
        CP_ASYNC16(dst,          (const void*)(Qh + g));
        CP_ASYNC16(dst + 16384,  (const void*)(Ql + g));
    }
    CP_COMMIT();

    const int nch = 2 * qi + 2;
    issue_kv(s0 + 32768, Kh, Kl, Vh, Vl, 0, t);
    CP_COMMIT();

    CP_WAIT(1);
    __syncthreads();

    uint32_t aQh[4][4], aQl[4][4];
#pragma unroll
    for (int s = 0; s < 4; s++) {
        int row = 16 * w + (lane & 15);
        int cb  = 2 * s + (lane >> 4);
        uint32_t ad = s0 + row * 128 + ((cb ^ (row & 7)) << 4);
        LDSM_X4(aQh[s][0], aQh[s][1], aQh[s][2], aQh[s][3], ad);
        LDSM_X4(aQl[s][0], aQl[s][1], aQl[s][2], aQl[s][3], ad + 16384);
    }

    float accO[8][4];
#pragma unroll
    for (int j = 0; j < 8; j++)
#pragma unroll
        for (int e = 0; e < 4; e++) accO[j][e] = 0.0f;

    float m0s = -1e30f, m1s = -1e30f, l0s = 0.0f, l1s = 0.0f;
    const int r0g = qbase + 16 * w + (lane >> 2);
    const int r1g = r0g + 8;

    for (int kc = 0; kc < nch; kc++) {
        const int kbase = kc * 64;
        const int stage = kc & 1;
        if (kc + 1 < nch) {
            issue_kv(s0 + 32768 + (stage ^ 1) * 32768, Kh, Kl, Vh, Vl, kbase + 64, t);
            CP_COMMIT();
            CP_WAIT(1);
        } else {
            CP_WAIT(0);
        }
        __syncthreads();
        const uint32_t kvb = s0 + 32768 + stage * 32768;

        if (kbase <= qbase + 16 * w + 15) {
            float sc[8][4];
#pragma unroll
            for (int j = 0; j < 8; j++)
#pragma unroll
                for (int e = 0; e < 4; e++) sc[j][e] = 0.0f;

#pragma unroll
            for (int s = 0; s < 4; s++) {
                uint32_t bKh[8][2], bKl[8][2];
#pragma unroll
                for (int jp = 0; jp < 4; jp++) {
                    int row = 16 * jp + ((lane >> 4) << 3) + (lane & 7);
                    int cb  = 2 * s + ((lane >> 3) & 1);
                    uint32_t ad = kvb + row * 128 + ((cb ^ (row & 7)) << 4);
                    LDSM_X4(bKh[2*jp][0], bKh[2*jp][1], bKh[2*jp+1][0], bKh[2*jp+1][1], ad);
                    LDSM_X4(bKl[2*jp][0], bKl[2*jp][1], bKl[2*jp+1][0], bKl[2*jp+1][1], ad + 8192);
                }
#pragma unroll
                for (int j = 0; j < 8; j++) {
                    MMA16816(sc[j], aQh[s], bKh[j][0], bKh[j][1]);
                    MMA16816(sc[j], aQh[s], bKl[j][0], bKl[j][1]);
                    MMA16816(sc[j], aQl[s], bKh[j][0], bKh[j][1]);
                }
            }

            const int c0b = kbase + 2 * (lane & 3);
#pragma unroll
            for (int j = 0; j < 8; j++) {
                int cc = c0b + 8 * j;
                sc[j][0] = (cc     > r0g) ? -1e30f : sc[j][0] * 0.125f;
                sc[j][1] = (cc + 1 > r0g) ? -1e30f : sc[j][1] * 0.125f;
                sc[j][2] = (cc     > r1g) ? -1e30f : sc[j][2] * 0.125f;
                sc[j][3] = (cc + 1 > r1g) ? -1e30f : sc[j][3] * 0.125f;
            }

            float mx0 = -1e30f, mx1 = -1e30f;
#pragma unroll
            for (int j = 0; j < 8; j++) {
                mx0 = fmaxf(mx0, fmaxf(sc[j][0], sc[j][1]));
                mx1 = fmaxf(mx1, fmaxf(sc[j][2], sc[j][3]));
            }
            mx0 = fmaxf(mx0, __shfl_xor_sync(0xffffffffu, mx0, 1));
            mx0 = fmaxf(mx0, __shfl_xor_sync(0xffffffffu, mx0, 2));
            mx1 = fmaxf(mx1, __shfl_xor_sync(0xffffffffu, mx1, 1));
            mx1 = fmaxf(mx1, __shfl_xor_sync(0xffffffffu, mx1, 2));
            float mn0 = fmaxf(m0s, mx0), mn1 = fmaxf(m1s, mx1);
            float cr0 = __expf(m0s - mn0), cr1 = __expf(m1s - mn1);
            m0s = mn0; m1s = mn1;

            float sum0 = 0.0f, sum1 = 0.0f;
            uint32_t aPh[4][4], aPl[4][4];
#pragma unroll
            for (int jp = 0; jp < 4; jp++) {
#pragma unroll
                for (int u = 0; u < 2; u++) {
                    int j = 2 * jp + u;
                    float p0 = __expf(sc[j][0] - mn0);
                    float p1 = __expf(sc[j][1] - mn0);
                    float p2 = __expf(sc[j][2] - mn1);
                    float p3 = __expf(sc[j][3] - mn1);
                    sum0 += p0 + p1;
                    sum1 += p2 + p3;
                    __nv_bfloat16 h0 = __float2bfloat16_rn(p0);
                    __nv_bfloat16 h1 = __float2bfloat16_rn(p1);
                    __nv_bfloat16 h2 = __float2bfloat16_rn(p2);
                    __nv_bfloat16 h3 = __float2bfloat16_rn(p3);
                    aPh[jp][2*u]     = pack2(h0, h1);
                    aPh[jp][2*u + 1] = pack2(h2, h3);
                    aPl[jp][2*u]     = pack2(__float2bfloat16_rn(p0 - __bfloat162float(h0)),
                                             __float2bfloat16_rn(p1 - __bfloat162float(h1)));
                    aPl[jp][2*u + 1] = pack2(__float2bfloat16_rn(p2 - __bfloat162float(h2)),
                                             __float2bfloat16_rn(p3 - __bfloat162float(h3)));
                }
            }
            sum0 += __shfl_xor_sync(0xffffffffu, sum0, 1);
            sum0 += __shfl_xor_sync(0xffffffffu, sum0, 2);
            sum1 += __shfl_xor_sync(0xffffffffu, sum1, 1);
            sum1 += __shfl_xor_sync(0xffffffffu, sum1, 2);
            l0s = l0s * cr0 + sum0;
            l1s = l1s * cr1 + sum1;

#pragma unroll
            for (int j = 0; j < 8; j++) {
                accO[j][0] *= cr0; accO[j][1] *= cr0;
                accO[j][2] *= cr1; accO[j][3] *= cr1;
            }

#pragma unroll
            for (int s = 0; s < 4; s++) {
                uint32_t bVh[8][2], bVl[8][2];
#pragma unroll
                for (int jp = 0; jp < 4; jp++) {
                    int row = 16 * s + ((lane >> 3) & 1) * 8 + (lane & 7);
                    int cb  = 2 * jp + (lane >> 4);
                    uint32_t ad = kvb + 16384 + row * 128 + ((cb ^ (row & 7)) << 4);
                    LDSM_X4_T(bVh[2*jp][0], bVh[2*jp][1], bVh[2*jp+1][0], bVh[2*jp+1][1], ad);
                    LDSM_X4_T(bVl[2*jp][0], bVl[2*jp][1], bVl[2*jp+1][0], bVl[2*jp+1][1], ad + 8192);
                }
#pragma unroll
                for (int j = 0; j < 8; j++) {
                    MMA16816(accO[j], aPh[s], bVh[j][0], bVh[j][1]);
                    MMA16816(accO[j], aPh[s], bVl[j][0], bVl[j][1]);
                    MMA16816(accO[j], aPl[s], bVh[j][0], bVh[j][1]);
                }
            }
        }
        __syncthreads();
    }

    // normalize + store as bf16 hi/lo
    const float i0 = 1.0f / l0s, i1 = 1.0f / l1s;
    const int b = bh >> 4, h = bh & 15;
    const size_t o0 = ((size_t)b * T_ + r0g) * C_ + h * 64 + 2 * (lane & 3);
    const size_t o1 = ((size_t)b * T_ + r1g) * C_ + h * 64 + 2 * (lane & 3);
#pragma unroll
    for (int j = 0; j < 8; j++) {
        __nv_bfloat162 lo;
        __nv_bfloat162 hi = split_hi2(accO[j][0] * i0, accO[j][1] * i0, &lo);
        *(__nv_bfloat162*)&Yh[o0 + 8 * j] = hi;
        *(__nv_bfloat162*)&Yl[o0 + 8 * j] = lo;
        hi = split_hi2(accO[j][2] * i1, accO[j][3] * i1, &lo);
        *(__nv_bfloat162*)&Yh[o1 + 8 * j] = hi;
        *(__nv_bfloat162*)&Yl[o1 + 8 * j] = lo;
    }
}

// ---------------------------------------------------------------------------
extern "C" void kernel_launch(void* const* d_in, const int* in_sizes, int n_in,
                              void* d_out, int out_size)
{
    const float* X  = (const float*)d_in[0];
    const float* Wq = (const float*)d_in[1];
    const float* Wk = (const float*)d_in[2];
    const float* Wv = (const float*)d_in[3];
    const float* Wo = (const float*)d_in[4];
    const float* bo = (const float*)d_in[5];
    float* out = (float*)d_out;

    __nv_bfloat16 *xh, *xl, *wh, *wl, *woh, *wol, *yh, *yl;
    __nv_bfloat16 *qh, *ql, *kh, *kl, *vh, *vl;
    cudaGetSymbolAddress((void**)&xh, g_Xhi);
    cudaGetSymbolAddress((void**)&xl, g_Xlo);
    cudaGetSymbolAddress((void**)&wh, g_Wh);
    cudaGetSymbolAddress((void**)&wl, g_Wl);
    cudaGetSymbolAddress((void**)&woh, g_Wohi);
    cudaGetSymbolAddress((void**)&wol, g_Wolo);
    cudaGetSymbolAddress((void**)&yh, g_Yhi);
    cudaGetSymbolAddress((void**)&yl, g_Ylo);
    cudaGetSymbolAddress((void**)&qh, g_Qhi);
    cudaGetSymbolAddress((void**)&ql, g_Qlo);
    cudaGetSymbolAddress((void**)&kh, g_Khi);
    cudaGetSymbolAddress((void**)&kl, g_Klo);
    cudaGetSymbolAddress((void**)&vh, g_Vhi);
    cudaGetSymbolAddress((void**)&vl, g_Vlo);

    // hi/lo split converts
    cvt_kernel<<<(M_ * C_ / 4 + 255) / 256, 256>>>(X, xh, xl, M_ * C_ / 4);
    cvt_kernel<<<(C_ * C_ / 4 + 255) / 256, 256>>>(Wq, wh,               wl,               C_ * C_ / 4);
    cvt_kernel<<<(C_ * C_ / 4 + 255) / 256, 256>>>(Wk, wh + C_ * C_,     wl + C_ * C_,     C_ * C_ / 4);
    cvt_kernel<<<(C_ * C_ / 4 + 255) / 256, 256>>>(Wv, wh + 2 * C_ * C_, wl + 2 * C_ * C_, C_ * C_ / 4);
    cvt_kernel<<<(C_ * C_ / 4 + 255) / 256, 256>>>(Wo, woh, wol, C_ * C_ / 4);

    // QKV projections (HMMA v2) -> bf16 hi/lo split-head
    cudaFuncSetAttribute((const void*)tc_gemm_qkv,
                         cudaFuncAttributeMaxDynamicSharedMemorySize, G_SMEM);
    tc_gemm_qkv<<<dim3(C_ / 256, M_ / 128, 3), 256, G_SMEM>>>(
        xh, xl, wh, wl, qh, ql, kh, kl, vh, vl);

    // Attention (HMMA flash) -> bf16 hi/lo Y
    cudaFuncSetAttribute((const void*)attn_hmma,
                         cudaFuncAttributeMaxDynamicSharedMemorySize, ATT_SMEM);
    attn_hmma<<<dim3(T_ / 128, B_ * H_), 256, ATT_SMEM>>>(qh, ql, kh, kl, vh, vl, yh, yl);

    // Output projection (HMMA v2)
    cudaFuncSetAttribute((const void*)tc_gemm_out,
                         cudaFuncAttributeMaxDynamicSharedMemorySize, G_SMEM);
    tc_gemm_out<<<dim3(C_ / 256, M_ / 128), 256, G_SMEM>>>(yh, yl, woh, wol, bo, out);
}

// round 11
// speedup vs baseline: 1.0866x; 1.0866x over previous
#include <cuda_runtime.h>
#include <cuda_bf16.h>
#include <cstdint>

// Problem constants
#define B_ 4
#define T_ 2048
#define C_ 1024
#define H_ 16
#define D_ 64
#define M_ (B_ * T_)   // 8192 rows

// ---------------------------------------------------------------------------
// Scratch (allocation-free rule: __device__ globals)
// ---------------------------------------------------------------------------
__device__ __align__(16) __nv_bfloat16 g_Xhi[(size_t)M_ * C_];
__device__ __align__(16) __nv_bfloat16 g_Xlo[(size_t)M_ * C_];
__device__ __align__(16) __nv_bfloat16 g_Wh[(size_t)3 * C_ * C_];
__device__ __align__(16) __nv_bfloat16 g_Wl[(size_t)3 * C_ * C_];
__device__ __align__(16) __nv_bfloat16 g_Wohi[(size_t)C_ * C_];
__device__ __align__(16) __nv_bfloat16 g_Wolo[(size_t)C_ * C_];
__device__ __align__(16) __nv_bfloat16 g_Yhi[(size_t)M_ * C_];
__device__ __align__(16) __nv_bfloat16 g_Ylo[(size_t)M_ * C_];
__device__ __align__(16) __nv_bfloat16 g_Qhi[(size_t)B_ * H_ * T_ * D_];
__device__ __align__(16) __nv_bfloat16 g_Qlo[(size_t)B_ * H_ * T_ * D_];
__device__ __align__(16) __nv_bfloat16 g_Khi[(size_t)B_ * H_ * T_ * D_];
__device__ __align__(16) __nv_bfloat16 g_Klo[(size_t)B_ * H_ * T_ * D_];
__device__ __align__(16) __nv_bfloat16 g_Vhi[(size_t)B_ * H_ * T_ * D_];
__device__ __align__(16) __nv_bfloat16 g_Vlo[(size_t)B_ * H_ * T_ * D_];

// ---------------------------------------------------------------------------
// Helpers
// ---------------------------------------------------------------------------
__device__ __forceinline__ uint32_t smem_u32(const void* p) {
    uint32_t a;
    asm("{ .reg .u64 t; cvta.to.shared.u64 t, %1; cvt.u32.u64 %0, t; }"
        : "=r"(a) : "l"(p));
    return a;
}

#define CP_ASYNC16(dst, src) \
    asm volatile("cp.async.cg.shared.global [%0], [%1], 16;" \
                 :: "r"(dst), "l"(src) : "memory")
#define CP_COMMIT()  asm volatile("cp.async.commit_group;" ::: "memory")
#define CP_WAIT(n)   asm volatile("cp.async.wait_group %0;" :: "n"(n) : "memory")

#define LDSM_X4(r0, r1, r2, r3, addr) \
    asm volatile("ldmatrix.sync.aligned.m8n8.x4.shared.b16 {%0,%1,%2,%3}, [%4];" \
                 : "=r"(r0), "=r"(r1), "=r"(r2), "=r"(r3) : "r"(addr))

#define LDSM_X4_T(r0, r1, r2, r3, addr) \
    asm volatile("ldmatrix.sync.aligned.m8n8.x4.trans.shared.b16 {%0,%1,%2,%3}, [%4];" \
                 : "=r"(r0), "=r"(r1), "=r"(r2), "=r"(r3) : "r"(addr))

#define MMA16816(d, a, b0, b1) \
    asm volatile("mma.sync.aligned.m16n8k16.row.col.f32.bf16.bf16.f32 " \
                 "{%0,%1,%2,%3}, {%4,%5,%6,%7}, {%8,%9}, {%0,%1,%2,%3};" \
                 : "+f"((d)[0]), "+f"((d)[1]), "+f"((d)[2]), "+f"((d)[3]) \
                 : "r"((a)[0]), "r"((a)[1]), "r"((a)[2]), "r"((a)[3]), \
                   "r"(b0), "r"(b1))

__device__ __forceinline__ uint32_t pack2(__nv_bfloat16 a, __nv_bfloat16 b) {
    __nv_bfloat162 v = __halves2bfloat162(a, b);
    return *reinterpret_cast<uint32_t*>(&v);
}

__device__ __forceinline__ __nv_bfloat162 split_hi2(float x, float y,
                                                    __nv_bfloat162* lo) {
    __nv_bfloat16 h0 = __float2bfloat16_rn(x);
    __nv_bfloat16 h1 = __float2bfloat16_rn(y);
    *lo = __halves2bfloat162(__float2bfloat16_rn(x - __bfloat162float(h0)),
                             __float2bfloat16_rn(y - __bfloat162float(h1)));
    return __halves2bfloat162(h0, h1);
}

// ---------------------------------------------------------------------------
// fp32 -> bf16 hi/lo split.  cvt_w: one launch converts all 4 weight mats.
// ---------------------------------------------------------------------------
__device__ __forceinline__
void cvt_body(const float* __restrict__ in, __nv_bfloat16* __restrict__ hi,
              __nv_bfloat16* __restrict__ lo, int i)
{
    float4 v = ((const float4*)in)[i];
    __nv_bfloat162 l01, l23;
    __nv_bfloat162 h01 = split_hi2(v.x, v.y, &l01);
    __nv_bfloat162 h23 = split_hi2(v.z, v.w, &l23);
    ((__nv_bfloat162*)hi)[2 * i]     = h01;
    ((__nv_bfloat162*)hi)[2 * i + 1] = h23;
    ((__nv_bfloat162*)lo)[2 * i]     = l01;
    ((__nv_bfloat162*)lo)[2 * i + 1] = l23;
}

__global__ __launch_bounds__(256)
void cvt_kernel(const float* __restrict__ in, __nv_bfloat16* __restrict__ hi,
                __nv_bfloat16* __restrict__ lo, int n4)
{
    int i = blockIdx.x * 256 + threadIdx.x;
    if (i < n4) cvt_body(in, hi, lo, i);
}

__global__ __launch_bounds__(256)
void cvt_w_kernel(const float* __restrict__ Wq, const float* __restrict__ Wk,
                  const float* __restrict__ Wv, const float* __restrict__ Wo,
                  __nv_bfloat16* __restrict__ Wh, __nv_bfloat16* __restrict__ Wl,
                  __nv_bfloat16* __restrict__ Woh, __nv_bfloat16* __restrict__ Wol)
{
    const int z = blockIdx.y;
    const float* in = (z == 0) ? Wq : (z == 1) ? Wk : (z == 2) ? Wv : Wo;
    __nv_bfloat16* hi = (z < 3) ? (Wh + (size_t)z * C_ * C_) : Woh;
    __nv_bfloat16* lo = (z < 3) ? (Wl + (size_t)z * C_ * C_) : Wol;
    int i = blockIdx.x * 256 + threadIdx.x;
    if (i < C_ * C_ / 4) cvt_body(in, hi, lo, i);
}

// ---------------------------------------------------------------------------
// HMMA bf16 GEMM v1 (extended-K hi/lo split), BM=128, BN=128, BK=64,
// 2-stage cp.async pipeline. 8 warps: 4(M) x 2(N), warp tile 32x64.
// (Proven 968us configuration; v2 BN=256/3-stage regressed — reverted.)
// MODE 0: fp32 [M,N] + bias.   MODE 1: bf16 hi/lo split-head [b,h,t,d].
// ---------------------------------------------------------------------------
#define NKCH 48
#define STAGE_B 32768

__device__ __forceinline__
void issue_chunk(uint32_t sbase, const __nv_bfloat16* __restrict__ Aseg,
                 const __nv_bfloat16* __restrict__ Bseg,
                 int m0, int n0, int k_in, int t)
{
#pragma unroll
    for (int rep = 0; rep < 4; rep++) {
        int idx = t + rep * 256;
        int r = idx >> 3, s = idx & 7;
        uint32_t dstA = sbase + r * 128 + ((s ^ (r & 7)) << 4);
        CP_ASYNC16(dstA, (const void*)(Aseg + (size_t)(m0 + r) * C_ + k_in + s * 8));
        CP_ASYNC16(dstA + 16384,
                   (const void*)(Bseg + (size_t)(n0 + r) * C_ + k_in + s * 8));
    }
}

__device__ __forceinline__
void seg_sel(int kn, const __nv_bfloat16* Ahi, const __nv_bfloat16* Alo,
             const __nv_bfloat16* Whi, const __nv_bfloat16* Wlo,
             const __nv_bfloat16** Aseg, const __nv_bfloat16** Bseg)
{
    *Aseg = (kn < 32) ? Ahi : Alo;
    *Bseg = (kn < 16) ? Whi : (kn < 32 ? Wlo : Whi);
}

template <int MODE>
__device__ __forceinline__
void hmma_gemm_body(const __nv_bfloat16* __restrict__ Ahi,
                    const __nv_bfloat16* __restrict__ Alo,
                    const __nv_bfloat16* __restrict__ Whi,
                    const __nv_bfloat16* __restrict__ Wlo,
                    const float* __restrict__ bias, float* __restrict__ out,
                    __nv_bfloat16* __restrict__ ohi, __nv_bfloat16* __restrict__ olo)
{
    extern __shared__ __align__(128) char sm[];
    const uint32_t sm0 = smem_u32(sm);
    const int t    = threadIdx.x;
    const int lane = t & 31;
    const int w    = t >> 5;
    const int wm   = w & 3;             // m offset 32*wm
    const int wn   = w >> 2;            // n offset 64*wn
    const int m0   = blockIdx.y * 128;
    const int n0   = blockIdx.x * 128;

    const int l4 = lane >> 4;
    uint32_t baseA[2], baseB[4];
#pragma unroll
    for (int mt = 0; mt < 2; mt++) {
        int m_l = wm * 32 + mt * 16 + ((lane >> 3) & 1) * 8 + (lane & 7);
        baseA[mt] = m_l * 128 + (((m_l & 7) ^ l4) << 4);
    }
#pragma unroll
    for (int j = 0; j < 4; j++) {
        int n_l = wn * 64 + j * 16 + ((lane >> 3) & 1) * 8 + (lane & 7);
        baseB[j] = 16384 + n_l * 128 + (((n_l & 7) ^ l4) << 4);
    }

    float acc[2][8][4];
#pragma unroll
    for (int mt = 0; mt < 2; mt++)
#pragma unroll
        for (int nt = 0; nt < 8; nt++)
#pragma unroll
            for (int e = 0; e < 4; e++) acc[mt][nt][e] = 0.0f;

    {
        const __nv_bfloat16 *As, *Bs;
        seg_sel(0, Ahi, Alo, Whi, Wlo, &As, &Bs);
        issue_chunk(sm0, As, Bs, m0, n0, 0, t);
        CP_COMMIT();
    }

    for (int kc = 0; kc < NKCH; kc++) {
        __syncthreads();
        if (kc + 1 < NKCH) {
            const int kn = kc + 1;
            const __nv_bfloat16 *As, *Bs;
            seg_sel(kn, Ahi, Alo, Whi, Wlo, &As, &Bs);
            issue_chunk(sm0 + ((kn & 1) ? STAGE_B : 0), As, Bs,
                        m0, n0, (kn & 15) * 64, t);
            CP_COMMIT();
            CP_WAIT(1);
        } else {
            CP_WAIT(0);
        }
        __syncthreads();

        const uint32_t sbase = sm0 + ((kc & 1) ? STAGE_B : 0);
#pragma unroll
        for (int kk = 0; kk < 4; kk++) {
            uint32_t a[2][4], b[4][4];
#pragma unroll
            for (int mt = 0; mt < 2; mt++)
                LDSM_X4(a[mt][0], a[mt][1], a[mt][2], a[mt][3],
                        sbase + (baseA[mt] ^ (kk << 5)));
#pragma unroll
            for (int j = 0; j < 4; j++)
                LDSM_X4(b[j][0], b[j][1], b[j][2], b[j][3],
                        sbase + (baseB[j] ^ (kk << 5)));
#pragma unroll
            for (int mt = 0; mt < 2; mt++)
#pragma unroll
                for (int nt = 0; nt < 8; nt++)
                    MMA16816(acc[mt][nt], a[mt],
                             b[nt >> 1][nt & 1], b[nt >> 1][(nt & 1) + 2]);
        }
    }

    // Epilogue
    const int qrow = lane >> 2;
    const int qcol = (lane & 3) * 2;
#pragma unroll
    for (int mt = 0; mt < 2; mt++) {
#pragma unroll
        for (int half = 0; half < 2; half++) {
            const int grow = m0 + wm * 32 + mt * 16 + half * 8 + qrow;
#pragma unroll
            for (int nt = 0; nt < 8; nt++) {
                const int gcol = n0 + wn * 64 + nt * 8 + qcol;
                float2 v = make_float2(acc[mt][nt][half * 2],
                                       acc[mt][nt][half * 2 + 1]);
                if (MODE == 0) {
                    v.x += bias[gcol];
                    v.y += bias[gcol + 1];
                    *(float2*)&out[(size_t)grow * C_ + gcol] = v;
                } else {
                    const int head = gcol >> 6, d = gcol & 63;
                    const int bb = grow >> 11, tt = grow & (T_ - 1);
                    size_t idx = (((size_t)bb * H_ + head) * T_ + tt) * D_ + d;
                    __nv_bfloat162 lo;
                    __nv_bfloat162 hi = split_hi2(v.x, v.y, &lo);
                    *(__nv_bfloat162*)&ohi[idx] = hi;
                    *(__nv_bfloat162*)&olo[idx] = lo;
                }
            }
        }
    }
}

__global__ __launch_bounds__(256)
void tc_gemm_qkv(const __nv_bfloat16* __restrict__ Xhi,
                 const __nv_bfloat16* __restrict__ Xlo,
                 const __nv_bfloat16* __restrict__ Wh,
                 const __nv_bfloat16* __restrict__ Wl,
                 __nv_bfloat16* __restrict__ Qh, __nv_bfloat16* __restrict__ Ql,
                 __nv_bfloat16* __restrict__ Kh, __nv_bfloat16* __restrict__ Kl,
                 __nv_bfloat16* __restrict__ Vh, __nv_bfloat16* __restrict__ Vl)
{
    const int z = blockIdx.z;
    const __nv_bfloat16* wh = Wh + (size_t)z * C_ * C_;
    const __nv_bfloat16* wl = Wl + (size_t)z * C_ * C_;
    __nv_bfloat16* oh = (z == 0) ? Qh : (z == 1) ? Kh : Vh;
    __nv_bfloat16* ol = (z == 0) ? Ql : (z == 1) ? Kl : Vl;
    hmma_gemm_body<1>(Xhi, Xlo, wh, wl, nullptr, nullptr, oh, ol);
}

__global__ __launch_bounds__(256)
void tc_gemm_out(const __nv_bfloat16* __restrict__ Yhi,
                 const __nv_bfloat16* __restrict__ Ylo,
                 const __nv_bfloat16* __restrict__ Wh,
                 const __nv_bfloat16* __restrict__ Wl,
                 const float* __restrict__ bias, float* __restrict__ out)
{
    hmma_gemm_body<0>(Yhi, Ylo, Wh, Wl, bias, out, nullptr, nullptr);
}

// ---------------------------------------------------------------------------
// HMMA flash attention (causal). Identical math to the R8/R10 passing kernel;
// epilogue emits bf16 hi/lo Y directly.
// ---------------------------------------------------------------------------
#define ATT_SMEM 98304

__device__ __forceinline__
void issue_kv(uint32_t dstbase,
              const __nv_bfloat16* __restrict__ Kh, const __nv_bfloat16* __restrict__ Kl,
              const __nv_bfloat16* __restrict__ Vh, const __nv_bfloat16* __restrict__ Vl,
              int kbase, int t)
{
#pragma unroll
    for (int rep = 0; rep < 2; rep++) {
        int idx = t + rep * 256;
        int r = idx >> 3, c = idx & 7;
        uint32_t dst = dstbase + r * 128 + ((c ^ (r & 7)) << 4);
        size_t g = (size_t)(kbase + r) * D_ + c * 8;
        CP_ASYNC16(dst,          (const void*)(Kh + g));
        CP_ASYNC16(dst + 8192,   (const void*)(Kl + g));
        CP_ASYNC16(dst + 16384,  (const void*)(Vh + g));
        CP_ASYNC16(dst + 24576,  (const void*)(Vl + g));
    }
}

__global__ __launch_bounds__(256)
void attn_hmma(const __nv_bfloat16* __restrict__ Qhi, const __nv_bfloat16* __restrict__ Qlo,
               const __nv_bfloat16* __restrict__ Khi, const __nv_bfloat16* __restrict__ Klo,
               const __nv_bfloat16* __restrict__ Vhi, const __nv_bfloat16* __restrict__ Vlo,
               __nv_bfloat16* __restrict__ Yh, __nv_bfloat16* __restrict__ Yl)
{
    extern __shared__ __align__(128) char sm[];
    const uint32_t s0 = smem_u32(sm);
    const int t = threadIdx.x, lane = t & 31, w = t >> 5;
    const int bh = blockIdx.y;
    const int qi = (int)(gridDim.x - 1 - blockIdx.x);
    const int qbase = qi * 128;
    const size_t base = (size_t)bh * T_ * D_;
    const __nv_bfloat16* Qh = Qhi + base + (size_t)qbase * D_;
    const __nv_bfloat16* Ql = Qlo + base + (size_t)qbase * D_;
    const __nv_bfloat16* Kh = Khi + base;
    const __nv_bfloat16* Kl = Klo + base;
    const __nv_bfloat16* Vh = Vhi + base;
    const __nv_bfloat16* Vl = Vlo + base;

#pragma unroll
    for (int rep = 0; rep < 4; rep++) {
        int idx = t + rep * 256;
        int r = idx >> 3, c = idx & 7;
        uint32_t dst = s0 + r * 128 + ((c ^ (r & 7)) << 4);
        size_t g = (size_t)r * D_ + c * 8;
        CP_ASYNC16(dst,          (const void*)(Qh + g));
        CP_ASYNC16(dst + 16384,  (const void*)(Ql + g));
    }
    CP_COMMIT();

    const int nch = 2 * qi + 2;
    issue_kv(s0 + 32768, Kh, Kl, Vh, Vl, 0, t);
    CP_COMMIT();

    CP_WAIT(1);
    __syncthreads();

    uint32_t aQh[4][4], aQl[4][4];
#pragma unroll
    for (int s = 0; s < 4; s++) {
        int row = 16 * w + (lane & 15);
        int cb  = 2 * s + (lane >> 4);
        uint32_t ad = s0 + row * 128 + ((cb ^ (row & 7)) << 4);
        LDSM_X4(aQh[s][0], aQh[s][1], aQh[s][2], aQh[s][3], ad);
        LDSM_X4(aQl[s][0], aQl[s][1], aQl[s][2], aQl[s][3], ad + 16384);
    }

    float accO[8][4];
#pragma unroll
    for (int j = 0; j < 8; j++)
#pragma unroll
        for (int e = 0; e < 4; e++) accO[j][e] = 0.0f;

    float m0s = -1e30f, m1s = -1e30f, l0s = 0.0f, l1s = 0.0f;
    const int r0g = qbase + 16 * w + (lane >> 2);
    const int r1g = r0g + 8;

    for (int kc = 0; kc < nch; kc++) {
        const int kbase = kc * 64;
        const int stage = kc & 1;
        if (kc + 1 < nch) {
            issue_kv(s0 + 32768 + (stage ^ 1) * 32768, Kh, Kl, Vh, Vl, kbase + 64, t);
            CP_COMMIT();
            CP_WAIT(1);
        } else {
            CP_WAIT(0);
        }
        __syncthreads();
        const uint32_t kvb = s0 + 32768 + stage * 32768;

        if (kbase <= qbase + 16 * w + 15) {
            float sc[8][4];
#pragma unroll
            for (int j = 0; j < 8; j++)
#pragma unroll
                for (int e = 0; e < 4; e++) sc[j][e] = 0.0f;

#pragma unroll
            for (int s = 0; s < 4; s++) {
                uint32_t bKh[8][2], bKl[8][2];
#pragma unroll
                for (int jp = 0; jp < 4; jp++) {
                    int row = 16 * jp + ((lane >> 4) << 3) + (lane & 7);
                    int cb  = 2 * s + ((lane >> 3) & 1);
                    uint32_t ad = kvb + row * 128 + ((cb ^ (row & 7)) << 4);
                    LDSM_X4(bKh[2*jp][0], bKh[2*jp][1], bKh[2*jp+1][0], bKh[2*jp+1][1], ad);
                    LDSM_X4(bKl[2*jp][0], bKl[2*jp][1], bKl[2*jp+1][0], bKl[2*jp+1][1], ad + 8192);
                }
#pragma unroll
                for (int j = 0; j < 8; j++) {
                    MMA16816(sc[j], aQh[s], bKh[j][0], bKh[j][1]);
                    MMA16816(sc[j], aQh[s], bKl[j][0], bKl[j][1]);
                    MMA16816(sc[j], aQl[s], bKh[j][0], bKh[j][1]);
                }
            }

            const int c0b = kbase + 2 * (lane & 3);
#pragma unroll
            for (int j = 0; j < 8; j++) {
                int cc = c0b + 8 * j;
                sc[j][0] = (cc     > r0g) ? -1e30f : sc[j][0] * 0.125f;
                sc[j][1] = (cc + 1 > r0g) ? -1e30f : sc[j][1] * 0.125f;
                sc[j][2] = (cc     > r1g) ? -1e30f : sc[j][2] * 0.125f;
                sc[j][3] = (cc + 1 > r1g) ? -1e30f : sc[j][3] * 0.125f;
            }

            float mx0 = -1e30f, mx1 = -1e30f;
#pragma unroll
            for (int j = 0; j < 8; j++) {
                mx0 = fmaxf(mx0, fmaxf(sc[j][0], sc[j][1]));
                mx1 = fmaxf(mx1, fmaxf(sc[j][2], sc[j][3]));
            }
            mx0 = fmaxf(mx0, __shfl_xor_sync(0xffffffffu, mx0, 1));
            mx0 = fmaxf(mx0, __shfl_xor_sync(0xffffffffu, mx0, 2));
            mx1 = fmaxf(mx1, __shfl_xor_sync(0xffffffffu, mx1, 1));
            mx1 = fmaxf(mx1, __shfl_xor_sync(0xffffffffu, mx1, 2));
            float mn0 = fmaxf(m0s, mx0), mn1 = fmaxf(m1s, mx1);
            float cr0 = __expf(m0s - mn0), cr1 = __expf(m1s - mn1);
            m0s = mn0; m1s = mn1;

            float sum0 = 0.0f, sum1 = 0.0f;
            uint32_t aPh[4][4], aPl[4][4];
#pragma unroll
            for (int jp = 0; jp < 4; jp++) {
#pragma unroll
                for (int u = 0; u < 2; u++) {
                    int j = 2 * jp + u;
                    float p0 = __expf(sc[j][0] - mn0);
                    float p1 = __expf(sc[j][1] - mn0);
                    float p2 = __expf(sc[j][2] - mn1);
                    float p3 = __expf(sc[j][3] - mn1);
                    sum0 += p0 + p1;
                    sum1 += p2 + p3;
                    __nv_bfloat16 h0 = __float2bfloat16_rn(p0);
                    __nv_bfloat16 h1 = __float2bfloat16_rn(p1);
                    __nv_bfloat16 h2 = __float2bfloat16_rn(p2);
                    __nv_bfloat16 h3 = __float2bfloat16_rn(p3);
                    aPh[jp][2*u]     = pack2(h0, h1);
                    aPh[jp][2*u + 1] = pack2(h2, h3);
                    aPl[jp][2*u]     = pack2(__float2bfloat16_rn(p0 - __bfloat162float(h0)),
                                             __float2bfloat16_rn(p1 - __bfloat162float(h1)));
                    aPl[jp][2*u + 1] = pack2(__float2bfloat16_rn(p2 - __bfloat162float(h2)),
                                             __float2bfloat16_rn(p3 - __bfloat162float(h3)));
                }
            }
            sum0 += __shfl_xor_sync(0xffffffffu, sum0, 1);
            sum0 += __shfl_xor_sync(0xffffffffu, sum0, 2);
            sum1 += __shfl_xor_sync(0xffffffffu, sum1, 1);
            sum1 += __shfl_xor_sync(0xffffffffu, sum1, 2);
            l0s = l0s * cr0 + sum0;
            l1s = l1s * cr1 + sum1;

#pragma unroll
            for (int j = 0; j < 8; j++) {
                accO[j][0] *= cr0; accO[j][1] *= cr0;
                accO[j][2] *= cr1; accO[j][3] *= cr1;
            }

#pragma unroll
            for (int s = 0; s < 4; s++) {
                uint32_t bVh[8][2], bVl[8][2];
#pragma unroll
                for (int jp = 0; jp < 4; jp++) {
                    int row = 16 * s + ((lane >> 3) & 1) * 8 + (lane & 7);
                    int cb  = 2 * jp + (lane >> 4);
                    uint32_t ad = kvb + 16384 + row * 128 + ((cb ^ (row & 7)) << 4);
                    LDSM_X4_T(bVh[2*jp][0], bVh[2*jp][1], bVh[2*jp+1][0], bVh[2*jp+1][1], ad);
                    LDSM_X4_T(bVl[2*jp][0], bVl[2*jp][1], bVl[2*jp+1][0], bVl[2*jp+1][1], ad + 8192);
                }
#pragma unroll
                for (int j = 0; j < 8; j++) {
                    MMA16816(accO[j], aPh[s], bVh[j][0], bVh[j][1]);
                    MMA16816(accO[j], aPh[s], bVl[j][0], bVl[j][1]);
                    MMA16816(accO[j], aPl[s], bVh[j][0], bVh[j][1]);
                }
            }
        }
        __syncthreads();
    }

    // normalize + store as bf16 hi/lo
    const float i0 = 1.0f / l0s, i1 = 1.0f / l1s;
    const int b = bh >> 4, h = bh & 15;
    const size_t o0 = ((size_t)b * T_ + r0g) * C_ + h * 64 + 2 * (lane & 3);
    const size_t o1 = ((size_t)b * T_ + r1g) * C_ + h * 64 + 2 * (lane & 3);
#pragma unroll
    for (int j = 0; j < 8; j++) {
        __nv_bfloat162 lo;
        __nv_bfloat162 hi = split_hi2(accO[j][0] * i0, accO[j][1] * i0, &lo);
        *(__nv_bfloat162*)&Yh[o0 + 8 * j] = hi;
        *(__nv_bfloat162*)&Yl[o0 + 8 * j] = lo;
        hi = split_hi2(accO[j][2] * i1, accO[j][3] * i1, &lo);
        *(__nv_bfloat162*)&Yh[o1 + 8 * j] = hi;
        *(__nv_bfloat162*)&Yl[o1 + 8 * j] = lo;
    }
}

// ---------------------------------------------------------------------------
extern "C" void kernel_launch(void* const* d_in, const int* in_sizes, int n_in,
                              void* d_out, int out_size)
{
    const float* X  = (const float*)d_in[0];
    const float* Wq = (const float*)d_in[1];
    const float* Wk = (const float*)d_in[2];
    const float* Wv = (const float*)d_in[3];
    const float* Wo = (const float*)d_in[4];
    const float* bo = (const float*)d_in[5];
    float* out = (float*)d_out;

    __nv_bfloat16 *xh, *xl, *wh, *wl, *woh, *wol, *yh, *yl;
    __nv_bfloat16 *qh, *ql, *kh, *kl, *vh, *vl;
    cudaGetSymbolAddress((void**)&xh, g_Xhi);
    cudaGetSymbolAddress((void**)&xl, g_Xlo);
    cudaGetSymbolAddress((void**)&wh, g_Wh);
    cudaGetSymbolAddress((void**)&wl, g_Wl);
    cudaGetSymbolAddress((void**)&woh, g_Wohi);
    cudaGetSymbolAddress((void**)&wol, g_Wolo);
    cudaGetSymbolAddress((void**)&yh, g_Yhi);
    cudaGetSymbolAddress((void**)&yl, g_Ylo);
    cudaGetSymbolAddress((void**)&qh, g_Qhi);
    cudaGetSymbolAddress((void**)&ql, g_Qlo);
    cudaGetSymbolAddress((void**)&kh, g_Khi);
    cudaGetSymbolAddress((void**)&kl, g_Klo);
    cudaGetSymbolAddress((void**)&vh, g_Vhi);
    cudaGetSymbolAddress((void**)&vl, g_Vlo);

    // hi/lo split converts: X (one launch) + all four weights (one launch)
    cvt_kernel<<<(M_ * C_ / 4 + 255) / 256, 256>>>(X, xh, xl, M_ * C_ / 4);
    cvt_w_kernel<<<dim3((C_ * C_ / 4 + 255) / 256, 4), 256>>>(
        Wq, Wk, Wv, Wo, wh, wl, woh, wol);

    // QKV projections (HMMA v1) -> bf16 hi/lo split-head
    const int smem_tc = 2 * STAGE_B;
    cudaFuncSetAttribute((const void*)tc_gemm_qkv,
                         cudaFuncAttributeMaxDynamicSharedMemorySize, smem_tc);
    tc_gemm_qkv<<<dim3(C_ / 128, M_ / 128, 3), 256, smem_tc>>>(
        xh, xl, wh, wl, qh, ql, kh, kl, vh, vl);

    // Attention (HMMA flash) -> bf16 hi/lo Y
    cudaFuncSetAttribute((const void*)attn_hmma,
                         cudaFuncAttributeMaxDynamicSharedMemorySize, ATT_SMEM);
    attn_hmma<<<dim3(T_ / 128, B_ * H_), 256, ATT_SMEM>>>(qh, ql, kh, kl, vh, vl, yh, yl);

    // Output projection (HMMA v1)
    cudaFuncSetAttribute((const void*)tc_gemm_out,
                         cudaFuncAttributeMaxDynamicSharedMemorySize, smem_tc);
    tc_gemm_out<<<dim3(C_ / 128, M_ / 128), 256, smem_tc>>>(yh, yl, woh, wol, bo, out);
}

// round 12
// speedup vs baseline: 1.1105x; 1.0220x over previous
#include <cuda_runtime.h>
#include <cuda_bf16.h>
#include <cstdint>

// Problem constants
#define B_ 4
#define T_ 2048
#define C_ 1024
#define H_ 16
#define D_ 64
#define M_ (B_ * T_)   // 8192 rows

// ---------------------------------------------------------------------------
// Scratch (allocation-free rule: __device__ globals)
// ---------------------------------------------------------------------------
__device__ __align__(16) __nv_bfloat16 g_Xhi[(size_t)M_ * C_];
__device__ __align__(16) __nv_bfloat16 g_Xlo[(size_t)M_ * C_];
__device__ __align__(16) __nv_bfloat16 g_Wh[(size_t)3 * C_ * C_];
__device__ __align__(16) __nv_bfloat16 g_Wl[(size_t)3 * C_ * C_];
__device__ __align__(16) __nv_bfloat16 g_Wohi[(size_t)C_ * C_];
__device__ __align__(16) __nv_bfloat16 g_Wolo[(size_t)C_ * C_];
__device__ __align__(16) __nv_bfloat16 g_Yhi[(size_t)M_ * C_];
__device__ __align__(16) __nv_bfloat16 g_Ylo[(size_t)M_ * C_];
__device__ __align__(16) __nv_bfloat16 g_Qhi[(size_t)B_ * H_ * T_ * D_];
__device__ __align__(16) __nv_bfloat16 g_Qlo[(size_t)B_ * H_ * T_ * D_];
__device__ __align__(16) __nv_bfloat16 g_Khi[(size_t)B_ * H_ * T_ * D_];
__device__ __align__(16) __nv_bfloat16 g_Klo[(size_t)B_ * H_ * T_ * D_];
__device__ __align__(16) __nv_bfloat16 g_Vhi[(size_t)B_ * H_ * T_ * D_];
__device__ __align__(16) __nv_bfloat16 g_Vlo[(size_t)B_ * H_ * T_ * D_];

// ---------------------------------------------------------------------------
// Helpers
// ---------------------------------------------------------------------------
__device__ __forceinline__ uint32_t smem_u32(const void* p) {
    uint32_t a;
    asm("{ .reg .u64 t; cvta.to.shared.u64 t, %1; cvt.u32.u64 %0, t; }"
        : "=r"(a) : "l"(p));
    return a;
}

#define CP_ASYNC16(dst, src) \
    asm volatile("cp.async.cg.shared.global [%0], [%1], 16;" \
                 :: "r"(dst), "l"(src) : "memory")
#define CP_COMMIT()  asm volatile("cp.async.commit_group;" ::: "memory")
#define CP_WAIT(n)   asm volatile("cp.async.wait_group %0;" :: "n"(n) : "memory")

#define LDSM_X4(r0, r1, r2, r3, addr) \
    asm volatile("ldmatrix.sync.aligned.m8n8.x4.shared.b16 {%0,%1,%2,%3}, [%4];" \
                 : "=r"(r0), "=r"(r1), "=r"(r2), "=r"(r3) : "r"(addr))

#define LDSM_X4_T(r0, r1, r2, r3, addr) \
    asm volatile("ldmatrix.sync.aligned.m8n8.x4.trans.shared.b16 {%0,%1,%2,%3}, [%4];" \
                 : "=r"(r0), "=r"(r1), "=r"(r2), "=r"(r3) : "r"(addr))

#define MMA16816(d, a, b0, b1) \
    asm volatile("mma.sync.aligned.m16n8k16.row.col.f32.bf16.bf16.f32 " \
                 "{%0,%1,%2,%3}, {%4,%5,%6,%7}, {%8,%9}, {%0,%1,%2,%3};" \
                 : "+f"((d)[0]), "+f"((d)[1]), "+f"((d)[2]), "+f"((d)[3]) \
                 : "r"((a)[0]), "r"((a)[1]), "r"((a)[2]), "r"((a)[3]), \
                   "r"(b0), "r"(b1))

__device__ __forceinline__ uint32_t pack2(__nv_bfloat16 a, __nv_bfloat16 b) {
    __nv_bfloat162 v = __halves2bfloat162(a, b);
    return *reinterpret_cast<uint32_t*>(&v);
}

__device__ __forceinline__ __nv_bfloat162 split_hi2(float x, float y,
                                                    __nv_bfloat162* lo) {
    __nv_bfloat16 h0 = __float2bfloat16_rn(x);
    __nv_bfloat16 h1 = __float2bfloat16_rn(y);
    *lo = __halves2bfloat162(__float2bfloat16_rn(x - __bfloat162float(h0)),
                             __float2bfloat16_rn(y - __bfloat162float(h1)));
    return __halves2bfloat162(h0, h1);
}

// ---------------------------------------------------------------------------
// fp32 -> bf16 hi/lo split.  cvt_w: one launch converts all 4 weight mats.
// ---------------------------------------------------------------------------
__device__ __forceinline__
void cvt_body(const float* __restrict__ in, __nv_bfloat16* __restrict__ hi,
              __nv_bfloat16* __restrict__ lo, int i)
{
    float4 v = ((const float4*)in)[i];
    __nv_bfloat162 l01, l23;
    __nv_bfloat162 h01 = split_hi2(v.x, v.y, &l01);
    __nv_bfloat162 h23 = split_hi2(v.z, v.w, &l23);
    ((__nv_bfloat162*)hi)[2 * i]     = h01;
    ((__nv_bfloat162*)hi)[2 * i + 1] = h23;
    ((__nv_bfloat162*)lo)[2 * i]     = l01;
    ((__nv_bfloat162*)lo)[2 * i + 1] = l23;
}

__global__ __launch_bounds__(256)
void cvt_kernel(const float* __restrict__ in, __nv_bfloat16* __restrict__ hi,
                __nv_bfloat16* __restrict__ lo, int n4)
{
    int i = blockIdx.x * 256 + threadIdx.x;
    if (i < n4) cvt_body(in, hi, lo, i);
}

__global__ __launch_bounds__(256)
void cvt_w_kernel(const float* __restrict__ Wq, const float* __restrict__ Wk,
                  const float* __restrict__ Wv, const float* __restrict__ Wo,
                  __nv_bfloat16* __restrict__ Wh, __nv_bfloat16* __restrict__ Wl,
                  __nv_bfloat16* __restrict__ Woh, __nv_bfloat16* __restrict__ Wol)
{
    const int z = blockIdx.y;
    const float* in = (z == 0) ? Wq : (z == 1) ? Wk : (z == 2) ? Wv : Wo;
    __nv_bfloat16* hi = (z < 3) ? (Wh + (size_t)z * C_ * C_) : Woh;
    __nv_bfloat16* lo = (z < 3) ? (Wl + (size_t)z * C_ * C_) : Wol;
    int i = blockIdx.x * 256 + threadIdx.x;
    if (i < C_ * C_ / 4) cvt_body(in, hi, lo, i);
}

// ---------------------------------------------------------------------------
// HMMA bf16 GEMM v1 (extended-K hi/lo split), BM=128, BN=128, BK=64,
// 2-stage cp.async pipeline. 8 warps: 4(M) x 2(N), warp tile 32x64.
// (Proven 968us configuration — unchanged this round.)
// MODE 0: fp32 [M,N] + bias.   MODE 1: bf16 hi/lo split-head [b,h,t,d].
// ---------------------------------------------------------------------------
#define NKCH 48
#define STAGE_B 32768

__device__ __forceinline__
void issue_chunk(uint32_t sbase, const __nv_bfloat16* __restrict__ Aseg,
                 const __nv_bfloat16* __restrict__ Bseg,
                 int m0, int n0, int k_in, int t)
{
#pragma unroll
    for (int rep = 0; rep < 4; rep++) {
        int idx = t + rep * 256;
        int r = idx >> 3, s = idx & 7;
        uint32_t dstA = sbase + r * 128 + ((s ^ (r & 7)) << 4);
        CP_ASYNC16(dstA, (const void*)(Aseg + (size_t)(m0 + r) * C_ + k_in + s * 8));
        CP_ASYNC16(dstA + 16384,
                   (const void*)(Bseg + (size_t)(n0 + r) * C_ + k_in + s * 8));
    }
}

__device__ __forceinline__
void seg_sel(int kn, const __nv_bfloat16* Ahi, const __nv_bfloat16* Alo,
             const __nv_bfloat16* Whi, const __nv_bfloat16* Wlo,
             const __nv_bfloat16** Aseg, const __nv_bfloat16** Bseg)
{
    *Aseg = (kn < 32) ? Ahi : Alo;
    *Bseg = (kn < 16) ? Whi : (kn < 32 ? Wlo : Whi);
}

template <int MODE>
__device__ __forceinline__
void hmma_gemm_body(const __nv_bfloat16* __restrict__ Ahi,
                    const __nv_bfloat16* __restrict__ Alo,
                    const __nv_bfloat16* __restrict__ Whi,
                    const __nv_bfloat16* __restrict__ Wlo,
                    const float* __restrict__ bias, float* __restrict__ out,
                    __nv_bfloat16* __restrict__ ohi, __nv_bfloat16* __restrict__ olo)
{
    extern __shared__ __align__(128) char sm[];
    const uint32_t sm0 = smem_u32(sm);
    const int t    = threadIdx.x;
    const int lane = t & 31;
    const int w    = t >> 5;
    const int wm   = w & 3;             // m offset 32*wm
    const int wn   = w >> 2;            // n offset 64*wn
    const int m0   = blockIdx.y * 128;
    const int n0   = blockIdx.x * 128;

    const int l4 = lane >> 4;
    uint32_t baseA[2], baseB[4];
#pragma unroll
    for (int mt = 0; mt < 2; mt++) {
        int m_l = wm * 32 + mt * 16 + ((lane >> 3) & 1) * 8 + (lane & 7);
        baseA[mt] = m_l * 128 + (((m_l & 7) ^ l4) << 4);
    }
#pragma unroll
    for (int j = 0; j < 4; j++) {
        int n_l = wn * 64 + j * 16 + ((lane >> 3) & 1) * 8 + (lane & 7);
        baseB[j] = 16384 + n_l * 128 + (((n_l & 7) ^ l4) << 4);
    }

    float acc[2][8][4];
#pragma unroll
    for (int mt = 0; mt < 2; mt++)
#pragma unroll
        for (int nt = 0; nt < 8; nt++)
#pragma unroll
            for (int e = 0; e < 4; e++) acc[mt][nt][e] = 0.0f;

    {
        const __nv_bfloat16 *As, *Bs;
        seg_sel(0, Ahi, Alo, Whi, Wlo, &As, &Bs);
        issue_chunk(sm0, As, Bs, m0, n0, 0, t);
        CP_COMMIT();
    }

    for (int kc = 0; kc < NKCH; kc++) {
        __syncthreads();
        if (kc + 1 < NKCH) {
            const int kn = kc + 1;
            const __nv_bfloat16 *As, *Bs;
            seg_sel(kn, Ahi, Alo, Whi, Wlo, &As, &Bs);
            issue_chunk(sm0 + ((kn & 1) ? STAGE_B : 0), As, Bs,
                        m0, n0, (kn & 15) * 64, t);
            CP_COMMIT();
            CP_WAIT(1);
        } else {
            CP_WAIT(0);
        }
        __syncthreads();

        const uint32_t sbase = sm0 + ((kc & 1) ? STAGE_B : 0);
#pragma unroll
        for (int kk = 0; kk < 4; kk++) {
            uint32_t a[2][4], b[4][4];
#pragma unroll
            for (int mt = 0; mt < 2; mt++)
                LDSM_X4(a[mt][0], a[mt][1], a[mt][2], a[mt][3],
                        sbase + (baseA[mt] ^ (kk << 5)));
#pragma unroll
            for (int j = 0; j < 4; j++)
                LDSM_X4(b[j][0], b[j][1], b[j][2], b[j][3],
                        sbase + (baseB[j] ^ (kk << 5)));
#pragma unroll
            for (int mt = 0; mt < 2; mt++)
#pragma unroll
                for (int nt = 0; nt < 8; nt++)
                    MMA16816(acc[mt][nt], a[mt],
                             b[nt >> 1][nt & 1], b[nt >> 1][(nt & 1) + 2]);
        }
    }

    // Epilogue
    const int qrow = lane >> 2;
    const int qcol = (lane & 3) * 2;
#pragma unroll
    for (int mt = 0; mt < 2; mt++) {
#pragma unroll
        for (int half = 0; half < 2; half++) {
            const int grow = m0 + wm * 32 + mt * 16 + half * 8 + qrow;
#pragma unroll
            for (int nt = 0; nt < 8; nt++) {
                const int gcol = n0 + wn * 64 + nt * 8 + qcol;
                float2 v = make_float2(acc[mt][nt][half * 2],
                                       acc[mt][nt][half * 2 + 1]);
                if (MODE == 0) {
                    v.x += bias[gcol];
                    v.y += bias[gcol + 1];
                    *(float2*)&out[(size_t)grow * C_ + gcol] = v;
                } else {
                    const int head = gcol >> 6, d = gcol & 63;
                    const int bb = grow >> 11, tt = grow & (T_ - 1);
                    size_t idx = (((size_t)bb * H_ + head) * T_ + tt) * D_ + d;
                    __nv_bfloat162 lo;
                    __nv_bfloat162 hi = split_hi2(v.x, v.y, &lo);
                    *(__nv_bfloat162*)&ohi[idx] = hi;
                    *(__nv_bfloat162*)&olo[idx] = lo;
                }
            }
        }
    }
}

__global__ __launch_bounds__(256)
void tc_gemm_qkv(const __nv_bfloat16* __restrict__ Xhi,
                 const __nv_bfloat16* __restrict__ Xlo,
                 const __nv_bfloat16* __restrict__ Wh,
                 const __nv_bfloat16* __restrict__ Wl,
                 __nv_bfloat16* __restrict__ Qh, __nv_bfloat16* __restrict__ Ql,
                 __nv_bfloat16* __restrict__ Kh, __nv_bfloat16* __restrict__ Kl,
                 __nv_bfloat16* __restrict__ Vh, __nv_bfloat16* __restrict__ Vl)
{
    const int z = blockIdx.z;
    const __nv_bfloat16* wh = Wh + (size_t)z * C_ * C_;
    const __nv_bfloat16* wl = Wl + (size_t)z * C_ * C_;
    __nv_bfloat16* oh = (z == 0) ? Qh : (z == 1) ? Kh : Vh;
    __nv_bfloat16* ol = (z == 0) ? Ql : (z == 1) ? Kl : Vl;
    hmma_gemm_body<1>(Xhi, Xlo, wh, wl, nullptr, nullptr, oh, ol);
}

__global__ __launch_bounds__(256)
void tc_gemm_out(const __nv_bfloat16* __restrict__ Yhi,
                 const __nv_bfloat16* __restrict__ Ylo,
                 const __nv_bfloat16* __restrict__ Wh,
                 const __nv_bfloat16* __restrict__ Wl,
                 const float* __restrict__ bias, float* __restrict__ out)
{
    hmma_gemm_body<0>(Yhi, Ylo, Wh, Wl, bias, out, nullptr, nullptr);
}

// ---------------------------------------------------------------------------
// HMMA flash attention (causal). Bit-identical math to R11; register diet:
//  - __launch_bounds__(256, 2) -> 2 CTAs/SM (was reg-limited to 1 @146 regs)
//  - Q fragments reloaded per chunk from smem (not persistent)
//  - K/V fragments processed in two halves (16 live frag regs, not 32)
// ---------------------------------------------------------------------------
#define ATT_SMEM 98304

__device__ __forceinline__
void issue_kv(uint32_t dstbase,
              const __nv_bfloat16* __restrict__ Kh, const __nv_bfloat16* __restrict__ Kl,
              const __nv_bfloat16* __restrict__ Vh, const __nv_bfloat16* __restrict__ Vl,
              int kbase, int t)
{
#pragma unroll
    for (int rep = 0; rep < 2; rep++) {
        int idx = t + rep * 256;
        int r = idx >> 3, c = idx & 7;
        uint32_t dst = dstbase + r * 128 + ((c ^ (r & 7)) << 4);
        size_t g = (size_t)(kbase + r) * D_ + c * 8;
        CP_ASYNC16(dst,          (const void*)(Kh + g));
        CP_ASYNC16(dst + 8192,   (const void*)(Kl + g));
        CP_ASYNC16(dst + 16384,  (const void*)(Vh + g));
        CP_ASYNC16(dst + 24576,  (const void*)(Vl + g));
    }
}

__global__ __launch_bounds__(256, 2)
void attn_hmma(const __nv_bfloat16* __restrict__ Qhi, const __nv_bfloat16* __restrict__ Qlo,
               const __nv_bfloat16* __restrict__ Khi, const __nv_bfloat16* __restrict__ Klo,
               const __nv_bfloat16* __restrict__ Vhi, const __nv_bfloat16* __restrict__ Vlo,
               __nv_bfloat16* __restrict__ Yh, __nv_bfloat16* __restrict__ Yl)
{
    extern __shared__ __align__(128) char sm[];
    const uint32_t s0 = smem_u32(sm);
    const int t = threadIdx.x, lane = t & 31, w = t >> 5;
    const int bh = blockIdx.y;
    const int qi = (int)(gridDim.x - 1 - blockIdx.x);
    const int qbase = qi * 128;
    const size_t base = (size_t)bh * T_ * D_;
    const __nv_bfloat16* Qh = Qhi + base + (size_t)qbase * D_;
    const __nv_bfloat16* Ql = Qlo + base + (size_t)qbase * D_;
    const __nv_bfloat16* Kh = Khi + base;
    const __nv_bfloat16* Kl = Klo + base;
    const __nv_bfloat16* Vh = Vhi + base;
    const __nv_bfloat16* Vl = Vlo + base;

#pragma unroll
    for (int rep = 0; rep < 4; rep++) {
        int idx = t + rep * 256;
        int r = idx >> 3, c = idx & 7;
        uint32_t dst = s0 + r * 128 + ((c ^ (r & 7)) << 4);
        size_t g = (size_t)r * D_ + c * 8;
        CP_ASYNC16(dst,          (const void*)(Qh + g));
        CP_ASYNC16(dst + 16384,  (const void*)(Ql + g));
    }
    CP_COMMIT();

    const int nch = 2 * qi + 2;
    issue_kv(s0 + 32768, Kh, Kl, Vh, Vl, 0, t);
    CP_COMMIT();

    CP_WAIT(1);            // Q landed
    __syncthreads();

    float accO[8][4];
#pragma unroll
    for (int j = 0; j < 8; j++)
#pragma unroll
        for (int e = 0; e < 4; e++) accO[j][e] = 0.0f;

    float m0s = -1e30f, m1s = -1e30f, l0s = 0.0f, l1s = 0.0f;
    const int r0g = qbase + 16 * w + (lane >> 2);
    const int r1g = r0g + 8;

    for (int kc = 0; kc < nch; kc++) {
        const int kbase = kc * 64;
        const int stage = kc & 1;
        if (kc + 1 < nch) {
            issue_kv(s0 + 32768 + (stage ^ 1) * 32768, Kh, Kl, Vh, Vl, kbase + 64, t);
            CP_COMMIT();
            CP_WAIT(1);
        } else {
            CP_WAIT(0);
        }
        __syncthreads();
        const uint32_t kvb = s0 + 32768 + stage * 32768;

        if (kbase <= qbase + 16 * w + 15) {
            // ---- S = Q @ K^T (16 x 64 per warp), 3-term split ----
            float sc[8][4];
#pragma unroll
            for (int j = 0; j < 8; j++)
#pragma unroll
                for (int e = 0; e < 4; e++) sc[j][e] = 0.0f;

#pragma unroll
            for (int s = 0; s < 4; s++) {
                uint32_t aQh[4], aQl[4];
                {
                    int row = 16 * w + (lane & 15);
                    int cb  = 2 * s + (lane >> 4);
                    uint32_t ad = s0 + row * 128 + ((cb ^ (row & 7)) << 4);
                    LDSM_X4(aQh[0], aQh[1], aQh[2], aQh[3], ad);
                    LDSM_X4(aQl[0], aQl[1], aQl[2], aQl[3], ad + 16384);
                }
#pragma unroll
                for (int hf = 0; hf < 2; hf++) {
                    uint32_t bKh[4][2], bKl[4][2];
#pragma unroll
                    for (int q = 0; q < 2; q++) {
                        int jp  = 2 * hf + q;
                        int row = 16 * jp + ((lane >> 4) << 3) + (lane & 7);
                        int cb  = 2 * s + ((lane >> 3) & 1);
                        uint32_t ad = kvb + row * 128 + ((cb ^ (row & 7)) << 4);
                        LDSM_X4(bKh[2*q][0], bKh[2*q][1], bKh[2*q+1][0], bKh[2*q+1][1], ad);
                        LDSM_X4(bKl[2*q][0], bKl[2*q][1], bKl[2*q+1][0], bKl[2*q+1][1], ad + 8192);
                    }
#pragma unroll
                    for (int jj = 0; jj < 4; jj++) {
                        int j = 4 * hf + jj;
                        MMA16816(sc[j], aQh, bKh[jj][0], bKh[jj][1]);
                        MMA16816(sc[j], aQh, bKl[jj][0], bKl[jj][1]);
                        MMA16816(sc[j], aQl, bKh[jj][0], bKh[jj][1]);
                    }
                }
            }

            // ---- scale + causal mask ----
            const int c0b = kbase + 2 * (lane & 3);
#pragma unroll
            for (int j = 0; j < 8; j++) {
                int cc = c0b + 8 * j;
                sc[j][0] = (cc     > r0g) ? -1e30f : sc[j][0] * 0.125f;
                sc[j][1] = (cc + 1 > r0g) ? -1e30f : sc[j][1] * 0.125f;
                sc[j][2] = (cc     > r1g) ? -1e30f : sc[j][2] * 0.125f;
                sc[j][3] = (cc + 1 > r1g) ? -1e30f : sc[j][3] * 0.125f;
            }

            // ---- online softmax (warp-local quad reduction) ----
            float mx0 = -1e30f, mx1 = -1e30f;
#pragma unroll
            for (int j = 0; j < 8; j++) {
                mx0 = fmaxf(mx0, fmaxf(sc[j][0], sc[j][1]));
                mx1 = fmaxf(mx1, fmaxf(sc[j][2], sc[j][3]));
            }
            mx0 = fmaxf(mx0, __shfl_xor_sync(0xffffffffu, mx0, 1));
            mx0 = fmaxf(mx0, __shfl_xor_sync(0xffffffffu, mx0, 2));
            mx1 = fmaxf(mx1, __shfl_xor_sync(0xffffffffu, mx1, 1));
            mx1 = fmaxf(mx1, __shfl_xor_sync(0xffffffffu, mx1, 2));
            float mn0 = fmaxf(m0s, mx0), mn1 = fmaxf(m1s, mx1);
            float cr0 = __expf(m0s - mn0), cr1 = __expf(m1s - mn1);
            m0s = mn0; m1s = mn1;

            float sum0 = 0.0f, sum1 = 0.0f;
            uint32_t aPh[4][4], aPl[4][4];
#pragma unroll
            for (int jp = 0; jp < 4; jp++) {
#pragma unroll
                for (int u = 0; u < 2; u++) {
                    int j = 2 * jp + u;
                    float p0 = __expf(sc[j][0] - mn0);
                    float p1 = __expf(sc[j][1] - mn0);
                    float p2 = __expf(sc[j][2] - mn1);
                    float p3 = __expf(sc[j][3] - mn1);
                    sum0 += p0 + p1;
                    sum1 += p2 + p3;
                    __nv_bfloat16 h0 = __float2bfloat16_rn(p0);
                    __nv_bfloat16 h1 = __float2bfloat16_rn(p1);
                    __nv_bfloat16 h2 = __float2bfloat16_rn(p2);
                    __nv_bfloat16 h3 = __float2bfloat16_rn(p3);
                    aPh[jp][2*u]     = pack2(h0, h1);
                    aPh[jp][2*u + 1] = pack2(h2, h3);
                    aPl[jp][2*u]     = pack2(__float2bfloat16_rn(p0 - __bfloat162float(h0)),
                                             __float2bfloat16_rn(p1 - __bfloat162float(h1)));
                    aPl[jp][2*u + 1] = pack2(__float2bfloat16_rn(p2 - __bfloat162float(h2)),
                                             __float2bfloat16_rn(p3 - __bfloat162float(h3)));
                }
            }
            sum0 += __shfl_xor_sync(0xffffffffu, sum0, 1);
            sum0 += __shfl_xor_sync(0xffffffffu, sum0, 2);
            sum1 += __shfl_xor_sync(0xffffffffu, sum1, 1);
            sum1 += __shfl_xor_sync(0xffffffffu, sum1, 2);
            l0s = l0s * cr0 + sum0;
            l1s = l1s * cr1 + sum1;

            // ---- rescale O, then O += P @ V (3-term split) ----
#pragma unroll
            for (int j = 0; j < 8; j++) {
                accO[j][0] *= cr0; accO[j][1] *= cr0;
                accO[j][2] *= cr1; accO[j][3] *= cr1;
            }

#pragma unroll
            for (int s = 0; s < 4; s++) {
#pragma unroll
                for (int hf = 0; hf < 2; hf++) {
                    uint32_t bVh[4][2], bVl[4][2];
#pragma unroll
                    for (int q = 0; q < 2; q++) {
                        int jp  = 2 * hf + q;
                        int row = 16 * s + ((lane >> 3) & 1) * 8 + (lane & 7);
                        int cb  = 2 * jp + (lane >> 4);
                        uint32_t ad = kvb + 16384 + row * 128 + ((cb ^ (row & 7)) << 4);
                        LDSM_X4_T(bVh[2*q][0], bVh[2*q][1], bVh[2*q+1][0], bVh[2*q+1][1], ad);
                        LDSM_X4_T(bVl[2*q][0], bVl[2*q][1], bVl[2*q+1][0], bVl[2*q+1][1], ad + 8192);
                    }
#pragma unroll
                    for (int jj = 0; jj < 4; jj++) {
                        int j = 4 * hf + jj;
                        MMA16816(accO[j], aPh[s], bVh[jj][0], bVh[jj][1]);
                        MMA16816(accO[j], aPh[s], bVl[jj][0], bVl[jj][1]);
                        MMA16816(accO[j], aPl[s], bVh[jj][0], bVh[jj][1]);
                    }
                }
            }
        }
        __syncthreads();
    }

    // normalize + store as bf16 hi/lo
    const float i0 = 1.0f / l0s, i1 = 1.0f / l1s;
    const int b = bh >> 4, h = bh & 15;
    const size_t o0 = ((size_t)b * T_ + r0g) * C_ + h * 64 + 2 * (lane & 3);
    const size_t o1 = ((size_t)b * T_ + r1g) * C_ + h * 64 + 2 * (lane & 3);
#pragma unroll
    for (int j = 0; j < 8; j++) {
        __nv_bfloat162 lo;
        __nv_bfloat162 hi = split_hi2(accO[j][0] * i0, accO[j][1] * i0, &lo);
        *(__nv_bfloat162*)&Yh[o0 + 8 * j] = hi;
        *(__nv_bfloat162*)&Yl[o0 + 8 * j] = lo;
        hi = split_hi2(accO[j][2] * i1, accO[j][3] * i1, &lo);
        *(__nv_bfloat162*)&Yh[o1 + 8 * j] = hi;
        *(__nv_bfloat162*)&Yl[o1 + 8 * j] = lo;
    }
}

// ---------------------------------------------------------------------------
extern "C" void kernel_launch(void* const* d_in, const int* in_sizes, int n_in,
                              void* d_out, int out_size)
{
    const float* X  = (const float*)d_in[0];
    const float* Wq = (const float*)d_in[1];
    const float* Wk = (const float*)d_in[2];
    const float* Wv = (const float*)d_in[3];
    const float* Wo = (const float*)d_in[4];
    const float* bo = (const float*)d_in[5];
    float* out = (float*)d_out;

    __nv_bfloat16 *xh, *xl, *wh, *wl, *woh, *wol, *yh, *yl;
    __nv_bfloat16 *qh, *ql, *kh, *kl, *vh, *vl;
    cudaGetSymbolAddress((void**)&xh, g_Xhi);
    cudaGetSymbolAddress((void**)&xl, g_Xlo);
    cudaGetSymbolAddress((void**)&wh, g_Wh);
    cudaGetSymbolAddress((void**)&wl, g_Wl);
    cudaGetSymbolAddress((void**)&woh, g_Wohi);
    cudaGetSymbolAddress((void**)&wol, g_Wolo);
    cudaGetSymbolAddress((void**)&yh, g_Yhi);
    cudaGetSymbolAddress((void**)&yl, g_Ylo);
    cudaGetSymbolAddress((void**)&qh, g_Qhi);
    cudaGetSymbolAddress((void**)&ql, g_Qlo);
    cudaGetSymbolAddress((void**)&kh, g_Khi);
    cudaGetSymbolAddress((void**)&kl, g_Klo);
    cudaGetSymbolAddress((void**)&vh, g_Vhi);
    cudaGetSymbolAddress((void**)&vl, g_Vlo);

    // hi/lo split converts: X (one launch) + all four weights (one launch)
    cvt_kernel<<<(M_ * C_ / 4 + 255) / 256, 256>>>(X, xh, xl, M_ * C_ / 4);
    cvt_w_kernel<<<dim3((C_ * C_ / 4 + 255) / 256, 4), 256>>>(
        Wq, Wk, Wv, Wo, wh, wl, woh, wol);

    // QKV projections (HMMA v1) -> bf16 hi/lo split-head
    const int smem_tc = 2 * STAGE_B;
    cudaFuncSetAttribute((const void*)tc_gemm_qkv,
                         cudaFuncAttributeMaxDynamicSharedMemorySize, smem_tc);
    tc_gemm_qkv<<<dim3(C_ / 128, M_ / 128, 3), 256, smem_tc>>>(
        xh, xl, wh, wl, qh, ql, kh, kl, vh, vl);

    // Attention (HMMA flash, 2 CTAs/SM) -> bf16 hi/lo Y
    cudaFuncSetAttribute((const void*)attn_hmma,
                         cudaFuncAttributeMaxDynamicSharedMemorySize, ATT_SMEM);
    attn_hmma<<<dim3(T_ / 128, B_ * H_), 256, ATT_SMEM>>>(qh, ql, kh, kl, vh, vl, yh, yl);

    // Output projection (HMMA v1)
    cudaFuncSetAttribute((const void*)tc_gemm_out,
                         cudaFuncAttributeMaxDynamicSharedMemorySize, smem_tc);
    tc_gemm_out<<<dim3(C_ / 128, M_ / 128), 256, smem_tc>>>(yh, yl, woh, wol, bo, out);
}

// round 13
// speedup vs baseline: 1.1126x; 1.0019x over previous
#include <cuda_runtime.h>
#include <cuda_bf16.h>
#include <cstdint>

// Problem constants
#define B_ 4
#define T_ 2048
#define C_ 1024
#define H_ 16
#define D_ 64
#define M_ (B_ * T_)   // 8192 rows

// ---------------------------------------------------------------------------
// Scratch (allocation-free rule: __device__ globals)
// ---------------------------------------------------------------------------
__device__ __align__(16) __nv_bfloat16 g_Xhi[(size_t)M_ * C_];
__device__ __align__(16) __nv_bfloat16 g_Xlo[(size_t)M_ * C_];
__device__ __align__(16) __nv_bfloat16 g_Wh[(size_t)3 * C_ * C_];
__device__ __align__(16) __nv_bfloat16 g_Wl[(size_t)3 * C_ * C_];
__device__ __align__(16) __nv_bfloat16 g_Wohi[(size_t)C_ * C_];
__device__ __align__(16) __nv_bfloat16 g_Wolo[(size_t)C_ * C_];
__device__ __align__(16) __nv_bfloat16 g_Yhi[(size_t)M_ * C_];
__device__ __align__(16) __nv_bfloat16 g_Ylo[(size_t)M_ * C_];
__device__ __align__(16) __nv_bfloat16 g_Qhi[(size_t)B_ * H_ * T_ * D_];
__device__ __align__(16) __nv_bfloat16 g_Qlo[(size_t)B_ * H_ * T_ * D_];
__device__ __align__(16) __nv_bfloat16 g_Khi[(size_t)B_ * H_ * T_ * D_];
__device__ __align__(16) __nv_bfloat16 g_Klo[(size_t)B_ * H_ * T_ * D_];
__device__ __align__(16) __nv_bfloat16 g_Vhi[(size_t)B_ * H_ * T_ * D_];
__device__ __align__(16) __nv_bfloat16 g_Vlo[(size_t)B_ * H_ * T_ * D_];

// ---------------------------------------------------------------------------
// Helpers
// ---------------------------------------------------------------------------
__device__ __forceinline__ uint32_t smem_u32(const void* p) {
    uint32_t a;
    asm("{ .reg .u64 t; cvta.to.shared.u64 t, %1; cvt.u32.u64 %0, t; }"
        : "=r"(a) : "l"(p));
    return a;
}

#define CP_ASYNC16(dst, src) \
    asm volatile("cp.async.cg.shared.global [%0], [%1], 16;" \
                 :: "r"(dst), "l"(src) : "memory")
#define CP_COMMIT()  asm volatile("cp.async.commit_group;" ::: "memory")
#define CP_WAIT(n)   asm volatile("cp.async.wait_group %0;" :: "n"(n) : "memory")

#define LDSM_X4(r0, r1, r2, r3, addr) \
    asm volatile("ldmatrix.sync.aligned.m8n8.x4.shared.b16 {%0,%1,%2,%3}, [%4];" \
                 : "=r"(r0), "=r"(r1), "=r"(r2), "=r"(r3) : "r"(addr))

#define LDSM_X4_T(r0, r1, r2, r3, addr) \
    asm volatile("ldmatrix.sync.aligned.m8n8.x4.trans.shared.b16 {%0,%1,%2,%3}, [%4];" \
                 : "=r"(r0), "=r"(r1), "=r"(r2), "=r"(r3) : "r"(addr))

#define MMA16816(d, a, b0, b1) \
    asm volatile("mma.sync.aligned.m16n8k16.row.col.f32.bf16.bf16.f32 " \
                 "{%0,%1,%2,%3}, {%4,%5,%6,%7}, {%8,%9}, {%0,%1,%2,%3};" \
                 : "+f"((d)[0]), "+f"((d)[1]), "+f"((d)[2]), "+f"((d)[3]) \
                 : "r"((a)[0]), "r"((a)[1]), "r"((a)[2]), "r"((a)[3]), \
                   "r"(b0), "r"(b1))

// Pack two fp32 -> bf16x2 in one instruction (low half = lo, high half = hi).
__device__ __forceinline__ uint32_t cvt2_bf16(float lo, float hi) {
    uint32_t r;
    asm("cvt.rn.bf16x2.f32 %0, %1, %2;" : "=r"(r) : "f"(hi), "f"(lo));
    return r;
}

__device__ __forceinline__ __nv_bfloat162 split_hi2(float x, float y,
                                                    __nv_bfloat162* lo) {
    uint32_t h = cvt2_bf16(x, y);
    __nv_bfloat162 hv = *reinterpret_cast<__nv_bfloat162*>(&h);
    float xr = x - __low2float(hv);
    float yr = y - __high2float(hv);
    uint32_t l = cvt2_bf16(xr, yr);
    *lo = *reinterpret_cast<__nv_bfloat162*>(&l);
    return hv;
}

// ---------------------------------------------------------------------------
// fp32 -> bf16 hi/lo split.  cvt_w: one launch converts all 4 weight mats.
// ---------------------------------------------------------------------------
__device__ __forceinline__
void cvt_body(const float* __restrict__ in, __nv_bfloat16* __restrict__ hi,
              __nv_bfloat16* __restrict__ lo, int i)
{
    float4 v = ((const float4*)in)[i];
    __nv_bfloat162 l01, l23;
    __nv_bfloat162 h01 = split_hi2(v.x, v.y, &l01);
    __nv_bfloat162 h23 = split_hi2(v.z, v.w, &l23);
    ((__nv_bfloat162*)hi)[2 * i]     = h01;
    ((__nv_bfloat162*)hi)[2 * i + 1] = h23;
    ((__nv_bfloat162*)lo)[2 * i]     = l01;
    ((__nv_bfloat162*)lo)[2 * i + 1] = l23;
}

__global__ __launch_bounds__(256)
void cvt_kernel(const float* __restrict__ in, __nv_bfloat16* __restrict__ hi,
                __nv_bfloat16* __restrict__ lo, int n4)
{
    int i = blockIdx.x * 256 + threadIdx.x;
    if (i < n4) cvt_body(in, hi, lo, i);
}

__global__ __launch_bounds__(256)
void cvt_w_kernel(const float* __restrict__ Wq, const float* __restrict__ Wk,
                  const float* __restrict__ Wv, const float* __restrict__ Wo,
                  __nv_bfloat16* __restrict__ Wh, __nv_bfloat16* __restrict__ Wl,
                  __nv_bfloat16* __restrict__ Woh, __nv_bfloat16* __restrict__ Wol)
{
    const int z = blockIdx.y;
    const float* in = (z == 0) ? Wq : (z == 1) ? Wk : (z == 2) ? Wv : Wo;
    __nv_bfloat16* hi = (z < 3) ? (Wh + (size_t)z * C_ * C_) : Woh;
    __nv_bfloat16* lo = (z < 3) ? (Wl + (size_t)z * C_ * C_) : Wol;
    int i = blockIdx.x * 256 + threadIdx.x;
    if (i < C_ * C_ / 4) cvt_body(in, hi, lo, i);
}

// ---------------------------------------------------------------------------
// HMMA bf16 GEMM v3 (extended-K hi/lo split), BM=128, BN=128, BK=64.
// Same tiles/fragments as the proven v1; pipeline upgraded to a 3-stage ring
// with ONE __syncthreads per chunk:  [wait(1); sync; compute(k); issue(k+2)].
// The top sync of iter k separates compute(k-1) from the issue into its
// buffer ((k+2)%3 == (k-1)%3); wait(1) means chunk k landed a full
// iteration ago (no exposed cp.async latency).
// MODE 0: fp32 [M,N] + bias.   MODE 1: bf16 hi/lo split-head [b,h,t,d].
// ---------------------------------------------------------------------------
#define NKCH 48
#define STAGE_B 32768
#define G_SMEM (3 * STAGE_B)

__device__ __forceinline__
void issue_chunk(uint32_t sbase, const __nv_bfloat16* __restrict__ Aseg,
                 const __nv_bfloat16* __restrict__ Bseg,
                 int m0, int n0, int k_in, int t)
{
#pragma unroll
    for (int rep = 0; rep < 4; rep++) {
        int idx = t + rep * 256;
        int r = idx >> 3, s = idx & 7;
        uint32_t dstA = sbase + r * 128 + ((s ^ (r & 7)) << 4);
        CP_ASYNC16(dstA, (const void*)(Aseg + (size_t)(m0 + r) * C_ + k_in + s * 8));
        CP_ASYNC16(dstA + 16384,
                   (const void*)(Bseg + (size_t)(n0 + r) * C_ + k_in + s * 8));
    }
}

__device__ __forceinline__
void seg_sel(int kn, const __nv_bfloat16* Ahi, const __nv_bfloat16* Alo,
             const __nv_bfloat16* Whi, const __nv_bfloat16* Wlo,
             const __nv_bfloat16** Aseg, const __nv_bfloat16** Bseg)
{
    *Aseg = (kn < 32) ? Ahi : Alo;
    *Bseg = (kn < 16) ? Whi : (kn < 32 ? Wlo : Whi);
}

template <int MODE>
__device__ __forceinline__
void hmma_gemm_body(const __nv_bfloat16* __restrict__ Ahi,
                    const __nv_bfloat16* __restrict__ Alo,
                    const __nv_bfloat16* __restrict__ Whi,
                    const __nv_bfloat16* __restrict__ Wlo,
                    const float* __restrict__ bias, float* __restrict__ out,
                    __nv_bfloat16* __restrict__ ohi, __nv_bfloat16* __restrict__ olo)
{
    extern __shared__ __align__(128) char sm[];
    const uint32_t sm0 = smem_u32(sm);
    const int t    = threadIdx.x;
    const int lane = t & 31;
    const int w    = t >> 5;
    const int wm   = w & 3;             // m offset 32*wm
    const int wn   = w >> 2;            // n offset 64*wn
    const int m0   = blockIdx.y * 128;
    const int n0   = blockIdx.x * 128;

    const int l4 = lane >> 4;
    uint32_t baseA[2], baseB[4];
#pragma unroll
    for (int mt = 0; mt < 2; mt++) {
        int m_l = wm * 32 + mt * 16 + ((lane >> 3) & 1) * 8 + (lane & 7);
        baseA[mt] = m_l * 128 + (((m_l & 7) ^ l4) << 4);
    }
#pragma unroll
    for (int j = 0; j < 4; j++) {
        int n_l = wn * 64 + j * 16 + ((lane >> 3) & 1) * 8 + (lane & 7);
        baseB[j] = 16384 + n_l * 128 + (((n_l & 7) ^ l4) << 4);
    }

    float acc[2][8][4];
#pragma unroll
    for (int mt = 0; mt < 2; mt++)
#pragma unroll
        for (int nt = 0; nt < 8; nt++)
#pragma unroll
            for (int e = 0; e < 4; e++) acc[mt][nt][e] = 0.0f;

    // Prologue: chunks 0 and 1 into stages 0 and 1
    {
        const __nv_bfloat16 *As, *Bs;
        seg_sel(0, Ahi, Alo, Whi, Wlo, &As, &Bs);
        issue_chunk(sm0, As, Bs, m0, n0, 0, t);
        CP_COMMIT();
        seg_sel(1, Ahi, Alo, Whi, Wlo, &As, &Bs);
        issue_chunk(sm0 + STAGE_B, As, Bs, m0, n0, 64, t);
        CP_COMMIT();
    }

    int st = 0;  // kc % 3
    for (int kc = 0; kc < NKCH; kc++) {
        if (kc + 1 < NKCH) { CP_WAIT(1); } else { CP_WAIT(0); }
        __syncthreads();

        const uint32_t sbase = sm0 + st * STAGE_B;
#pragma unroll
        for (int kk = 0; kk < 4; kk++) {
            uint32_t a[2][4], b[4][4];
#pragma unroll
            for (int mt = 0; mt < 2; mt++)
                LDSM_X4(a[mt][0], a[mt][1], a[mt][2], a[mt][3],
                        sbase + (baseA[mt] ^ (kk << 5)));
#pragma unroll
            for (int j = 0; j < 4; j++)
                LDSM_X4(b[j][0], b[j][1], b[j][2], b[j][3],
                        sbase + (baseB[j] ^ (kk << 5)));
#pragma unroll
            for (int mt = 0; mt < 2; mt++)
#pragma unroll
                for (int nt = 0; nt < 8; nt++)
                    MMA16816(acc[mt][nt], a[mt],
                             b[nt >> 1][nt & 1], b[nt >> 1][(nt & 1) + 2]);
        }

        // Issue chunk kc+2 into stage (kc+2)%3 — its previous readers were
        // iteration kc-1, separated by this iteration's top sync.
        if (kc + 2 < NKCH) {
            const int kn = kc + 2;
            int st2 = st + 2; if (st2 >= 3) st2 -= 3;
            const __nv_bfloat16 *As, *Bs;
            seg_sel(kn, Ahi, Alo, Whi, Wlo, &As, &Bs);
            issue_chunk(sm0 + st2 * STAGE_B, As, Bs, m0, n0, (kn & 15) * 64, t);
            CP_COMMIT();
        }
        if (++st == 3) st = 0;
    }

    // Epilogue
    const int qrow = lane >> 2;
    const int qcol = (lane & 3) * 2;
#pragma unroll
    for (int mt = 0; mt < 2; mt++) {
#pragma unroll
        for (int half = 0; half < 2; half++) {
            const int grow = m0 + wm * 32 + mt * 16 + half * 8 + qrow;
#pragma unroll
            for (int nt = 0; nt < 8; nt++) {
                const int gcol = n0 + wn * 64 + nt * 8 + qcol;
                float2 v = make_float2(acc[mt][nt][half * 2],
                                       acc[mt][nt][half * 2 + 1]);
                if (MODE == 0) {
                    v.x += bias[gcol];
                    v.y += bias[gcol + 1];
                    *(float2*)&out[(size_t)grow * C_ + gcol] = v;
                } else {
                    const int head = gcol >> 6, d = gcol & 63;
                    const int bb = grow >> 11, tt = grow & (T_ - 1);
                    size_t idx = (((size_t)bb * H_ + head) * T_ + tt) * D_ + d;
                    __nv_bfloat162 lo;
                    __nv_bfloat162 hi = split_hi2(v.x, v.y, &lo);
                    *(__nv_bfloat162*)&ohi[idx] = hi;
                    *(__nv_bfloat162*)&olo[idx] = lo;
                }
            }
        }
    }
}

__global__ __launch_bounds__(256)
void tc_gemm_qkv(const __nv_bfloat16* __restrict__ Xhi,
                 const __nv_bfloat16* __restrict__ Xlo,
                 const __nv_bfloat16* __restrict__ Wh,
                 const __nv_bfloat16* __restrict__ Wl,
                 __nv_bfloat16* __restrict__ Qh, __nv_bfloat16* __restrict__ Ql,
                 __nv_bfloat16* __restrict__ Kh, __nv_bfloat16* __restrict__ Kl,
                 __nv_bfloat16* __restrict__ Vh, __nv_bfloat16* __restrict__ Vl)
{
    const int z = blockIdx.z;
    const __nv_bfloat16* wh = Wh + (size_t)z * C_ * C_;
    const __nv_bfloat16* wl = Wl + (size_t)z * C_ * C_;
    __nv_bfloat16* oh = (z == 0) ? Qh : (z == 1) ? Kh : Vh;
    __nv_bfloat16* ol = (z == 0) ? Ql : (z == 1) ? Kl : Vl;
    hmma_gemm_body<1>(Xhi, Xlo, wh, wl, nullptr, nullptr, oh, ol);
}

__global__ __launch_bounds__(256)
void tc_gemm_out(const __nv_bfloat16* __restrict__ Yhi,
                 const __nv_bfloat16* __restrict__ Ylo,
                 const __nv_bfloat16* __restrict__ Wh,
                 const __nv_bfloat16* __restrict__ Wl,
                 const float* __restrict__ bias, float* __restrict__ out)
{
    hmma_gemm_body<0>(Yhi, Ylo, Wh, Wl, bias, out, nullptr, nullptr);
}

// ---------------------------------------------------------------------------
// HMMA flash attention (causal). R12 structure (2 CTAs/SM) with a scalar
// diet: exp2-domain softmax (0.125*log2e folded into the mask-scale) and
// single-instruction bf16x2 packing for P hi/lo.
// ---------------------------------------------------------------------------
#define ATT_SMEM 98304
#define SCL 0.18033688f   // 0.125 * log2(e)

__device__ __forceinline__
void issue_kv(uint32_t dstbase,
              const __nv_bfloat16* __restrict__ Kh, const __nv_bfloat16* __restrict__ Kl,
              const __nv_bfloat16* __restrict__ Vh, const __nv_bfloat16* __restrict__ Vl,
              int kbase, int t)
{
#pragma unroll
    for (int rep = 0; rep < 2; rep++) {
        int idx = t + rep * 256;
        int r = idx >> 3, c = idx & 7;
        uint32_t dst = dstbase + r * 128 + ((c ^ (r & 7)) << 4);
        size_t g = (size_t)(kbase + r) * D_ + c * 8;
        CP_ASYNC16(dst,          (const void*)(Kh + g));
        CP_ASYNC16(dst + 8192,   (const void*)(Kl + g));
        CP_ASYNC16(dst + 16384,  (const void*)(Vh + g));
        CP_ASYNC16(dst + 24576,  (const void*)(Vl + g));
    }
}

__global__ __launch_bounds__(256, 2)
void attn_hmma(const __nv_bfloat16* __restrict__ Qhi, const __nv_bfloat16* __restrict__ Qlo,
               const __nv_bfloat16* __restrict__ Khi, const __nv_bfloat16* __restrict__ Klo,
               const __nv_bfloat16* __restrict__ Vhi, const __nv_bfloat16* __restrict__ Vlo,
               __nv_bfloat16* __restrict__ Yh, __nv_bfloat16* __restrict__ Yl)
{
    extern __shared__ __align__(128) char sm[];
    const uint32_t s0 = smem_u32(sm);
    const int t = threadIdx.x, lane = t & 31, w = t >> 5;
    const int bh = blockIdx.y;
    const int qi = (int)(gridDim.x - 1 - blockIdx.x);
    const int qbase = qi * 128;
    const size_t base = (size_t)bh * T_ * D_;
    const __nv_bfloat16* Qh = Qhi + base + (size_t)qbase * D_;
    const __nv_bfloat16* Ql = Qlo + base + (size_t)qbase * D_;
    const __nv_bfloat16* Kh = Khi + base;
    const __nv_bfloat16* Kl = Klo + base;
    const __nv_bfloat16* Vh = Vhi + base;
    const __nv_bfloat16* Vl = Vlo + base;

#pragma unroll
    for (int rep = 0; rep < 4; rep++) {
        int idx = t + rep * 256;
        int r = idx >> 3, c = idx & 7;
        uint32_t dst = s0 + r * 128 + ((c ^ (r & 7)) << 4);
        size_t g = (size_t)r * D_ + c * 8;
        CP_ASYNC16(dst,          (const void*)(Qh + g));
        CP_ASYNC16(dst + 16384,  (const void*)(Ql + g));
    }
    CP_COMMIT();

    const int nch = 2 * qi + 2;
    issue_kv(s0 + 32768, Kh, Kl, Vh, Vl, 0, t);
    CP_COMMIT();

    CP_WAIT(1);            // Q landed
    __syncthreads();

    float accO[8][4];
#pragma unroll
    for (int j = 0; j < 8; j++)
#pragma unroll
        for (int e = 0; e < 4; e++) accO[j][e] = 0.0f;

    float m0s = -1e30f, m1s = -1e30f, l0s = 0.0f, l1s = 0.0f;
    const int r0g = qbase + 16 * w + (lane >> 2);
    const int r1g = r0g + 8;

    for (int kc = 0; kc < nch; kc++) {
        const int kbase = kc * 64;
        const int stage = kc & 1;
        if (kc + 1 < nch) {
            issue_kv(s0 + 32768 + (stage ^ 1) * 32768, Kh, Kl, Vh, Vl, kbase + 64, t);
            CP_COMMIT();
            CP_WAIT(1);
        } else {
            CP_WAIT(0);
        }
        __syncthreads();
        const uint32_t kvb = s0 + 32768 + stage * 32768;

        if (kbase <= qbase + 16 * w + 15) {
            // ---- S = Q @ K^T (16 x 64 per warp), 3-term split ----
            float sc[8][4];
#pragma unroll
            for (int j = 0; j < 8; j++)
#pragma unroll
                for (int e = 0; e < 4; e++) sc[j][e] = 0.0f;

#pragma unroll
            for (int s = 0; s < 4; s++) {
                uint32_t aQh[4], aQl[4];
                {
                    int row = 16 * w + (lane & 15);
                    int cb  = 2 * s + (lane >> 4);
                    uint32_t ad = s0 + row * 128 + ((cb ^ (row & 7)) << 4);
                    LDSM_X4(aQh[0], aQh[1], aQh[2], aQh[3], ad);
                    LDSM_X4(aQl[0], aQl[1], aQl[2], aQl[3], ad + 16384);
                }
#pragma unroll
                for (int hf = 0; hf < 2; hf++) {
                    uint32_t bKh[4][2], bKl[4][2];
#pragma unroll
                    for (int q = 0; q < 2; q++) {
                        int jp  = 2 * hf + q;
                        int row = 16 * jp + ((lane >> 4) << 3) + (lane & 7);
                        int cb  = 2 * s + ((lane >> 3) & 1);
                        uint32_t ad = kvb + row * 128 + ((cb ^ (row & 7)) << 4);
                        LDSM_X4(bKh[2*q][0], bKh[2*q][1], bKh[2*q+1][0], bKh[2*q+1][1], ad);
                        LDSM_X4(bKl[2*q][0], bKl[2*q][1], bKl[2*q+1][0], bKl[2*q+1][1], ad + 8192);
                    }
#pragma unroll
                    for (int jj = 0; jj < 4; jj++) {
                        int j = 4 * hf + jj;
                        MMA16816(sc[j], aQh, bKh[jj][0], bKh[jj][1]);
                        MMA16816(sc[j], aQh, bKl[jj][0], bKl[jj][1]);
                        MMA16816(sc[j], aQl, bKh[jj][0], bKh[jj][1]);
                    }
                }
            }

            // ---- scale into exp2 domain + causal mask ----
            const int c0b = kbase + 2 * (lane & 3);
#pragma unroll
            for (int j = 0; j < 8; j++) {
                int cc = c0b + 8 * j;
                sc[j][0] = (cc     > r0g) ? -1e30f : sc[j][0] * SCL;
                sc[j][1] = (cc + 1 > r0g) ? -1e30f : sc[j][1] * SCL;
                sc[j][2] = (cc     > r1g) ? -1e30f : sc[j][2] * SCL;
                sc[j][3] = (cc + 1 > r1g) ? -1e30f : sc[j][3] * SCL;
            }

            // ---- online softmax (warp-local quad reduction, exp2 domain) ----
            float mx0 = -1e30f, mx1 = -1e30f;
#pragma unroll
            for (int j = 0; j < 8; j++) {
                mx0 = fmaxf(mx0, fmaxf(sc[j][0], sc[j][1]));
                mx1 = fmaxf(mx1, fmaxf(sc[j][2], sc[j][3]));
            }
            mx0 = fmaxf(mx0, __shfl_xor_sync(0xffffffffu, mx0, 1));
            mx0 = fmaxf(mx0, __shfl_xor_sync(0xffffffffu, mx0, 2));
            mx1 = fmaxf(mx1, __shfl_xor_sync(0xffffffffu, mx1, 1));
            mx1 = fmaxf(mx1, __shfl_xor_sync(0xffffffffu, mx1, 2));
            float mn0 = fmaxf(m0s, mx0), mn1 = fmaxf(m1s, mx1);
            float cr0 = exp2f(m0s - mn0), cr1 = exp2f(m1s - mn1);
            m0s = mn0; m1s = mn1;

            float sum0 = 0.0f, sum1 = 0.0f;
            uint32_t aPh[4][4], aPl[4][4];
#pragma unroll
            for (int jp = 0; jp < 4; jp++) {
#pragma unroll
                for (int u = 0; u < 2; u++) {
                    int j = 2 * jp + u;
                    float p0 = exp2f(sc[j][0] - mn0);
                    float p1 = exp2f(sc[j][1] - mn0);
                    float p2 = exp2f(sc[j][2] - mn1);
                    float p3 = exp2f(sc[j][3] - mn1);
                    sum0 += p0 + p1;
                    sum1 += p2 + p3;
                    uint32_t hA = cvt2_bf16(p0, p1);
                    uint32_t hB = cvt2_bf16(p2, p3);
                    aPh[jp][2*u]     = hA;
                    aPh[jp][2*u + 1] = hB;
                    __nv_bfloat162 hA2 = *reinterpret_cast<__nv_bfloat162*>(&hA);
                    __nv_bfloat162 hB2 = *reinterpret_cast<__nv_bfloat162*>(&hB);
                    aPl[jp][2*u]     = cvt2_bf16(p0 - __low2float(hA2),
                                                 p1 - __high2float(hA2));
                    aPl[jp][2*u + 1] = cvt2_bf16(p2 - __low2float(hB2),
                                                 p3 - __high2float(hB2));
                }
            }
            sum0 += __shfl_xor_sync(0xffffffffu, sum0, 1);
            sum0 += __shfl_xor_sync(0xffffffffu, sum0, 2);
            sum1 += __shfl_xor_sync(0xffffffffu, sum1, 1);
            sum1 += __shfl_xor_sync(0xffffffffu, sum1, 2);
            l0s = l0s * cr0 + sum0;
            l1s = l1s * cr1 + sum1;

            // ---- rescale O, then O += P @ V (3-term split) ----
#pragma unroll
            for (int j = 0; j < 8; j++) {
                accO[j][0] *= cr0; accO[j][1] *= cr0;
                accO[j][2] *= cr1; accO[j][3] *= cr1;
            }

#pragma unroll
            for (int s = 0; s < 4; s++) {
#pragma unroll
                for (int hf = 0; hf < 2; hf++) {
                    uint32_t bVh[4][2], bVl[4][2];
#pragma unroll
                    for (int q = 0; q < 2; q++) {
                        int jp  = 2 * hf + q;
                        int row = 16 * s + ((lane >> 3) & 1) * 8 + (lane & 7);
                        int cb  = 2 * jp + (lane >> 4);
                        uint32_t ad = kvb + 16384 + row * 128 + ((cb ^ (row & 7)) << 4);
                        LDSM_X4_T(bVh[2*q][0], bVh[2*q][1], bVh[2*q+1][0], bVh[2*q+1][1], ad);
                        LDSM_X4_T(bVl[2*q][0], bVl[2*q][1], bVl[2*q+1][0], bVl[2*q+1][1], ad + 8192);
                    }
#pragma unroll
                    for (int jj = 0; jj < 4; jj++) {
                        int j = 4 * hf + jj;
                        MMA16816(accO[j], aPh[s], bVh[jj][0], bVh[jj][1]);
                        MMA16816(accO[j], aPh[s], bVl[jj][0], bVl[jj][1]);
                        MMA16816(accO[j], aPl[s], bVh[jj][0], bVh[jj][1]);
                    }
                }
            }
        }
        __syncthreads();
    }

    // normalize + store as bf16 hi/lo
    const float i0 = 1.0f / l0s, i1 = 1.0f / l1s;
    const int b = bh >> 4, h = bh & 15;
    const size_t o0 = ((size_t)b * T_ + r0g) * C_ + h * 64 + 2 * (lane & 3);
    const size_t o1 = ((size_t)b * T_ + r1g) * C_ + h * 64 + 2 * (lane & 3);
#pragma unroll
    for (int j = 0; j < 8; j++) {
        __nv_bfloat162 lo;
        __nv_bfloat162 hi = split_hi2(accO[j][0] * i0, accO[j][1] * i0, &lo);
        *(__nv_bfloat162*)&Yh[o0 + 8 * j] = hi;
        *(__nv_bfloat162*)&Yl[o0 + 8 * j] = lo;
        hi = split_hi2(accO[j][2] * i1, accO[j][3] * i1, &lo);
        *(__nv_bfloat162*)&Yh[o1 + 8 * j] = hi;
        *(__nv_bfloat162*)&Yl[o1 + 8 * j] = lo;
    }
}

// ---------------------------------------------------------------------------
extern "C" void kernel_launch(void* const* d_in, const int* in_sizes, int n_in,
                              void* d_out, int out_size)
{
    const float* X  = (const float*)d_in[0];
    const float* Wq = (const float*)d_in[1];
    const float* Wk = (const float*)d_in[2];
    const float* Wv = (const float*)d_in[3];
    const float* Wo = (const float*)d_in[4];
    const float* bo = (const float*)d_in[5];
    float* out = (float*)d_out;

    __nv_bfloat16 *xh, *xl, *wh, *wl, *woh, *wol, *yh, *yl;
    __nv_bfloat16 *qh, *ql, *kh, *kl, *vh, *vl;
    cudaGetSymbolAddress((void**)&xh, g_Xhi);
    cudaGetSymbolAddress((void**)&xl, g_Xlo);
    cudaGetSymbolAddress((void**)&wh, g_Wh);
    cudaGetSymbolAddress((void**)&wl, g_Wl);
    cudaGetSymbolAddress((void**)&woh, g_Wohi);
    cudaGetSymbolAddress((void**)&wol, g_Wolo);
    cudaGetSymbolAddress((void**)&yh, g_Yhi);
    cudaGetSymbolAddress((void**)&yl, g_Ylo);
    cudaGetSymbolAddress((void**)&qh, g_Qhi);
    cudaGetSymbolAddress((void**)&ql, g_Qlo);
    cudaGetSymbolAddress((void**)&kh, g_Khi);
    cudaGetSymbolAddress((void**)&kl, g_Klo);
    cudaGetSymbolAddress((void**)&vh, g_Vhi);
    cudaGetSymbolAddress((void**)&vl, g_Vlo);

    // hi/lo split converts: X (one launch) + all four weights (one launch)
    cvt_kernel<<<(M_ * C_ / 4 + 255) / 256, 256>>>(X, xh, xl, M_ * C_ / 4);
    cvt_w_kernel<<<dim3((C_ * C_ / 4 + 255) / 256, 4), 256>>>(
        Wq, Wk, Wv, Wo, wh, wl, woh, wol);

    // QKV projections (HMMA v3, 3-stage single-sync) -> bf16 hi/lo split-head
    cudaFuncSetAttribute((const void*)tc_gemm_qkv,
                         cudaFuncAttributeMaxDynamicSharedMemorySize, G_SMEM);
    tc_gemm_qkv<<<dim3(C_ / 128, M_ / 128, 3), 256, G_SMEM>>>(
        xh, xl, wh, wl, qh, ql, kh, kl, vh, vl);

    // Attention (HMMA flash, 2 CTAs/SM) -> bf16 hi/lo Y
    cudaFuncSetAttribute((const void*)attn_hmma,
                         cudaFuncAttributeMaxDynamicSharedMemorySize, ATT_SMEM);
    attn_hmma<<<dim3(T_ / 128, B_ * H_), 256, ATT_SMEM>>>(qh, ql, kh, kl, vh, vl, yh, yl);

    // Output projection (HMMA v3)
    cudaFuncSetAttribute((const void*)tc_gemm_out,
                         cudaFuncAttributeMaxDynamicSharedMemorySize, G_SMEM);
    tc_gemm_out<<<dim3(C_ / 128, M_ / 128), 256, G_SMEM>>>(yh, yl, woh, wol, bo, out);
}

// round 14
// speedup vs baseline: 1.1179x; 1.0047x over previous
#include <cuda_runtime.h>
#include <cuda_bf16.h>
#include <cstdint>

// Problem constants
#define B_ 4
#define T_ 2048
#define C_ 1024
#define H_ 16
#define D_ 64
#define M_ (B_ * T_)   // 8192 rows

// ---------------------------------------------------------------------------
// Scratch (allocation-free rule: __device__ globals)
// ---------------------------------------------------------------------------
__device__ __align__(16) __nv_bfloat16 g_Xhi[(size_t)M_ * C_];
__device__ __align__(16) __nv_bfloat16 g_Xlo[(size_t)M_ * C_];
__device__ __align__(16) __nv_bfloat16 g_Wh[(size_t)3 * C_ * C_];
__device__ __align__(16) __nv_bfloat16 g_Wl[(size_t)3 * C_ * C_];
__device__ __align__(16) __nv_bfloat16 g_Wohi[(size_t)C_ * C_];
__device__ __align__(16) __nv_bfloat16 g_Wolo[(size_t)C_ * C_];
__device__ __align__(16) __nv_bfloat16 g_Yhi[(size_t)M_ * C_];
__device__ __align__(16) __nv_bfloat16 g_Ylo[(size_t)M_ * C_];
__device__ __align__(16) __nv_bfloat16 g_Qhi[(size_t)B_ * H_ * T_ * D_];
__device__ __align__(16) __nv_bfloat16 g_Qlo[(size_t)B_ * H_ * T_ * D_];
__device__ __align__(16) __nv_bfloat16 g_Khi[(size_t)B_ * H_ * T_ * D_];
__device__ __align__(16) __nv_bfloat16 g_Klo[(size_t)B_ * H_ * T_ * D_];
__device__ __align__(16) __nv_bfloat16 g_Vhi[(size_t)B_ * H_ * T_ * D_];
__device__ __align__(16) __nv_bfloat16 g_Vlo[(size_t)B_ * H_ * T_ * D_];

// ---------------------------------------------------------------------------
// Helpers
// ---------------------------------------------------------------------------
__device__ __forceinline__ uint32_t smem_u32(const void* p) {
    uint32_t a;
    asm("{ .reg .u64 t; cvta.to.shared.u64 t, %1; cvt.u32.u64 %0, t; }"
        : "=r"(a) : "l"(p));
    return a;
}

#define CP_ASYNC16(dst, src) \
    asm volatile("cp.async.cg.shared.global [%0], [%1], 16;" \
                 :: "r"(dst), "l"(src) : "memory")
#define CP_COMMIT()  asm volatile("cp.async.commit_group;" ::: "memory")
#define CP_WAIT(n)   asm volatile("cp.async.wait_group %0;" :: "n"(n) : "memory")

#define LDSM_X4(r0, r1, r2, r3, addr) \
    asm volatile("ldmatrix.sync.aligned.m8n8.x4.shared.b16 {%0,%1,%2,%3}, [%4];" \
                 : "=r"(r0), "=r"(r1), "=r"(r2), "=r"(r3) : "r"(addr))

#define LDSM_X4_T(r0, r1, r2, r3, addr) \
    asm volatile("ldmatrix.sync.aligned.m8n8.x4.trans.shared.b16 {%0,%1,%2,%3}, [%4];" \
                 : "=r"(r0), "=r"(r1), "=r"(r2), "=r"(r3) : "r"(addr))

#define MMA16816(d, a, b0, b1) \
    asm volatile("mma.sync.aligned.m16n8k16.row.col.f32.bf16.bf16.f32 " \
                 "{%0,%1,%2,%3}, {%4,%5,%6,%7}, {%8,%9}, {%0,%1,%2,%3};" \
                 : "+f"((d)[0]), "+f"((d)[1]), "+f"((d)[2]), "+f"((d)[3]) \
                 : "r"((a)[0]), "r"((a)[1]), "r"((a)[2]), "r"((a)[3]), \
                   "r"(b0), "r"(b1))

// Pack two fp32 -> bf16x2 in one instruction (low half = lo, high half = hi).
__device__ __forceinline__ uint32_t cvt2_bf16(float lo, float hi) {
    uint32_t r;
    asm("cvt.rn.bf16x2.f32 %0, %1, %2;" : "=r"(r) : "f"(hi), "f"(lo));
    return r;
}

__device__ __forceinline__ __nv_bfloat162 split_hi2(float x, float y,
                                                    __nv_bfloat162* lo) {
    uint32_t h = cvt2_bf16(x, y);
    __nv_bfloat162 hv = *reinterpret_cast<__nv_bfloat162*>(&h);
    float xr = x - __low2float(hv);
    float yr = y - __high2float(hv);
    uint32_t l = cvt2_bf16(xr, yr);
    *lo = *reinterpret_cast<__nv_bfloat162*>(&l);
    return hv;
}

// ---------------------------------------------------------------------------
// fp32 -> bf16 hi/lo split.  cvt_w: one launch converts all 4 weight mats.
// ---------------------------------------------------------------------------
__device__ __forceinline__
void cvt_body(const float* __restrict__ in, __nv_bfloat16* __restrict__ hi,
              __nv_bfloat16* __restrict__ lo, int i)
{
    float4 v = ((const float4*)in)[i];
    __nv_bfloat162 l01, l23;
    __nv_bfloat162 h01 = split_hi2(v.x, v.y, &l01);
    __nv_bfloat162 h23 = split_hi2(v.z, v.w, &l23);
    ((__nv_bfloat162*)hi)[2 * i]     = h01;
    ((__nv_bfloat162*)hi)[2 * i + 1] = h23;
    ((__nv_bfloat162*)lo)[2 * i]     = l01;
    ((__nv_bfloat162*)lo)[2 * i + 1] = l23;
}

__global__ __launch_bounds__(256)
void cvt_kernel(const float* __restrict__ in, __nv_bfloat16* __restrict__ hi,
                __nv_bfloat16* __restrict__ lo, int n4)
{
    int i = blockIdx.x * 256 + threadIdx.x;
    if (i < n4) cvt_body(in, hi, lo, i);
}

__global__ __launch_bounds__(256)
void cvt_w_kernel(const float* __restrict__ Wq, const float* __restrict__ Wk,
                  const float* __restrict__ Wv, const float* __restrict__ Wo,
                  __nv_bfloat16* __restrict__ Wh, __nv_bfloat16* __restrict__ Wl,
                  __nv_bfloat16* __restrict__ Woh, __nv_bfloat16* __restrict__ Wol)
{
    const int z = blockIdx.y;
    const float* in = (z == 0) ? Wq : (z == 1) ? Wk : (z == 2) ? Wv : Wo;
    __nv_bfloat16* hi = (z < 3) ? (Wh + (size_t)z * C_ * C_) : Woh;
    __nv_bfloat16* lo = (z < 3) ? (Wl + (size_t)z * C_ * C_) : Wol;
    int i = blockIdx.x * 256 + threadIdx.x;
    if (i < C_ * C_ / 4) cvt_body(in, hi, lo, i);
}

// ---------------------------------------------------------------------------
// HMMA bf16 GEMM v3b (extended-K hi/lo split), BM=128, BN=128, BK=64,
// 3-stage ring, one __syncthreads per chunk, __launch_bounds__(256,2) to
// cap regs at 128 and get 2 CTAs/SM (96KB smem x2 = 192KB fits).
// MODE 0: fp32 [M,N] + bias.   MODE 1: bf16 hi/lo split-head [b,h,t,d].
// ---------------------------------------------------------------------------
#define NKCH 48
#define STAGE_B 32768
#define G_SMEM (3 * STAGE_B)

__device__ __forceinline__
void issue_chunk(uint32_t sbase, const __nv_bfloat16* __restrict__ Aseg,
                 const __nv_bfloat16* __restrict__ Bseg,
                 int m0, int n0, int k_in, int t)
{
#pragma unroll
    for (int rep = 0; rep < 4; rep++) {
        int idx = t + rep * 256;
        int r = idx >> 3, s = idx & 7;
        uint32_t dstA = sbase + r * 128 + ((s ^ (r & 7)) << 4);
        CP_ASYNC16(dstA, (const void*)(Aseg + (size_t)(m0 + r) * C_ + k_in + s * 8));
        CP_ASYNC16(dstA + 16384,
                   (const void*)(Bseg + (size_t)(n0 + r) * C_ + k_in + s * 8));
    }
}

__device__ __forceinline__
void seg_sel(int kn, const __nv_bfloat16* Ahi, const __nv_bfloat16* Alo,
             const __nv_bfloat16* Whi, const __nv_bfloat16* Wlo,
             const __nv_bfloat16** Aseg, const __nv_bfloat16** Bseg)
{
    *Aseg = (kn < 32) ? Ahi : Alo;
    *Bseg = (kn < 16) ? Whi : (kn < 32 ? Wlo : Whi);
}

template <int MODE>
__device__ __forceinline__
void hmma_gemm_body(const __nv_bfloat16* __restrict__ Ahi,
                    const __nv_bfloat16* __restrict__ Alo,
                    const __nv_bfloat16* __restrict__ Whi,
                    const __nv_bfloat16* __restrict__ Wlo,
                    const float* __restrict__ bias, float* __restrict__ out,
                    __nv_bfloat16* __restrict__ ohi, __nv_bfloat16* __restrict__ olo)
{
    extern __shared__ __align__(128) char sm[];
    const uint32_t sm0 = smem_u32(sm);
    const int t    = threadIdx.x;
    const int lane = t & 31;
    const int w    = t >> 5;
    const int wm   = w & 3;             // m offset 32*wm
    const int wn   = w >> 2;            // n offset 64*wn
    const int m0   = blockIdx.y * 128;
    const int n0   = blockIdx.x * 128;

    const int l4 = lane >> 4;
    uint32_t baseA[2], baseB[4];
#pragma unroll
    for (int mt = 0; mt < 2; mt++) {
        int m_l = wm * 32 + mt * 16 + ((lane >> 3) & 1) * 8 + (lane & 7);
        baseA[mt] = m_l * 128 + (((m_l & 7) ^ l4) << 4);
    }
#pragma unroll
    for (int j = 0; j < 4; j++) {
        int n_l = wn * 64 + j * 16 + ((lane >> 3) & 1) * 8 + (lane & 7);
        baseB[j] = 16384 + n_l * 128 + (((n_l & 7) ^ l4) << 4);
    }

    float acc[2][8][4];
#pragma unroll
    for (int mt = 0; mt < 2; mt++)
#pragma unroll
        for (int nt = 0; nt < 8; nt++)
#pragma unroll
            for (int e = 0; e < 4; e++) acc[mt][nt][e] = 0.0f;

    // Prologue: chunks 0 and 1 into stages 0 and 1
    {
        const __nv_bfloat16 *As, *Bs;
        seg_sel(0, Ahi, Alo, Whi, Wlo, &As, &Bs);
        issue_chunk(sm0, As, Bs, m0, n0, 0, t);
        CP_COMMIT();
        seg_sel(1, Ahi, Alo, Whi, Wlo, &As, &Bs);
        issue_chunk(sm0 + STAGE_B, As, Bs, m0, n0, 64, t);
        CP_COMMIT();
    }

    int st = 0;  // kc % 3
    for (int kc = 0; kc < NKCH; kc++) {
        if (kc + 1 < NKCH) { CP_WAIT(1); } else { CP_WAIT(0); }
        __syncthreads();

        const uint32_t sbase = sm0 + st * STAGE_B;
#pragma unroll
        for (int kk = 0; kk < 4; kk++) {
            uint32_t a[2][4], b[4][4];
#pragma unroll
            for (int mt = 0; mt < 2; mt++)
                LDSM_X4(a[mt][0], a[mt][1], a[mt][2], a[mt][3],
                        sbase + (baseA[mt] ^ (kk << 5)));
#pragma unroll
            for (int j = 0; j < 4; j++)
                LDSM_X4(b[j][0], b[j][1], b[j][2], b[j][3],
                        sbase + (baseB[j] ^ (kk << 5)));
#pragma unroll
            for (int mt = 0; mt < 2; mt++)
#pragma unroll
                for (int nt = 0; nt < 8; nt++)
                    MMA16816(acc[mt][nt], a[mt],
                             b[nt >> 1][nt & 1], b[nt >> 1][(nt & 1) + 2]);
        }

        // Issue chunk kc+2 into stage (kc+2)%3 — its previous readers were
        // iteration kc-1, separated by this iteration's top sync.
        if (kc + 2 < NKCH) {
            const int kn = kc + 2;
            int st2 = st + 2; if (st2 >= 3) st2 -= 3;
            const __nv_bfloat16 *As, *Bs;
            seg_sel(kn, Ahi, Alo, Whi, Wlo, &As, &Bs);
            issue_chunk(sm0 + st2 * STAGE_B, As, Bs, m0, n0, (kn & 15) * 64, t);
            CP_COMMIT();
        }
        if (++st == 3) st = 0;
    }

    // Epilogue
    const int qrow = lane >> 2;
    const int qcol = (lane & 3) * 2;
#pragma unroll
    for (int mt = 0; mt < 2; mt++) {
#pragma unroll
        for (int half = 0; half < 2; half++) {
            const int grow = m0 + wm * 32 + mt * 16 + half * 8 + qrow;
#pragma unroll
            for (int nt = 0; nt < 8; nt++) {
                const int gcol = n0 + wn * 64 + nt * 8 + qcol;
                float2 v = make_float2(acc[mt][nt][half * 2],
                                       acc[mt][nt][half * 2 + 1]);
                if (MODE == 0) {
                    v.x += bias[gcol];
                    v.y += bias[gcol + 1];
                    *(float2*)&out[(size_t)grow * C_ + gcol] = v;
                } else {
                    const int head = gcol >> 6, d = gcol & 63;
                    const int bb = grow >> 11, tt = grow & (T_ - 1);
                    size_t idx = (((size_t)bb * H_ + head) * T_ + tt) * D_ + d;
                    __nv_bfloat162 lo;
                    __nv_bfloat162 hi = split_hi2(v.x, v.y, &lo);
                    *(__nv_bfloat162*)&ohi[idx] = hi;
                    *(__nv_bfloat162*)&olo[idx] = lo;
                }
            }
        }
    }
}

__global__ __launch_bounds__(256, 2)
void tc_gemm_qkv(const __nv_bfloat16* __restrict__ Xhi,
                 const __nv_bfloat16* __restrict__ Xlo,
                 const __nv_bfloat16* __restrict__ Wh,
                 const __nv_bfloat16* __restrict__ Wl,
                 __nv_bfloat16* __restrict__ Qh, __nv_bfloat16* __restrict__ Ql,
                 __nv_bfloat16* __restrict__ Kh, __nv_bfloat16* __restrict__ Kl,
                 __nv_bfloat16* __restrict__ Vh, __nv_bfloat16* __restrict__ Vl)
{
    const int z = blockIdx.z;
    const __nv_bfloat16* wh = Wh + (size_t)z * C_ * C_;
    const __nv_bfloat16* wl = Wl + (size_t)z * C_ * C_;
    __nv_bfloat16* oh = (z == 0) ? Qh : (z == 1) ? Kh : Vh;
    __nv_bfloat16* ol = (z == 0) ? Ql : (z == 1) ? Kl : Vl;
    hmma_gemm_body<1>(Xhi, Xlo, wh, wl, nullptr, nullptr, oh, ol);
}

__global__ __launch_bounds__(256, 2)
void tc_gemm_out(const __nv_bfloat16* __restrict__ Yhi,
                 const __nv_bfloat16* __restrict__ Ylo,
                 const __nv_bfloat16* __restrict__ Wh,
                 const __nv_bfloat16* __restrict__ Wl,
                 const float* __restrict__ bias, float* __restrict__ out)
{
    hmma_gemm_body<0>(Yhi, Ylo, Wh, Wl, bias, out, nullptr, nullptr);
}

// ---------------------------------------------------------------------------
// HMMA flash attention (causal). Unchanged from R13 (best measured config):
// 2 CTAs/SM, exp2-domain softmax, bf16x2 single-instruction packing.
// ---------------------------------------------------------------------------
#define ATT_SMEM 98304
#define SCL 0.18033688f   // 0.125 * log2(e)

__device__ __forceinline__
void issue_kv(uint32_t dstbase,
              const __nv_bfloat16* __restrict__ Kh, const __nv_bfloat16* __restrict__ Kl,
              const __nv_bfloat16* __restrict__ Vh, const __nv_bfloat16* __restrict__ Vl,
              int kbase, int t)
{
#pragma unroll
    for (int rep = 0; rep < 2; rep++) {
        int idx = t + rep * 256;
        int r = idx >> 3, c = idx & 7;
        uint32_t dst = dstbase + r * 128 + ((c ^ (r & 7)) << 4);
        size_t g = (size_t)(kbase + r) * D_ + c * 8;
        CP_ASYNC16(dst,          (const void*)(Kh + g));
        CP_ASYNC16(dst + 8192,   (const void*)(Kl + g));
        CP_ASYNC16(dst + 16384,  (const void*)(Vh + g));
        CP_ASYNC16(dst + 24576,  (const void*)(Vl + g));
    }
}

__global__ __launch_bounds__(256, 2)
void attn_hmma(const __nv_bfloat16* __restrict__ Qhi, const __nv_bfloat16* __restrict__ Qlo,
               const __nv_bfloat16* __restrict__ Khi, const __nv_bfloat16* __restrict__ Klo,
               const __nv_bfloat16* __restrict__ Vhi, const __nv_bfloat16* __restrict__ Vlo,
               __nv_bfloat16* __restrict__ Yh, __nv_bfloat16* __restrict__ Yl)
{
    extern __shared__ __align__(128) char sm[];
    const uint32_t s0 = smem_u32(sm);
    const int t = threadIdx.x, lane = t & 31, w = t >> 5;
    const int bh = blockIdx.y;
    const int qi = (int)(gridDim.x - 1 - blockIdx.x);
    const int qbase = qi * 128;
    const size_t base = (size_t)bh * T_ * D_;
    const __nv_bfloat16* Qh = Qhi + base + (size_t)qbase * D_;
    const __nv_bfloat16* Ql = Qlo + base + (size_t)qbase * D_;
    const __nv_bfloat16* Kh = Khi + base;
    const __nv_bfloat16* Kl = Klo + base;
    const __nv_bfloat16* Vh = Vhi + base;
    const __nv_bfloat16* Vl = Vlo + base;

#pragma unroll
    for (int rep = 0; rep < 4; rep++) {
        int idx = t + rep * 256;
        int r = idx >> 3, c = idx & 7;
        uint32_t dst = s0 + r * 128 + ((c ^ (r & 7)) << 4);
        size_t g = (size_t)r * D_ + c * 8;
        CP_ASYNC16(dst,          (const void*)(Qh + g));
        CP_ASYNC16(dst + 16384,  (const void*)(Ql + g));
    }
    CP_COMMIT();

    const int nch = 2 * qi + 2;
    issue_kv(s0 + 32768, Kh, Kl, Vh, Vl, 0, t);
    CP_COMMIT();

    CP_WAIT(1);            // Q landed
    __syncthreads();

    float accO[8][4];
#pragma unroll
    for (int j = 0; j < 8; j++)
#pragma unroll
        for (int e = 0; e < 4; e++) accO[j][e] = 0.0f;

    float m0s = -1e30f, m1s = -1e30f, l0s = 0.0f, l1s = 0.0f;
    const int r0g = qbase + 16 * w + (lane >> 2);
    const int r1g = r0g + 8;

    for (int kc = 0; kc < nch; kc++) {
        const int kbase = kc * 64;
        const int stage = kc & 1;
        if (kc + 1 < nch) {
            issue_kv(s0 + 32768 + (stage ^ 1) * 32768, Kh, Kl, Vh, Vl, kbase + 64, t);
            CP_COMMIT();
            CP_WAIT(1);
        } else {
            CP_WAIT(0);
        }
        __syncthreads();
        const uint32_t kvb = s0 + 32768 + stage * 32768;

        if (kbase <= qbase + 16 * w + 15) {
            // ---- S = Q @ K^T (16 x 64 per warp), 3-term split ----
            float sc[8][4];
#pragma unroll
            for (int j = 0; j < 8; j++)
#pragma unroll
                for (int e = 0; e < 4; e++) sc[j][e] = 0.0f;

#pragma unroll
            for (int s = 0; s < 4; s++) {
                uint32_t aQh[4], aQl[4];
                {
                    int row = 16 * w + (lane & 15);
                    int cb  = 2 * s + (lane >> 4);
                    uint32_t ad = s0 + row * 128 + ((cb ^ (row & 7)) << 4);
                    LDSM_X4(aQh[0], aQh[1], aQh[2], aQh[3], ad);
                    LDSM_X4(aQl[0], aQl[1], aQl[2], aQl[3], ad + 16384);
                }
#pragma unroll
                for (int hf = 0; hf < 2; hf++) {
                    uint32_t bKh[4][2], bKl[4][2];
#pragma unroll
                    for (int q = 0; q < 2; q++) {
                        int jp  = 2 * hf + q;
                        int row = 16 * jp + ((lane >> 4) << 3) + (lane & 7);
                        int cb  = 2 * s + ((lane >> 3) & 1);
                        uint32_t ad = kvb + row * 128 + ((cb ^ (row & 7)) << 4);
                        LDSM_X4(bKh[2*q][0], bKh[2*q][1], bKh[2*q+1][0], bKh[2*q+1][1], ad);
                        LDSM_X4(bKl[2*q][0], bKl[2*q][1], bKl[2*q+1][0], bKl[2*q+1][1], ad + 8192);
                    }
#pragma unroll
                    for (int jj = 0; jj < 4; jj++) {
                        int j = 4 * hf + jj;
                        MMA16816(sc[j], aQh, bKh[jj][0], bKh[jj][1]);
                        MMA16816(sc[j], aQh, bKl[jj][0], bKl[jj][1]);
                        MMA16816(sc[j], aQl, bKh[jj][0], bKh[jj][1]);
                    }
                }
            }

            // ---- scale into exp2 domain + causal mask ----
            const int c0b = kbase + 2 * (lane & 3);
#pragma unroll
            for (int j = 0; j < 8; j++) {
                int cc = c0b + 8 * j;
                sc[j][0] = (cc     > r0g) ? -1e30f : sc[j][0] * SCL;
                sc[j][1] = (cc + 1 > r0g) ? -1e30f : sc[j][1] * SCL;
                sc[j][2] = (cc     > r1g) ? -1e30f : sc[j][2] * SCL;
                sc[j][3] = (cc + 1 > r1g) ? -1e30f : sc[j][3] * SCL;
            }

            // ---- online softmax (warp-local quad reduction, exp2 domain) ----
            float mx0 = -1e30f, mx1 = -1e30f;
#pragma unroll
            for (int j = 0; j < 8; j++) {
                mx0 = fmaxf(mx0, fmaxf(sc[j][0], sc[j][1]));
                mx1 = fmaxf(mx1, fmaxf(sc[j][2], sc[j][3]));
            }
            mx0 = fmaxf(mx0, __shfl_xor_sync(0xffffffffu, mx0, 1));
            mx0 = fmaxf(mx0, __shfl_xor_sync(0xffffffffu, mx0, 2));
            mx1 = fmaxf(mx1, __shfl_xor_sync(0xffffffffu, mx1, 1));
            mx1 = fmaxf(mx1, __shfl_xor_sync(0xffffffffu, mx1, 2));
            float mn0 = fmaxf(m0s, mx0), mn1 = fmaxf(m1s, mx1);
            float cr0 = exp2f(m0s - mn0), cr1 = exp2f(m1s - mn1);
            m0s = mn0; m1s = mn1;

            float sum0 = 0.0f, sum1 = 0.0f;
            uint32_t aPh[4][4], aPl[4][4];
#pragma unroll
            for (int jp = 0; jp < 4; jp++) {
#pragma unroll
                for (int u = 0; u < 2; u++) {
                    int j = 2 * jp + u;
                    float p0 = exp2f(sc[j][0] - mn0);
                    float p1 = exp2f(sc[j][1] - mn0);
                    float p2 = exp2f(sc[j][2] - mn1);
                    float p3 = exp2f(sc[j][3] - mn1);
                    sum0 += p0 + p1;
                    sum1 += p2 + p3;
                    uint32_t hA = cvt2_bf16(p0, p1);
                    uint32_t hB = cvt2_bf16(p2, p3);
                    aPh[jp][2*u]     = hA;
                    aPh[jp][2*u + 1] = hB;
                    __nv_bfloat162 hA2 = *reinterpret_cast<__nv_bfloat162*>(&hA);
                    __nv_bfloat162 hB2 = *reinterpret_cast<__nv_bfloat162*>(&hB);
                    aPl[jp][2*u]     = cvt2_bf16(p0 - __low2float(hA2),
                                                 p1 - __high2float(hA2));
                    aPl[jp][2*u + 1] = cvt2_bf16(p2 - __low2float(hB2),
                                                 p3 - __high2float(hB2));
                }
            }
            sum0 += __shfl_xor_sync(0xffffffffu, sum0, 1);
            sum0 += __shfl_xor_sync(0xffffffffu, sum0, 2);
            sum1 += __shfl_xor_sync(0xffffffffu, sum1, 1);
            sum1 += __shfl_xor_sync(0xffffffffu, sum1, 2);
            l0s = l0s * cr0 + sum0;
            l1s = l1s * cr1 + sum1;

            // ---- rescale O, then O += P @ V (3-term split) ----
#pragma unroll
            for (int j = 0; j < 8; j++) {
                accO[j][0] *= cr0; accO[j][1] *= cr0;
                accO[j][2] *= cr1; accO[j][3] *= cr1;
            }

#pragma unroll
            for (int s = 0; s < 4; s++) {
#pragma unroll
                for (int hf = 0; hf < 2; hf++) {
                    uint32_t bVh[4][2], bVl[4][2];
#pragma unroll
                    for (int q = 0; q < 2; q++) {
                        int jp  = 2 * hf + q;
                        int row = 16 * s + ((lane >> 3) & 1) * 8 + (lane & 7);
                        int cb  = 2 * jp + (lane >> 4);
                        uint32_t ad = kvb + 16384 + row * 128 + ((cb ^ (row & 7)) << 4);
                        LDSM_X4_T(bVh[2*q][0], bVh[2*q][1], bVh[2*q+1][0], bVh[2*q+1][1], ad);
                        LDSM_X4_T(bVl[2*q][0], bVl[2*q][1], bVl[2*q+1][0], bVl[2*q+1][1], ad + 8192);
                    }
#pragma unroll
                    for (int jj = 0; jj < 4; jj++) {
                        int j = 4 * hf + jj;
                        MMA16816(accO[j], aPh[s], bVh[jj][0], bVh[jj][1]);
                        MMA16816(accO[j], aPh[s], bVl[jj][0], bVl[jj][1]);
                        MMA16816(accO[j], aPl[s], bVh[jj][0], bVh[jj][1]);
                    }
                }
            }
        }
        __syncthreads();
    }

    // normalize + store as bf16 hi/lo
    const float i0 = 1.0f / l0s, i1 = 1.0f / l1s;
    const int b = bh >> 4, h = bh & 15;
    const size_t o0 = ((size_t)b * T_ + r0g) * C_ + h * 64 + 2 * (lane & 3);
    const size_t o1 = ((size_t)b * T_ + r1g) * C_ + h * 64 + 2 * (lane & 3);
#pragma unroll
    for (int j = 0; j < 8; j++) {
        __nv_bfloat162 lo;
        __nv_bfloat162 hi = split_hi2(accO[j][0] * i0, accO[j][1] * i0, &lo);
        *(__nv_bfloat162*)&Yh[o0 + 8 * j] = hi;
        *(__nv_bfloat162*)&Yl[o0 + 8 * j] = lo;
        hi = split_hi2(accO[j][2] * i1, accO[j][3] * i1, &lo);
        *(__nv_bfloat162*)&Yh[o1 + 8 * j] = hi;
        *(__nv_bfloat162*)&Yl[o1 + 8 * j] = lo;
    }
}

// ---------------------------------------------------------------------------
extern "C" void kernel_launch(void* const* d_in, const int* in_sizes, int n_in,
                              void* d_out, int out_size)
{
    const float* X  = (const float*)d_in[0];
    const float* Wq = (const float*)d_in[1];
    const float* Wk = (const float*)d_in[2];
    const float* Wv = (const float*)d_in[3];
    const float* Wo = (const float*)d_in[4];
    const float* bo = (const float*)d_in[5];
    float* out = (float*)d_out;

    __nv_bfloat16 *xh, *xl, *wh, *wl, *woh, *wol, *yh, *yl;
    __nv_bfloat16 *qh, *ql, *kh, *kl, *vh, *vl;
    cudaGetSymbolAddress((void**)&xh, g_Xhi);
    cudaGetSymbolAddress((void**)&xl, g_Xlo);
    cudaGetSymbolAddress((void**)&wh, g_Wh);
    cudaGetSymbolAddress((void**)&wl, g_Wl);
    cudaGetSymbolAddress((void**)&woh, g_Wohi);
    cudaGetSymbolAddress((void**)&wol, g_Wolo);
    cudaGetSymbolAddress((void**)&yh, g_Yhi);
    cudaGetSymbolAddress((void**)&yl, g_Ylo);
    cudaGetSymbolAddress((void**)&qh, g_Qhi);
    cudaGetSymbolAddress((void**)&ql, g_Qlo);
    cudaGetSymbolAddress((void**)&kh, g_Khi);
    cudaGetSymbolAddress((void**)&kl, g_Klo);
    cudaGetSymbolAddress((void**)&vh, g_Vhi);
    cudaGetSymbolAddress((void**)&vl, g_Vlo);

    // hi/lo split converts: X (one launch) + all four weights (one launch)
    cvt_kernel<<<(M_ * C_ / 4 + 255) / 256, 256>>>(X, xh, xl, M_ * C_ / 4);
    cvt_w_kernel<<<dim3((C_ * C_ / 4 + 255) / 256, 4), 256>>>(
        Wq, Wk, Wv, Wo, wh, wl, woh, wol);

    // QKV projections (HMMA v3b, 2 CTAs/SM) -> bf16 hi/lo split-head
    cudaFuncSetAttribute((const void*)tc_gemm_qkv,
                         cudaFuncAttributeMaxDynamicSharedMemorySize, G_SMEM);
    tc_gemm_qkv<<<dim3(C_ / 128, M_ / 128, 3), 256, G_SMEM>>>(
        xh, xl, wh, wl, qh, ql, kh, kl, vh, vl);

    // Attention (HMMA flash, 2 CTAs/SM) -> bf16 hi/lo Y
    cudaFuncSetAttribute((const void*)attn_hmma,
                         cudaFuncAttributeMaxDynamicSharedMemorySize, ATT_SMEM);
    attn_hmma<<<dim3(T_ / 128, B_ * H_), 256, ATT_SMEM>>>(qh, ql, kh, kl, vh, vl, yh, yl);

    // Output projection (HMMA v3b, 2 CTAs/SM)
    cudaFuncSetAttribute((const void*)tc_gemm_out,
                         cudaFuncAttributeMaxDynamicSharedMemorySize, G_SMEM);
    tc_gemm_out<<<dim3(C_ / 128, M_ / 128), 256, G_SMEM>>>(yh, yl, woh, wol, bo, out);
}

// round 15
// speedup vs baseline: 1.1277x; 1.0088x over previous
#include <cuda_runtime.h>
#include <cuda_bf16.h>
#include <cstdint>

// Problem constants
#define B_ 4
#define T_ 2048
#define C_ 1024
#define H_ 16
#define D_ 64
#define M_ (B_ * T_)   // 8192 rows

// ---------------------------------------------------------------------------
// Scratch (allocation-free rule: __device__ globals)
// ---------------------------------------------------------------------------
__device__ __align__(16) __nv_bfloat16 g_Xhi[(size_t)M_ * C_];
__device__ __align__(16) __nv_bfloat16 g_Xlo[(size_t)M_ * C_];
__device__ __align__(16) __nv_bfloat16 g_Wh[(size_t)3 * C_ * C_];
__device__ __align__(16) __nv_bfloat16 g_Wl[(size_t)3 * C_ * C_];
__device__ __align__(16) __nv_bfloat16 g_Wohi[(size_t)C_ * C_];
__device__ __align__(16) __nv_bfloat16 g_Wolo[(size_t)C_ * C_];
__device__ __align__(16) __nv_bfloat16 g_Yhi[(size_t)M_ * C_];
__device__ __align__(16) __nv_bfloat16 g_Ylo[(size_t)M_ * C_];
__device__ __align__(16) __nv_bfloat16 g_Qhi[(size_t)B_ * H_ * T_ * D_];
__device__ __align__(16) __nv_bfloat16 g_Qlo[(size_t)B_ * H_ * T_ * D_];
__device__ __align__(16) __nv_bfloat16 g_Khi[(size_t)B_ * H_ * T_ * D_];
__device__ __align__(16) __nv_bfloat16 g_Klo[(size_t)B_ * H_ * T_ * D_];
__device__ __align__(16) __nv_bfloat16 g_Vhi[(size_t)B_ * H_ * T_ * D_];
__device__ __align__(16) __nv_bfloat16 g_Vlo[(size_t)B_ * H_ * T_ * D_];

// ---------------------------------------------------------------------------
// Helpers
// ---------------------------------------------------------------------------
__device__ __forceinline__ uint32_t smem_u32(const void* p) {
    uint32_t a;
    asm("{ .reg .u64 t; cvta.to.shared.u64 t, %1; cvt.u32.u64 %0, t; }"
        : "=r"(a) : "l"(p));
    return a;
}

#define CP_ASYNC16(dst, src) \
    asm volatile("cp.async.cg.shared.global [%0], [%1], 16;" \
                 :: "r"(dst), "l"(src) : "memory")
#define CP_COMMIT()  asm volatile("cp.async.commit_group;" ::: "memory")
#define CP_WAIT(n)   asm volatile("cp.async.wait_group %0;" :: "n"(n) : "memory")

#define LDSM_X4(r0, r1, r2, r3, addr) \
    asm volatile("ldmatrix.sync.aligned.m8n8.x4.shared.b16 {%0,%1,%2,%3}, [%4];" \
                 : "=r"(r0), "=r"(r1), "=r"(r2), "=r"(r3) : "r"(addr))

#define LDSM_X4_T(r0, r1, r2, r3, addr) \
    asm volatile("ldmatrix.sync.aligned.m8n8.x4.trans.shared.b16 {%0,%1,%2,%3}, [%4];" \
                 : "=r"(r0), "=r"(r1), "=r"(r2), "=r"(r3) : "r"(addr))

#define MMA16816(d, a, b0, b1) \
    asm volatile("mma.sync.aligned.m16n8k16.row.col.f32.bf16.bf16.f32 " \
                 "{%0,%1,%2,%3}, {%4,%5,%6,%7}, {%8,%9}, {%0,%1,%2,%3};" \
                 : "+f"((d)[0]), "+f"((d)[1]), "+f"((d)[2]), "+f"((d)[3]) \
                 : "r"((a)[0]), "r"((a)[1]), "r"((a)[2]), "r"((a)[3]), \
                   "r"(b0), "r"(b1))

// Pack two fp32 -> bf16x2 in one instruction.
__device__ __forceinline__ uint32_t cvt2_bf16(float lo, float hi) {
    uint32_t r;
    asm("cvt.rn.bf16x2.f32 %0, %1, %2;" : "=r"(r) : "f"(hi), "f"(lo));
    return r;
}

__device__ __forceinline__ __nv_bfloat162 split_hi2(float x, float y,
                                                    __nv_bfloat162* lo) {
    uint32_t h = cvt2_bf16(x, y);
    __nv_bfloat162 hv = *reinterpret_cast<__nv_bfloat162*>(&h);
    float xr = x - __low2float(hv);
    float yr = y - __high2float(hv);
    uint32_t l = cvt2_bf16(xr, yr);
    *lo = *reinterpret_cast<__nv_bfloat162*>(&l);
    return hv;
}

// ---------------------------------------------------------------------------
// fp32 -> bf16 hi/lo split. One fused launch: X (2 float4/thread, MLP=2)
// plus all four weight matrices.
// ---------------------------------------------------------------------------
__device__ __forceinline__
void cvt_body(const float* __restrict__ in, __nv_bfloat16* __restrict__ hi,
              __nv_bfloat16* __restrict__ lo, int i)
{
    float4 v = ((const float4*)in)[i];
    __nv_bfloat162 l01, l23;
    __nv_bfloat162 h01 = split_hi2(v.x, v.y, &l01);
    __nv_bfloat162 h23 = split_hi2(v.z, v.w, &l23);
    ((__nv_bfloat162*)hi)[2 * i]     = h01;
    ((__nv_bfloat162*)hi)[2 * i + 1] = h23;
    ((__nv_bfloat162*)lo)[2 * i]     = l01;
    ((__nv_bfloat162*)lo)[2 * i + 1] = l23;
}

#define XHALF (M_ * C_ / 8)          // 1048576 float4 slots per half
#define XBLK  (XHALF / 256)          // 4096 blocks for X
#define WBLK  (C_ * C_ / 4 / 256)    // 1024 blocks per weight

__global__ __launch_bounds__(256)
void cvt_all_kernel(const float* __restrict__ X,
                    const float* __restrict__ Wq, const float* __restrict__ Wk,
                    const float* __restrict__ Wv, const float* __restrict__ Wo,
                    __nv_bfloat16* __restrict__ xh, __nv_bfloat16* __restrict__ xl,
                    __nv_bfloat16* __restrict__ Wh, __nv_bfloat16* __restrict__ Wl,
                    __nv_bfloat16* __restrict__ Woh, __nv_bfloat16* __restrict__ Wol)
{
    const int blk = blockIdx.x;
    const int tid = threadIdx.x;
    if (blk < XBLK) {
        int i = blk * 256 + tid;
        cvt_body(X, xh, xl, i);
        cvt_body(X, xh, xl, i + XHALF);   // second independent chain (MLP=2)
    } else {
        int r = blk - XBLK;
        int z = r >> 10;                   // WBLK == 1024
        int i = (r & (WBLK - 1)) * 256 + tid;
        const float* in = (z == 0) ? Wq : (z == 1) ? Wk : (z == 2) ? Wv : Wo;
        __nv_bfloat16* hi = (z < 3) ? (Wh + (size_t)z * C_ * C_) : Woh;
        __nv_bfloat16* lo = (z < 3) ? (Wl + (size_t)z * C_ * C_) : Wol;
        cvt_body(in, hi, lo, i);
    }
}

// ---------------------------------------------------------------------------
// HMMA bf16 GEMM (extended-K hi/lo split), BM=128, BN=128, BK=64,
// 3-stage ring, one __syncthreads per chunk, 2 CTAs/SM.
// MODE 0: fp32 [M,N], atomicAdd epilogue (+ optional bias) — split-K capable.
// MODE 1: bf16 hi/lo split-head [b,h,t,d], full-K.
// ---------------------------------------------------------------------------
#define NKCH 48
#define STAGE_B 32768
#define G_SMEM (3 * STAGE_B)

__device__ __forceinline__
void issue_chunk(uint32_t sbase, const __nv_bfloat16* __restrict__ Aseg,
                 const __nv_bfloat16* __restrict__ Bseg,
                 int m0, int n0, int k_in, int t)
{
#pragma unroll
    for (int rep = 0; rep < 4; rep++) {
        int idx = t + rep * 256;
        int r = idx >> 3, s = idx & 7;
        uint32_t dstA = sbase + r * 128 + ((s ^ (r & 7)) << 4);
        CP_ASYNC16(dstA, (const void*)(Aseg + (size_t)(m0 + r) * C_ + k_in + s * 8));
        CP_ASYNC16(dstA + 16384,
                   (const void*)(Bseg + (size_t)(n0 + r) * C_ + k_in + s * 8));
    }
}

__device__ __forceinline__
void seg_sel(int kn, const __nv_bfloat16* Ahi, const __nv_bfloat16* Alo,
             const __nv_bfloat16* Whi, const __nv_bfloat16* Wlo,
             const __nv_bfloat16** Aseg, const __nv_bfloat16** Bseg)
{
    *Aseg = (kn < 32) ? Ahi : Alo;
    *Bseg = (kn < 16) ? Whi : (kn < 32 ? Wlo : Whi);
}

template <int MODE>
__device__ __forceinline__
void hmma_gemm_body(const __nv_bfloat16* __restrict__ Ahi,
                    const __nv_bfloat16* __restrict__ Alo,
                    const __nv_bfloat16* __restrict__ Whi,
                    const __nv_bfloat16* __restrict__ Wlo,
                    const float* __restrict__ bias, float* __restrict__ out,
                    __nv_bfloat16* __restrict__ ohi, __nv_bfloat16* __restrict__ olo,
                    int kn0, int nk)
{
    extern __shared__ __align__(128) char sm[];
    const uint32_t sm0 = smem_u32(sm);
    const int t    = threadIdx.x;
    const int lane = t & 31;
    const int w    = t >> 5;
    const int wm   = w & 3;             // m offset 32*wm
    const int wn   = w >> 2;            // n offset 64*wn
    const int m0   = blockIdx.y * 128;
    const int n0   = blockIdx.x * 128;

    const int l4 = lane >> 4;
    uint32_t baseA[2], baseB[4];
#pragma unroll
    for (int mt = 0; mt < 2; mt++) {
        int m_l = wm * 32 + mt * 16 + ((lane >> 3) & 1) * 8 + (lane & 7);
        baseA[mt] = m_l * 128 + (((m_l & 7) ^ l4) << 4);
    }
#pragma unroll
    for (int j = 0; j < 4; j++) {
        int n_l = wn * 64 + j * 16 + ((lane >> 3) & 1) * 8 + (lane & 7);
        baseB[j] = 16384 + n_l * 128 + (((n_l & 7) ^ l4) << 4);
    }

    float acc[2][8][4];
#pragma unroll
    for (int mt = 0; mt < 2; mt++)
#pragma unroll
        for (int nt = 0; nt < 8; nt++)
#pragma unroll
            for (int e = 0; e < 4; e++) acc[mt][nt][e] = 0.0f;

    // Prologue: chunks kn0, kn0+1 into stages 0, 1
    {
        const __nv_bfloat16 *As, *Bs;
        seg_sel(kn0, Ahi, Alo, Whi, Wlo, &As, &Bs);
        issue_chunk(sm0, As, Bs, m0, n0, (kn0 & 15) * 64, t);
        CP_COMMIT();
        seg_sel(kn0 + 1, Ahi, Alo, Whi, Wlo, &As, &Bs);
        issue_chunk(sm0 + STAGE_B, As, Bs, m0, n0, ((kn0 + 1) & 15) * 64, t);
        CP_COMMIT();
    }

    int st = 0;  // local chunk index % 3
    for (int kci = 0; kci < nk; kci++) {
        if (kci + 1 < nk) { CP_WAIT(1); } else { CP_WAIT(0); }
        __syncthreads();

        const uint32_t sbase = sm0 + st * STAGE_B;
#pragma unroll
        for (int kk = 0; kk < 4; kk++) {
            uint32_t a[2][4], b[4][4];
#pragma unroll
            for (int mt = 0; mt < 2; mt++)
                LDSM_X4(a[mt][0], a[mt][1], a[mt][2], a[mt][3],
                        sbase + (baseA[mt] ^ (kk << 5)));
#pragma unroll
            for (int j = 0; j < 4; j++)
                LDSM_X4(b[j][0], b[j][1], b[j][2], b[j][3],
                        sbase + (baseB[j] ^ (kk << 5)));
#pragma unroll
            for (int mt = 0; mt < 2; mt++)
#pragma unroll
                for (int nt = 0; nt < 8; nt++)
                    MMA16816(acc[mt][nt], a[mt],
                             b[nt >> 1][nt & 1], b[nt >> 1][(nt & 1) + 2]);
        }

        if (kci + 2 < nk) {
            const int kn = kn0 + kci + 2;
            int st2 = st + 2; if (st2 >= 3) st2 -= 3;
            const __nv_bfloat16 *As, *Bs;
            seg_sel(kn, Ahi, Alo, Whi, Wlo, &As, &Bs);
            issue_chunk(sm0 + st2 * STAGE_B, As, Bs, m0, n0, (kn & 15) * 64, t);
            CP_COMMIT();
        }
        if (++st == 3) st = 0;
    }

    // Epilogue
    const int qrow = lane >> 2;
    const int qcol = (lane & 3) * 2;
#pragma unroll
    for (int mt = 0; mt < 2; mt++) {
#pragma unroll
        for (int half = 0; half < 2; half++) {
            const int grow = m0 + wm * 32 + mt * 16 + half * 8 + qrow;
#pragma unroll
            for (int nt = 0; nt < 8; nt++) {
                const int gcol = n0 + wn * 64 + nt * 8 + qcol;
                float2 v = make_float2(acc[mt][nt][half * 2],
                                       acc[mt][nt][half * 2 + 1]);
                if (MODE == 0) {
                    if (bias) {
                        v.x += bias[gcol];
                        v.y += bias[gcol + 1];
                    }
                    float* po = &out[(size_t)grow * C_ + gcol];
                    atomicAdd(po,     v.x);
                    atomicAdd(po + 1, v.y);
                } else {
                    const int head = gcol >> 6, d = gcol & 63;
                    const int bb = grow >> 11, tt = grow & (T_ - 1);
                    size_t idx = (((size_t)bb * H_ + head) * T_ + tt) * D_ + d;
                    __nv_bfloat162 lo;
                    __nv_bfloat162 hi = split_hi2(v.x, v.y, &lo);
                    *(__nv_bfloat162*)&ohi[idx] = hi;
                    *(__nv_bfloat162*)&olo[idx] = lo;
                }
            }
        }
    }
}

__global__ __launch_bounds__(256, 2)
void tc_gemm_qkv(const __nv_bfloat16* __restrict__ Xhi,
                 const __nv_bfloat16* __restrict__ Xlo,
                 const __nv_bfloat16* __restrict__ Wh,
                 const __nv_bfloat16* __restrict__ Wl,
                 __nv_bfloat16* __restrict__ Qh, __nv_bfloat16* __restrict__ Ql,
                 __nv_bfloat16* __restrict__ Kh, __nv_bfloat16* __restrict__ Kl,
                 __nv_bfloat16* __restrict__ Vh, __nv_bfloat16* __restrict__ Vl)
{
    const int z = blockIdx.z;
    const __nv_bfloat16* wh = Wh + (size_t)z * C_ * C_;
    const __nv_bfloat16* wl = Wl + (size_t)z * C_ * C_;
    __nv_bfloat16* oh = (z == 0) ? Qh : (z == 1) ? Kh : Vh;
    __nv_bfloat16* ol = (z == 0) ? Ql : (z == 1) ? Kl : Vl;
    hmma_gemm_body<1>(Xhi, Xlo, wh, wl, nullptr, nullptr, oh, ol, 0, NKCH);
}

// Split-K x2 output projection: blockIdx.z selects K-half; split 0 carries
// the bias; both halves atomicAdd onto a zeroed output (2 fp32 adds per
// element — commutative, hence deterministic across replays).
__global__ __launch_bounds__(256, 2)
void tc_gemm_out(const __nv_bfloat16* __restrict__ Yhi,
                 const __nv_bfloat16* __restrict__ Ylo,
                 const __nv_bfloat16* __restrict__ Wh,
                 const __nv_bfloat16* __restrict__ Wl,
                 const float* __restrict__ bias, float* __restrict__ out)
{
    const int z = blockIdx.z;
    hmma_gemm_body<0>(Yhi, Ylo, Wh, Wl, z == 0 ? bias : nullptr, out,
                      nullptr, nullptr, z * (NKCH / 2), NKCH / 2);
}

// ---------------------------------------------------------------------------
// HMMA flash attention (causal). Unchanged from R13/R14 best config:
// 2 CTAs/SM, exp2-domain softmax, bf16x2 single-instruction packing.
// ---------------------------------------------------------------------------
#define ATT_SMEM 98304
#define SCL 0.18033688f   // 0.125 * log2(e)

__device__ __forceinline__
void issue_kv(uint32_t dstbase,
              const __nv_bfloat16* __restrict__ Kh, const __nv_bfloat16* __restrict__ Kl,
              const __nv_bfloat16* __restrict__ Vh, const __nv_bfloat16* __restrict__ Vl,
              int kbase, int t)
{
#pragma unroll
    for (int rep = 0; rep < 2; rep++) {
        int idx = t + rep * 256;
        int r = idx >> 3, c = idx & 7;
        uint32_t dst = dstbase + r * 128 + ((c ^ (r & 7)) << 4);
        size_t g = (size_t)(kbase + r) * D_ + c * 8;
        CP_ASYNC16(dst,          (const void*)(Kh + g));
        CP_ASYNC16(dst + 8192,   (const void*)(Kl + g));
        CP_ASYNC16(dst + 16384,  (const void*)(Vh + g));
        CP_ASYNC16(dst + 24576,  (const void*)(Vl + g));
    }
}

__global__ __launch_bounds__(256, 2)
void attn_hmma(const __nv_bfloat16* __restrict__ Qhi, const __nv_bfloat16* __restrict__ Qlo,
               const __nv_bfloat16* __restrict__ Khi, const __nv_bfloat16* __restrict__ Klo,
               const __nv_bfloat16* __restrict__ Vhi, const __nv_bfloat16* __restrict__ Vlo,
               __nv_bfloat16* __restrict__ Yh, __nv_bfloat16* __restrict__ Yl)
{
    extern __shared__ __align__(128) char sm[];
    const uint32_t s0 = smem_u32(sm);
    const int t = threadIdx.x, lane = t & 31, w = t >> 5;
    const int bh = blockIdx.y;
    const int qi = (int)(gridDim.x - 1 - blockIdx.x);
    const int qbase = qi * 128;
    const size_t base = (size_t)bh * T_ * D_;
    const __nv_bfloat16* Qh = Qhi + base + (size_t)qbase * D_;
    const __nv_bfloat16* Ql = Qlo + base + (size_t)qbase * D_;
    const __nv_bfloat16* Kh = Khi + base;
    const __nv_bfloat16* Kl = Klo + base;
    const __nv_bfloat16* Vh = Vhi + base;
    const __nv_bfloat16* Vl = Vlo + base;

#pragma unroll
    for (int rep = 0; rep < 4; rep++) {
        int idx = t + rep * 256;
        int r = idx >> 3, c = idx & 7;
        uint32_t dst = s0 + r * 128 + ((c ^ (r & 7)) << 4);
        size_t g = (size_t)r * D_ + c * 8;
        CP_ASYNC16(dst,          (const void*)(Qh + g));
        CP_ASYNC16(dst + 16384,  (const void*)(Ql + g));
    }
    CP_COMMIT();

    const int nch = 2 * qi + 2;
    issue_kv(s0 + 32768, Kh, Kl, Vh, Vl, 0, t);
    CP_COMMIT();

    CP_WAIT(1);            // Q landed
    __syncthreads();

    float accO[8][4];
#pragma unroll
    for (int j = 0; j < 8; j++)
#pragma unroll
        for (int e = 0; e < 4; e++) accO[j][e] = 0.0f;

    float m0s = -1e30f, m1s = -1e30f, l0s = 0.0f, l1s = 0.0f;
    const int r0g = qbase + 16 * w + (lane >> 2);
    const int r1g = r0g + 8;

    for (int kc = 0; kc < nch; kc++) {
        const int kbase = kc * 64;
        const int stage = kc & 1;
        if (kc + 1 < nch) {
            issue_kv(s0 + 32768 + (stage ^ 1) * 32768, Kh, Kl, Vh, Vl, kbase + 64, t);
            CP_COMMIT();
            CP_WAIT(1);
        } else {
            CP_WAIT(0);
        }
        __syncthreads();
        const uint32_t kvb = s0 + 32768 + stage * 32768;

        if (kbase <= qbase + 16 * w + 15) {
            // ---- S = Q @ K^T (16 x 64 per warp), 3-term split ----
            float sc[8][4];
#pragma unroll
            for (int j = 0; j < 8; j++)
#pragma unroll
                for (int e = 0; e < 4; e++) sc[j][e] = 0.0f;

#pragma unroll
            for (int s = 0; s < 4; s++) {
                uint32_t aQh[4], aQl[4];
                {
                    int row = 16 * w + (lane & 15);
                    int cb  = 2 * s + (lane >> 4);
                    uint32_t ad = s0 + row * 128 + ((cb ^ (row & 7)) << 4);
                    LDSM_X4(aQh[0], aQh[1], aQh[2], aQh[3], ad);
                    LDSM_X4(aQl[0], aQl[1], aQl[2], aQl[3], ad + 16384);
                }
#pragma unroll
                for (int hf = 0; hf < 2; hf++) {
                    uint32_t bKh[4][2], bKl[4][2];
#pragma unroll
                    for (int q = 0; q < 2; q++) {
                        int jp  = 2 * hf + q;
                        int row = 16 * jp + ((lane >> 4) << 3) + (lane & 7);
                        int cb  = 2 * s + ((lane >> 3) & 1);
                        uint32_t ad = kvb + row * 128 + ((cb ^ (row & 7)) << 4);
                        LDSM_X4(bKh[2*q][0], bKh[2*q][1], bKh[2*q+1][0], bKh[2*q+1][1], ad);
                        LDSM_X4(bKl[2*q][0], bKl[2*q][1], bKl[2*q+1][0], bKl[2*q+1][1], ad + 8192);
                    }
#pragma unroll
                    for (int jj = 0; jj < 4; jj++) {
                        int j = 4 * hf + jj;
                        MMA16816(sc[j], aQh, bKh[jj][0], bKh[jj][1]);
                        MMA16816(sc[j], aQh, bKl[jj][0], bKl[jj][1]);
                        MMA16816(sc[j], aQl, bKh[jj][0], bKh[jj][1]);
                    }
                }
            }

            // ---- scale into exp2 domain + causal mask ----
            const int c0b = kbase + 2 * (lane & 3);
#pragma unroll
            for (int j = 0; j < 8; j++) {
                int cc = c0b + 8 * j;
                sc[j][0] = (cc     > r0g) ? -1e30f : sc[j][0] * SCL;
                sc[j][1] = (cc + 1 > r0g) ? -1e30f : sc[j][1] * SCL;
                sc[j][2] = (cc     > r1g) ? -1e30f : sc[j][2] * SCL;
                sc[j][3] = (cc + 1 > r1g) ? -1e30f : sc[j][3] * SCL;
            }

            // ---- online softmax (warp-local quad reduction, exp2 domain) ----
            float mx0 = -1e30f, mx1 = -1e30f;
#pragma unroll
            for (int j = 0; j < 8; j++) {
                mx0 = fmaxf(mx0, fmaxf(sc[j][0], sc[j][1]));
                mx1 = fmaxf(mx1, fmaxf(sc[j][2], sc[j][3]));
            }
            mx0 = fmaxf(mx0, __shfl_xor_sync(0xffffffffu, mx0, 1));
            mx0 = fmaxf(mx0, __shfl_xor_sync(0xffffffffu, mx0, 2));
            mx1 = fmaxf(mx1, __shfl_xor_sync(0xffffffffu, mx1, 1));
            mx1 = fmaxf(mx1, __shfl_xor_sync(0xffffffffu, mx1, 2));
            float mn0 = fmaxf(m0s, mx0), mn1 = fmaxf(m1s, mx1);
            float cr0 = exp2f(m0s - mn0), cr1 = exp2f(m1s - mn1);
            m0s = mn0; m1s = mn1;

            float sum0 = 0.0f, sum1 = 0.0f;
            uint32_t aPh[4][4], aPl[4][4];
#pragma unroll
            for (int jp = 0; jp < 4; jp++) {
#pragma unroll
                for (int u = 0; u < 2; u++) {
                    int j = 2 * jp + u;
                    float p0 = exp2f(sc[j][0] - mn0);
                    float p1 = exp2f(sc[j][1] - mn0);
                    float p2 = exp2f(sc[j][2] - mn1);
                    float p3 = exp2f(sc[j][3] - mn1);
                    sum0 += p0 + p1;
                    sum1 += p2 + p3;
                    uint32_t hA = cvt2_bf16(p0, p1);
                    uint32_t hB = cvt2_bf16(p2, p3);
                    aPh[jp][2*u]     = hA;
                    aPh[jp][2*u + 1] = hB;
                    __nv_bfloat162 hA2 = *reinterpret_cast<__nv_bfloat162*>(&hA);
                    __nv_bfloat162 hB2 = *reinterpret_cast<__nv_bfloat162*>(&hB);
                    aPl[jp][2*u]     = cvt2_bf16(p0 - __low2float(hA2),
                                                 p1 - __high2float(hA2));
                    aPl[jp][2*u + 1] = cvt2_bf16(p2 - __low2float(hB2),
                                                 p3 - __high2float(hB2));
                }
            }
            sum0 += __shfl_xor_sync(0xffffffffu, sum0, 1);
            sum0 += __shfl_xor_sync(0xffffffffu, sum0, 2);
            sum1 += __shfl_xor_sync(0xffffffffu, sum1, 1);
            sum1 += __shfl_xor_sync(0xffffffffu, sum1, 2);
            l0s = l0s * cr0 + sum0;
            l1s = l1s * cr1 + sum1;

            // ---- rescale O, then O += P @ V (3-term split) ----
#pragma unroll
            for (int j = 0; j < 8; j++) {
                accO[j][0] *= cr0; accO[j][1] *= cr0;
                accO[j][2] *= cr1; accO[j][3] *= cr1;
            }

#pragma unroll
            for (int s = 0; s < 4; s++) {
#pragma unroll
                for (int hf = 0; hf < 2; hf++) {
                    uint32_t bVh[4][2], bVl[4][2];
#pragma unroll
                    for (int q = 0; q < 2; q++) {
                        int jp  = 2 * hf + q;
                        int row = 16 * s + ((lane >> 3) & 1) * 8 + (lane & 7);
                        int cb  = 2 * jp + (lane >> 4);
                        uint32_t ad = kvb + 16384 + row * 128 + ((cb ^ (row & 7)) << 4);
                        LDSM_X4_T(bVh[2*q][0], bVh[2*q][1], bVh[2*q+1][0], bVh[2*q+1][1], ad);
                        LDSM_X4_T(bVl[2*q][0], bVl[2*q][1], bVl[2*q+1][0], bVl[2*q+1][1], ad + 8192);
                    }
#pragma unroll
                    for (int jj = 0; jj < 4; jj++) {
                        int j = 4 * hf + jj;
                        MMA16816(accO[j], aPh[s], bVh[jj][0], bVh[jj][1]);
                        MMA16816(accO[j], aPh[s], bVl[jj][0], bVl[jj][1]);
                        MMA16816(accO[j], aPl[s], bVh[jj][0], bVh[jj][1]);
                    }
                }
            }
        }
        __syncthreads();
    }

    // normalize + store as bf16 hi/lo
    const float i0 = 1.0f / l0s, i1 = 1.0f / l1s;
    const int b = bh >> 4, h = bh & 15;
    const size_t o0 = ((size_t)b * T_ + r0g) * C_ + h * 64 + 2 * (lane & 3);
    const size_t o1 = ((size_t)b * T_ + r1g) * C_ + h * 64 + 2 * (lane & 3);
#pragma unroll
    for (int j = 0; j < 8; j++) {
        __nv_bfloat162 lo;
        __nv_bfloat162 hi = split_hi2(accO[j][0] * i0, accO[j][1] * i0, &lo);
        *(__nv_bfloat162*)&Yh[o0 + 8 * j] = hi;
        *(__nv_bfloat162*)&Yl[o0 + 8 * j] = lo;
        hi = split_hi2(accO[j][2] * i1, accO[j][3] * i1, &lo);
        *(__nv_bfloat162*)&Yh[o1 + 8 * j] = hi;
        *(__nv_bfloat162*)&Yl[o1 + 8 * j] = lo;
    }
}

// ---------------------------------------------------------------------------
extern "C" void kernel_launch(void* const* d_in, const int* in_sizes, int n_in,
                              void* d_out, int out_size)
{
    const float* X  = (const float*)d_in[0];
    const float* Wq = (const float*)d_in[1];
    const float* Wk = (const float*)d_in[2];
    const float* Wv = (const float*)d_in[3];
    const float* Wo = (const float*)d_in[4];
    const float* bo = (const float*)d_in[5];
    float* out = (float*)d_out;

    __nv_bfloat16 *xh, *xl, *wh, *wl, *woh, *wol, *yh, *yl;
    __nv_bfloat16 *qh, *ql, *kh, *kl, *vh, *vl;
    cudaGetSymbolAddress((void**)&xh, g_Xhi);
    cudaGetSymbolAddress((void**)&xl, g_Xlo);
    cudaGetSymbolAddress((void**)&wh, g_Wh);
    cudaGetSymbolAddress((void**)&wl, g_Wl);
    cudaGetSymbolAddress((void**)&woh, g_Wohi);
    cudaGetSymbolAddress((void**)&wol, g_Wolo);
    cudaGetSymbolAddress((void**)&yh, g_Yhi);
    cudaGetSymbolAddress((void**)&yl, g_Ylo);
    cudaGetSymbolAddress((void**)&qh, g_Qhi);
    cudaGetSymbolAddress((void**)&ql, g_Qlo);
    cudaGetSymbolAddress((void**)&kh, g_Khi);
    cudaGetSymbolAddress((void**)&kl, g_Klo);
    cudaGetSymbolAddress((void**)&vh, g_Vhi);
    cudaGetSymbolAddress((void**)&vl, g_Vlo);

    // All hi/lo converts in ONE launch (X with MLP=2 + 4 weight matrices)
    cvt_all_kernel<<<XBLK + 4 * WBLK, 256>>>(
        X, Wq, Wk, Wv, Wo, xh, xl, wh, wl, woh, wol);

    // Zero the output for the split-K atomic epilogue (stream-ordered).
    cudaMemsetAsync(out, 0, (size_t)out_size * sizeof(float));

    // QKV projections (HMMA, 2 CTAs/SM) -> bf16 hi/lo split-head
    cudaFuncSetAttribute((const void*)tc_gemm_qkv,
                         cudaFuncAttributeMaxDynamicSharedMemorySize, G_SMEM);
    tc_gemm_qkv<<<dim3(C_ / 128, M_ / 128, 3), 256, G_SMEM>>>(
        xh, xl, wh, wl, qh, ql, kh, kl, vh, vl);

    // Attention (HMMA flash, 2 CTAs/SM) -> bf16 hi/lo Y
    cudaFuncSetAttribute((const void*)attn_hmma,
                         cudaFuncAttributeMaxDynamicSharedMemorySize, ATT_SMEM);
    attn_hmma<<<dim3(T_ / 128, B_ * H_), 256, ATT_SMEM>>>(qh, ql, kh, kl, vh, vl, yh, yl);

    // Output projection, split-K x2 (atomicAdd epilogue; bias in split 0)
    cudaFuncSetAttribute((const void*)tc_gemm_out,
                         cudaFuncAttributeMaxDynamicSharedMemorySize, G_SMEM);
    tc_gemm_out<<<dim3(C_ / 128, M_ / 128, 2), 256, G_SMEM>>>(
        yh, yl, woh, wol, bo, out);
}

// round 16
// speedup vs baseline: 1.1436x; 1.0141x over previous
#include <cuda_runtime.h>
#include <cuda_bf16.h>
#include <cstdint>

// Problem constants
#define B_ 4
#define T_ 2048
#define C_ 1024
#define H_ 16
#define D_ 64
#define M_ (B_ * T_)   // 8192 rows

// ---------------------------------------------------------------------------
// Scratch (allocation-free rule: __device__ globals)
// ---------------------------------------------------------------------------
__device__ __align__(16) __nv_bfloat16 g_Xhi[(size_t)M_ * C_];
__device__ __align__(16) __nv_bfloat16 g_Xlo[(size_t)M_ * C_];
__device__ __align__(16) __nv_bfloat16 g_Wh[(size_t)3 * C_ * C_];
__device__ __align__(16) __nv_bfloat16 g_Wl[(size_t)3 * C_ * C_];
__device__ __align__(16) __nv_bfloat16 g_Wohi[(size_t)C_ * C_];
__device__ __align__(16) __nv_bfloat16 g_Wolo[(size_t)C_ * C_];
__device__ __align__(16) __nv_bfloat16 g_Yhi[(size_t)M_ * C_];
__device__ __align__(16) __nv_bfloat16 g_Ylo[(size_t)M_ * C_];
__device__ __align__(16) __nv_bfloat16 g_Qhi[(size_t)B_ * H_ * T_ * D_];
__device__ __align__(16) __nv_bfloat16 g_Qlo[(size_t)B_ * H_ * T_ * D_];
__device__ __align__(16) __nv_bfloat16 g_Khi[(size_t)B_ * H_ * T_ * D_];
__device__ __align__(16) __nv_bfloat16 g_Klo[(size_t)B_ * H_ * T_ * D_];
__device__ __align__(16) __nv_bfloat16 g_Vhi[(size_t)B_ * H_ * T_ * D_];
__device__ __align__(16) __nv_bfloat16 g_Vlo[(size_t)B_ * H_ * T_ * D_];

// ---------------------------------------------------------------------------
// Helpers
// ---------------------------------------------------------------------------
__device__ __forceinline__ uint32_t smem_u32(const void* p) {
    uint32_t a;
    asm("{ .reg .u64 t; cvta.to.shared.u64 t, %1; cvt.u32.u64 %0, t; }"
        : "=r"(a) : "l"(p));
    return a;
}

#define CP_ASYNC16(dst, src) \
    asm volatile("cp.async.cg.shared.global [%0], [%1], 16;" \
                 :: "r"(dst), "l"(src) : "memory")
#define CP_COMMIT()  asm volatile("cp.async.commit_group;" ::: "memory")
#define CP_WAIT(n)   asm volatile("cp.async.wait_group %0;" :: "n"(n) : "memory")

#define LDSM_X4(r0, r1, r2, r3, addr) \
    asm volatile("ldmatrix.sync.aligned.m8n8.x4.shared.b16 {%0,%1,%2,%3}, [%4];" \
                 : "=r"(r0), "=r"(r1), "=r"(r2), "=r"(r3) : "r"(addr))

#define LDSM_X4_T(r0, r1, r2, r3, addr) \
    asm volatile("ldmatrix.sync.aligned.m8n8.x4.trans.shared.b16 {%0,%1,%2,%3}, [%4];" \
                 : "=r"(r0), "=r"(r1), "=r"(r2), "=r"(r3) : "r"(addr))

#define MMA16816(d, a, b0, b1) \
    asm volatile("mma.sync.aligned.m16n8k16.row.col.f32.bf16.bf16.f32 " \
                 "{%0,%1,%2,%3}, {%4,%5,%6,%7}, {%8,%9}, {%0,%1,%2,%3};" \
                 : "+f"((d)[0]), "+f"((d)[1]), "+f"((d)[2]), "+f"((d)[3]) \
                 : "r"((a)[0]), "r"((a)[1]), "r"((a)[2]), "r"((a)[3]), \
                   "r"(b0), "r"(b1))

// Pack two fp32 -> bf16x2 in one instruction.
__device__ __forceinline__ uint32_t cvt2_bf16(float lo, float hi) {
    uint32_t r;
    asm("cvt.rn.bf16x2.f32 %0, %1, %2;" : "=r"(r) : "f"(hi), "f"(lo));
    return r;
}

__device__ __forceinline__ __nv_bfloat162 split_hi2(float x, float y,
                                                    __nv_bfloat162* lo) {
    uint32_t h = cvt2_bf16(x, y);
    __nv_bfloat162 hv = *reinterpret_cast<__nv_bfloat162*>(&h);
    float xr = x - __low2float(hv);
    float yr = y - __high2float(hv);
    uint32_t l = cvt2_bf16(xr, yr);
    *lo = *reinterpret_cast<__nv_bfloat162*>(&l);
    return hv;
}

// ---------------------------------------------------------------------------
// fp32 -> bf16 hi/lo split + d_out zeroing, one fused launch.
// Blocks [0, XBLK): X with 2 independent chains (MLP=2).
// Blocks [XBLK, XBLK+4*WBLK): the four weight matrices.
// Blocks [XBLK+4*WBLK, ...): zero d_out (split-K atomic epilogue target).
// ---------------------------------------------------------------------------
__device__ __forceinline__
void cvt_body(const float* __restrict__ in, __nv_bfloat16* __restrict__ hi,
              __nv_bfloat16* __restrict__ lo, int i)
{
    float4 v = ((const float4*)in)[i];
    __nv_bfloat162 l01, l23;
    __nv_bfloat162 h01 = split_hi2(v.x, v.y, &l01);
    __nv_bfloat162 h23 = split_hi2(v.z, v.w, &l23);
    ((__nv_bfloat162*)hi)[2 * i]     = h01;
    ((__nv_bfloat162*)hi)[2 * i + 1] = h23;
    ((__nv_bfloat162*)lo)[2 * i]     = l01;
    ((__nv_bfloat162*)lo)[2 * i + 1] = l23;
}

#define XHALF (M_ * C_ / 8)          // 1048576 float4 slots per half
#define XBLK  (XHALF / 256)          // 4096 blocks for X
#define WBLK  (C_ * C_ / 4 / 256)    // 1024 blocks per weight
#define ZBLK  (M_ * C_ / 4 / 256)    // 8192 blocks to zero d_out

__global__ __launch_bounds__(256)
void cvt_all_kernel(const float* __restrict__ X,
                    const float* __restrict__ Wq, const float* __restrict__ Wk,
                    const float* __restrict__ Wv, const float* __restrict__ Wo,
                    __nv_bfloat16* __restrict__ xh, __nv_bfloat16* __restrict__ xl,
                    __nv_bfloat16* __restrict__ Wh, __nv_bfloat16* __restrict__ Wl,
                    __nv_bfloat16* __restrict__ Woh, __nv_bfloat16* __restrict__ Wol,
                    float* __restrict__ outz)
{
    const int blk = blockIdx.x;
    const int tid = threadIdx.x;
    if (blk < XBLK) {
        int i = blk * 256 + tid;
        cvt_body(X, xh, xl, i);
        cvt_body(X, xh, xl, i + XHALF);   // second independent chain (MLP=2)
    } else if (blk < XBLK + 4 * WBLK) {
        int r = blk - XBLK;
        int z = r >> 10;                   // WBLK == 1024
        int i = (r & (WBLK - 1)) * 256 + tid;
        const float* in = (z == 0) ? Wq : (z == 1) ? Wk : (z == 2) ? Wv : Wo;
        __nv_bfloat16* hi = (z < 3) ? (Wh + (size_t)z * C_ * C_) : Woh;
        __nv_bfloat16* lo = (z < 3) ? (Wl + (size_t)z * C_ * C_) : Wol;
        cvt_body(in, hi, lo, i);
    } else {
        int i = (blk - XBLK - 4 * WBLK) * 256 + tid;
        ((float4*)outz)[i] = make_float4(0.f, 0.f, 0.f, 0.f);
    }
}

// ---------------------------------------------------------------------------
// HMMA bf16 GEMM (extended-K hi/lo split), BM=128, BN=128, BK=64,
// 3-stage ring, one __syncthreads per chunk, 2 CTAs/SM.
// MODE 0: fp32 [M,N], atomicAdd epilogue (+ optional bias) — split-K capable.
// MODE 1: bf16 hi/lo split-head [b,h,t,d], full-K.
// ---------------------------------------------------------------------------
#define NKCH 48
#define STAGE_B 32768
#define G_SMEM (3 * STAGE_B)

__device__ __forceinline__
void issue_chunk(uint32_t sbase, const __nv_bfloat16* __restrict__ Aseg,
                 const __nv_bfloat16* __restrict__ Bseg,
                 int m0, int n0, int k_in, int t)
{
#pragma unroll
    for (int rep = 0; rep < 4; rep++) {
        int idx = t + rep * 256;
        int r = idx >> 3, s = idx & 7;
        uint32_t dstA = sbase + r * 128 + ((s ^ (r & 7)) << 4);
        CP_ASYNC16(dstA, (const void*)(Aseg + (size_t)(m0 + r) * C_ + k_in + s * 8));
        CP_ASYNC16(dstA + 16384,
                   (const void*)(Bseg + (size_t)(n0 + r) * C_ + k_in + s * 8));
    }
}

__device__ __forceinline__
void seg_sel(int kn, const __nv_bfloat16* Ahi, const __nv_bfloat16* Alo,
             const __nv_bfloat16* Whi, const __nv_bfloat16* Wlo,
             const __nv_bfloat16** Aseg, const __nv_bfloat16** Bseg)
{
    *Aseg = (kn < 32) ? Ahi : Alo;
    *Bseg = (kn < 16) ? Whi : (kn < 32 ? Wlo : Whi);
}

template <int MODE>
__device__ __forceinline__
void hmma_gemm_body(const __nv_bfloat16* __restrict__ Ahi,
                    const __nv_bfloat16* __restrict__ Alo,
                    const __nv_bfloat16* __restrict__ Whi,
                    const __nv_bfloat16* __restrict__ Wlo,
                    const float* __restrict__ bias, float* __restrict__ out,
                    __nv_bfloat16* __restrict__ ohi, __nv_bfloat16* __restrict__ olo,
                    int kn0, int nk)
{
    extern __shared__ __align__(128) char sm[];
    const uint32_t sm0 = smem_u32(sm);
    const int t    = threadIdx.x;
    const int lane = t & 31;
    const int w    = t >> 5;
    const int wm   = w & 3;             // m offset 32*wm
    const int wn   = w >> 2;            // n offset 64*wn
    const int m0   = blockIdx.y * 128;
    const int n0   = blockIdx.x * 128;

    const int l4 = lane >> 4;
    uint32_t baseA[2], baseB[4];
#pragma unroll
    for (int mt = 0; mt < 2; mt++) {
        int m_l = wm * 32 + mt * 16 + ((lane >> 3) & 1) * 8 + (lane & 7);
        baseA[mt] = m_l * 128 + (((m_l & 7) ^ l4) << 4);
    }
#pragma unroll
    for (int j = 0; j < 4; j++) {
        int n_l = wn * 64 + j * 16 + ((lane >> 3) & 1) * 8 + (lane & 7);
        baseB[j] = 16384 + n_l * 128 + (((n_l & 7) ^ l4) << 4);
    }

    float acc[2][8][4];
#pragma unroll
    for (int mt = 0; mt < 2; mt++)
#pragma unroll
        for (int nt = 0; nt < 8; nt++)
#pragma unroll
            for (int e = 0; e < 4; e++) acc[mt][nt][e] = 0.0f;

    // Prologue: chunks kn0, kn0+1 into stages 0, 1
    {
        const __nv_bfloat16 *As, *Bs;
        seg_sel(kn0, Ahi, Alo, Whi, Wlo, &As, &Bs);
        issue_chunk(sm0, As, Bs, m0, n0, (kn0 & 15) * 64, t);
        CP_COMMIT();
        seg_sel(kn0 + 1, Ahi, Alo, Whi, Wlo, &As, &Bs);
        issue_chunk(sm0 + STAGE_B, As, Bs, m0, n0, ((kn0 + 1) & 15) * 64, t);
        CP_COMMIT();
    }

    int st = 0;  // local chunk index % 3
    for (int kci = 0; kci < nk; kci++) {
        if (kci + 1 < nk) { CP_WAIT(1); } else { CP_WAIT(0); }
        __syncthreads();

        const uint32_t sbase = sm0 + st * STAGE_B;
#pragma unroll
        for (int kk = 0; kk < 4; kk++) {
            uint32_t a[2][4], b[4][4];
#pragma unroll
            for (int mt = 0; mt < 2; mt++)
                LDSM_X4(a[mt][0], a[mt][1], a[mt][2], a[mt][3],
                        sbase + (baseA[mt] ^ (kk << 5)));
#pragma unroll
            for (int j = 0; j < 4; j++)
                LDSM_X4(b[j][0], b[j][1], b[j][2], b[j][3],
                        sbase + (baseB[j] ^ (kk << 5)));
#pragma unroll
            for (int mt = 0; mt < 2; mt++)
#pragma unroll
                for (int nt = 0; nt < 8; nt++)
                    MMA16816(acc[mt][nt], a[mt],
                             b[nt >> 1][nt & 1], b[nt >> 1][(nt & 1) + 2]);
        }

        if (kci + 2 < nk) {
            const int kn = kn0 + kci + 2;
            int st2 = st + 2; if (st2 >= 3) st2 -= 3;
            const __nv_bfloat16 *As, *Bs;
            seg_sel(kn, Ahi, Alo, Whi, Wlo, &As, &Bs);
            issue_chunk(sm0 + st2 * STAGE_B, As, Bs, m0, n0, (kn & 15) * 64, t);
            CP_COMMIT();
        }
        if (++st == 3) st = 0;
    }

    // Epilogue
    const int qrow = lane >> 2;
    const int qcol = (lane & 3) * 2;
#pragma unroll
    for (int mt = 0; mt < 2; mt++) {
#pragma unroll
        for (int half = 0; half < 2; half++) {
            const int grow = m0 + wm * 32 + mt * 16 + half * 8 + qrow;
#pragma unroll
            for (int nt = 0; nt < 8; nt++) {
                const int gcol = n0 + wn * 64 + nt * 8 + qcol;
                float2 v = make_float2(acc[mt][nt][half * 2],
                                       acc[mt][nt][half * 2 + 1]);
                if (MODE == 0) {
                    if (bias) {
                        v.x += bias[gcol];
                        v.y += bias[gcol + 1];
                    }
                    float* po = &out[(size_t)grow * C_ + gcol];
                    atomicAdd(po,     v.x);
                    atomicAdd(po + 1, v.y);
                } else {
                    const int head = gcol >> 6, d = gcol & 63;
                    const int bb = grow >> 11, tt = grow & (T_ - 1);
                    size_t idx = (((size_t)bb * H_ + head) * T_ + tt) * D_ + d;
                    __nv_bfloat162 lo;
                    __nv_bfloat162 hi = split_hi2(v.x, v.y, &lo);
                    *(__nv_bfloat162*)&ohi[idx] = hi;
                    *(__nv_bfloat162*)&olo[idx] = lo;
                }
            }
        }
    }
}

__global__ __launch_bounds__(256, 2)
void tc_gemm_qkv(const __nv_bfloat16* __restrict__ Xhi,
                 const __nv_bfloat16* __restrict__ Xlo,
                 const __nv_bfloat16* __restrict__ Wh,
                 const __nv_bfloat16* __restrict__ Wl,
                 __nv_bfloat16* __restrict__ Qh, __nv_bfloat16* __restrict__ Ql,
                 __nv_bfloat16* __restrict__ Kh, __nv_bfloat16* __restrict__ Kl,
                 __nv_bfloat16* __restrict__ Vh, __nv_bfloat16* __restrict__ Vl)
{
    const int z = blockIdx.z;
    const __nv_bfloat16* wh = Wh + (size_t)z * C_ * C_;
    const __nv_bfloat16* wl = Wl + (size_t)z * C_ * C_;
    __nv_bfloat16* oh = (z == 0) ? Qh : (z == 1) ? Kh : Vh;
    __nv_bfloat16* ol = (z == 0) ? Ql : (z == 1) ? Kl : Vl;
    hmma_gemm_body<1>(Xhi, Xlo, wh, wl, nullptr, nullptr, oh, ol, 0, NKCH);
}

// Split-K x2 output projection (atomicAdd epilogue; bias in split 0).
__global__ __launch_bounds__(256, 2)
void tc_gemm_out(const __nv_bfloat16* __restrict__ Yhi,
                 const __nv_bfloat16* __restrict__ Ylo,
                 const __nv_bfloat16* __restrict__ Wh,
                 const __nv_bfloat16* __restrict__ Wl,
                 const float* __restrict__ bias, float* __restrict__ out)
{
    const int z = blockIdx.z;
    hmma_gemm_body<0>(Yhi, Ylo, Wh, Wl, z == 0 ? bias : nullptr, out,
                      nullptr, nullptr, z * (NKCH / 2), NKCH / 2);
}

// ---------------------------------------------------------------------------
// HMMA flash attention (causal). R13/R14 math, single-sync 2-stage KV loop:
//   [CP_WAIT(0); sync; issue(kc+1); compute(kc)]
// The issue into buffer (kc+1)&1 follows the sync proving all warps finished
// compute(kc-1) — the last reader of that buffer. Exactly one cp.async group
// (g_kc, issued one iteration earlier) is pending at each wait.
// ---------------------------------------------------------------------------
#define ATT_SMEM 98304
#define SCL 0.18033688f   // 0.125 * log2(e)

__device__ __forceinline__
void issue_kv(uint32_t dstbase,
              const __nv_bfloat16* __restrict__ Kh, const __nv_bfloat16* __restrict__ Kl,
              const __nv_bfloat16* __restrict__ Vh, const __nv_bfloat16* __restrict__ Vl,
              int kbase, int t)
{
#pragma unroll
    for (int rep = 0; rep < 2; rep++) {
        int idx = t + rep * 256;
        int r = idx >> 3, c = idx & 7;
        uint32_t dst = dstbase + r * 128 + ((c ^ (r & 7)) << 4);
        size_t g = (size_t)(kbase + r) * D_ + c * 8;
        CP_ASYNC16(dst,          (const void*)(Kh + g));
        CP_ASYNC16(dst + 8192,   (const void*)(Kl + g));
        CP_ASYNC16(dst + 16384,  (const void*)(Vh + g));
        CP_ASYNC16(dst + 24576,  (const void*)(Vl + g));
    }
}

__global__ __launch_bounds__(256, 2)
void attn_hmma(const __nv_bfloat16* __restrict__ Qhi, const __nv_bfloat16* __restrict__ Qlo,
               const __nv_bfloat16* __restrict__ Khi, const __nv_bfloat16* __restrict__ Klo,
               const __nv_bfloat16* __restrict__ Vhi, const __nv_bfloat16* __restrict__ Vlo,
               __nv_bfloat16* __restrict__ Yh, __nv_bfloat16* __restrict__ Yl)
{
    extern __shared__ __align__(128) char sm[];
    const uint32_t s0 = smem_u32(sm);
    const int t = threadIdx.x, lane = t & 31, w = t >> 5;
    const int bh = blockIdx.y;
    const int qi = (int)(gridDim.x - 1 - blockIdx.x);
    const int qbase = qi * 128;
    const size_t base = (size_t)bh * T_ * D_;
    const __nv_bfloat16* Qh = Qhi + base + (size_t)qbase * D_;
    const __nv_bfloat16* Ql = Qlo + base + (size_t)qbase * D_;
    const __nv_bfloat16* Kh = Khi + base;
    const __nv_bfloat16* Kl = Klo + base;
    const __nv_bfloat16* Vh = Vhi + base;
    const __nv_bfloat16* Vl = Vlo + base;

    // Prologue: Q tiles + KV chunk 0 (one group each)
#pragma unroll
    for (int rep = 0; rep < 4; rep++) {
        int idx = t + rep * 256;
        int r = idx >> 3, c = idx & 7;
        uint32_t dst = s0 + r * 128 + ((c ^ (r & 7)) << 4);
        size_t g = (size_t)r * D_ + c * 8;
        CP_ASYNC16(dst,          (const void*)(Qh + g));
        CP_ASYNC16(dst + 16384,  (const void*)(Ql + g));
    }
    CP_COMMIT();
    issue_kv(s0 + 32768, Kh, Kl, Vh, Vl, 0, t);
    CP_COMMIT();

    const int nch = 2 * qi + 2;

    float accO[8][4];
#pragma unroll
    for (int j = 0; j < 8; j++)
#pragma unroll
        for (int e = 0; e < 4; e++) accO[j][e] = 0.0f;

    float m0s = -1e30f, m1s = -1e30f, l0s = 0.0f, l1s = 0.0f;
    const int r0g = qbase + 16 * w + (lane >> 2);
    const int r1g = r0g + 8;

    for (int kc = 0; kc < nch; kc++) {
        const int kbase = kc * 64;
        const int stage = kc & 1;

        CP_WAIT(0);                 // g_kc landed (issued one iteration ago)
        __syncthreads();            // all warps done with buffer (kc+1)&1

        if (kc + 1 < nch) {         // prefetch next chunk, overlaps compute
            issue_kv(s0 + 32768 + (stage ^ 1) * 32768, Kh, Kl, Vh, Vl, kbase + 64, t);
            CP_COMMIT();
        }
        const uint32_t kvb = s0 + 32768 + stage * 32768;

        if (kbase <= qbase + 16 * w + 15) {
            // ---- S = Q @ K^T (16 x 64 per warp), 3-term split ----
            float sc[8][4];
#pragma unroll
            for (int j = 0; j < 8; j++)
#pragma unroll
                for (int e = 0; e < 4; e++) sc[j][e] = 0.0f;

#pragma unroll
            for (int s = 0; s < 4; s++) {
                uint32_t aQh[4], aQl[4];
                {
                    int row = 16 * w + (lane & 15);
                    int cb  = 2 * s + (lane >> 4);
                    uint32_t ad = s0 + row * 128 + ((cb ^ (row & 7)) << 4);
                    LDSM_X4(aQh[0], aQh[1], aQh[2], aQh[3], ad);
                    LDSM_X4(aQl[0], aQl[1], aQl[2], aQl[3], ad + 16384);
                }
#pragma unroll
                for (int hf = 0; hf < 2; hf++) {
                    uint32_t bKh[4][2], bKl[4][2];
#pragma unroll
                    for (int q = 0; q < 2; q++) {
                        int jp  = 2 * hf + q;
                        int row = 16 * jp + ((lane >> 4) << 3) + (lane & 7);
                        int cb  = 2 * s + ((lane >> 3) & 1);
                        uint32_t ad = kvb + row * 128 + ((cb ^ (row & 7)) << 4);
                        LDSM_X4(bKh[2*q][0], bKh[2*q][1], bKh[2*q+1][0], bKh[2*q+1][1], ad);
                        LDSM_X4(bKl[2*q][0], bKl[2*q][1], bKl[2*q+1][0], bKl[2*q+1][1], ad + 8192);
                    }
#pragma unroll
                    for (int jj = 0; jj < 4; jj++) {
                        int j = 4 * hf + jj;
                        MMA16816(sc[j], aQh, bKh[jj][0], bKh[jj][1]);
                        MMA16816(sc[j], aQh, bKl[jj][0], bKl[jj][1]);
                        MMA16816(sc[j], aQl, bKh[jj][0], bKh[jj][1]);
                    }
                }
            }

            // ---- scale into exp2 domain + causal mask ----
            const int c0b = kbase + 2 * (lane & 3);
#pragma unroll
            for (int j = 0; j < 8; j++) {
                int cc = c0b + 8 * j;
                sc[j][0] = (cc     > r0g) ? -1e30f : sc[j][0] * SCL;
                sc[j][1] = (cc + 1 > r0g) ? -1e30f : sc[j][1] * SCL;
                sc[j][2] = (cc     > r1g) ? -1e30f : sc[j][2] * SCL;
                sc[j][3] = (cc + 1 > r1g) ? -1e30f : sc[j][3] * SCL;
            }

            // ---- online softmax (warp-local quad reduction, exp2 domain) ----
            float mx0 = -1e30f, mx1 = -1e30f;
#pragma unroll
            for (int j = 0; j < 8; j++) {
                mx0 = fmaxf(mx0, fmaxf(sc[j][0], sc[j][1]));
                mx1 = fmaxf(mx1, fmaxf(sc[j][2], sc[j][3]));
            }
            mx0 = fmaxf(mx0, __shfl_xor_sync(0xffffffffu, mx0, 1));
            mx0 = fmaxf(mx0, __shfl_xor_sync(0xffffffffu, mx0, 2));
            mx1 = fmaxf(mx1, __shfl_xor_sync(0xffffffffu, mx1, 1));
            mx1 = fmaxf(mx1, __shfl_xor_sync(0xffffffffu, mx1, 2));
            float mn0 = fmaxf(m0s, mx0), mn1 = fmaxf(m1s, mx1);
            float cr0 = exp2f(m0s - mn0), cr1 = exp2f(m1s - mn1);
            m0s = mn0; m1s = mn1;

            float sum0 = 0.0f, sum1 = 0.0f;
            uint32_t aPh[4][4], aPl[4][4];
#pragma unroll
            for (int jp = 0; jp < 4; jp++) {
#pragma unroll
                for (int u = 0; u < 2; u++) {
                    int j = 2 * jp + u;
                    float p0 = exp2f(sc[j][0] - mn0);
                    float p1 = exp2f(sc[j][1] - mn0);
                    float p2 = exp2f(sc[j][2] - mn1);
                    float p3 = exp2f(sc[j][3] - mn1);
                    sum0 += p0 + p1;
                    sum1 += p2 + p3;
                    uint32_t hA = cvt2_bf16(p0, p1);
                    uint32_t hB = cvt2_bf16(p2, p3);
                    aPh[jp][2*u]     = hA;
                    aPh[jp][2*u + 1] = hB;
                    __nv_bfloat162 hA2 = *reinterpret_cast<__nv_bfloat162*>(&hA);
                    __nv_bfloat162 hB2 = *reinterpret_cast<__nv_bfloat162*>(&hB);
                    aPl[jp][2*u]     = cvt2_bf16(p0 - __low2float(hA2),
                                                 p1 - __high2float(hA2));
                    aPl[jp][2*u + 1] = cvt2_bf16(p2 - __low2float(hB2),
                                                 p3 - __high2float(hB2));
                }
            }
            sum0 += __shfl_xor_sync(0xffffffffu, sum0, 1);
            sum0 += __shfl_xor_sync(0xffffffffu, sum0, 2);
            sum1 += __shfl_xor_sync(0xffffffffu, sum1, 1);
            sum1 += __shfl_xor_sync(0xffffffffu, sum1, 2);
            l0s = l0s * cr0 + sum0;
            l1s = l1s * cr1 + sum1;

            // ---- rescale O, then O += P @ V (3-term split) ----
#pragma unroll
            for (int j = 0; j < 8; j++) {
                accO[j][0] *= cr0; accO[j][1] *= cr0;
                accO[j][2] *= cr1; accO[j][3] *= cr1;
            }

#pragma unroll
            for (int s = 0; s < 4; s++) {
#pragma unroll
                for (int hf = 0; hf < 2; hf++) {
                    uint32_t bVh[4][2], bVl[4][2];
#pragma unroll
                    for (int q = 0; q < 2; q++) {
                        int jp  = 2 * hf + q;
                        int row = 16 * s + ((lane >> 3) & 1) * 8 + (lane & 7);
                        int cb  = 2 * jp + (lane >> 4);
                        uint32_t ad = kvb + 16384 + row * 128 + ((cb ^ (row & 7)) << 4);
                        LDSM_X4_T(bVh[2*q][0], bVh[2*q][1], bVh[2*q+1][0], bVh[2*q+1][1], ad);
                        LDSM_X4_T(bVl[2*q][0], bVl[2*q][1], bVl[2*q+1][0], bVl[2*q+1][1], ad + 8192);
                    }
#pragma unroll
                    for (int jj = 0; jj < 4; jj++) {
                        int j = 4 * hf + jj;
                        MMA16816(accO[j], aPh[s], bVh[jj][0], bVh[jj][1]);
                        MMA16816(accO[j], aPh[s], bVl[jj][0], bVl[jj][1]);
                        MMA16816(accO[j], aPl[s], bVh[jj][0], bVh[jj][1]);
                    }
                }
            }
        }
    }

    // normalize + store as bf16 hi/lo
    const float i0 = 1.0f / l0s, i1 = 1.0f / l1s;
    const int b = bh >> 4, h = bh & 15;
    const size_t o0 = ((size_t)b * T_ + r0g) * C_ + h * 64 + 2 * (lane & 3);
    const size_t o1 = ((size_t)b * T_ + r1g) * C_ + h * 64 + 2 * (lane & 3);
#pragma unroll
    for (int j = 0; j < 8; j++) {
        __nv_bfloat162 lo;
        __nv_bfloat162 hi = split_hi2(accO[j][0] * i0, accO[j][1] * i0, &lo);
        *(__nv_bfloat162*)&Yh[o0 + 8 * j] = hi;
        *(__nv_bfloat162*)&Yl[o0 + 8 * j] = lo;
        hi = split_hi2(accO[j][2] * i1, accO[j][3] * i1, &lo);
        *(__nv_bfloat162*)&Yh[o1 + 8 * j] = hi;
        *(__nv_bfloat162*)&Yl[o1 + 8 * j] = lo;
    }
}

// ---------------------------------------------------------------------------
extern "C" void kernel_launch(void* const* d_in, const int* in_sizes, int n_in,
                              void* d_out, int out_size)
{
    const float* X  = (const float*)d_in[0];
    const float* Wq = (const float*)d_in[1];
    const float* Wk = (const float*)d_in[2];
    const float* Wv = (const float*)d_in[3];
    const float* Wo = (const float*)d_in[4];
    const float* bo = (const float*)d_in[5];
    float* out = (float*)d_out;

    __nv_bfloat16 *xh, *xl, *wh, *wl, *woh, *wol, *yh, *yl;
    __nv_bfloat16 *qh, *ql, *kh, *kl, *vh, *vl;
    cudaGetSymbolAddress((void**)&xh, g_Xhi);
    cudaGetSymbolAddress((void**)&xl, g_Xlo);
    cudaGetSymbolAddress((void**)&wh, g_Wh);
    cudaGetSymbolAddress((void**)&wl, g_Wl);
    cudaGetSymbolAddress((void**)&woh, g_Wohi);
    cudaGetSymbolAddress((void**)&wol, g_Wolo);
    cudaGetSymbolAddress((void**)&yh, g_Yhi);
    cudaGetSymbolAddress((void**)&yl, g_Ylo);
    cudaGetSymbolAddress((void**)&qh, g_Qhi);
    cudaGetSymbolAddress((void**)&ql, g_Qlo);
    cudaGetSymbolAddress((void**)&kh, g_Khi);
    cudaGetSymbolAddress((void**)&kl, g_Klo);
    cudaGetSymbolAddress((void**)&vh, g_Vhi);
    cudaGetSymbolAddress((void**)&vl, g_Vlo);

    // Converts + d_out zeroing in ONE launch
    cvt_all_kernel<<<XBLK + 4 * WBLK + ZBLK, 256>>>(
        X, Wq, Wk, Wv, Wo, xh, xl, wh, wl, woh, wol, out);

    // QKV projections (HMMA, 2 CTAs/SM) -> bf16 hi/lo split-head
    cudaFuncSetAttribute((const void*)tc_gemm_qkv,
                         cudaFuncAttributeMaxDynamicSharedMemorySize, G_SMEM);
    tc_gemm_qkv<<<dim3(C_ / 128, M_ / 128, 3), 256, G_SMEM>>>(
        xh, xl, wh, wl, qh, ql, kh, kl, vh, vl);

    // Attention (HMMA flash, 2 CTAs/SM, single-sync loop) -> bf16 hi/lo Y
    cudaFuncSetAttribute((const void*)attn_hmma,
                         cudaFuncAttributeMaxDynamicSharedMemorySize, ATT_SMEM);
    attn_hmma<<<dim3(T_ / 128, B_ * H_), 256, ATT_SMEM>>>(qh, ql, kh, kl, vh, vl, yh, yl);

    // Output projection, split-K x2 (atomicAdd epilogue; bias in split 0)
    cudaFuncSetAttribute((const void*)tc_gemm_out,
                         cudaFuncAttributeMaxDynamicSharedMemorySize, G_SMEM);
    tc_gemm_out<<<dim3(C_ / 128, M_ / 128, 2), 256, G_SMEM>>>(
        yh, yl, woh, wol, bo, out);
}

// round 17
// speedup vs baseline: 1.1537x; 1.0088x over previous
#include <cuda_runtime.h>
#include <cuda_bf16.h>
#include <cstdint>

// Problem constants
#define B_ 4
#define T_ 2048
#define C_ 1024
#define H_ 16
#define D_ 64
#define M_ (B_ * T_)   // 8192 rows

// ---------------------------------------------------------------------------
// Scratch (allocation-free rule: __device__ globals)
// ---------------------------------------------------------------------------
__device__ __align__(16) __nv_bfloat16 g_Xhi[(size_t)M_ * C_];
__device__ __align__(16) __nv_bfloat16 g_Xlo[(size_t)M_ * C_];
__device__ __align__(16) __nv_bfloat16 g_Wh[(size_t)3 * C_ * C_];
__device__ __align__(16) __nv_bfloat16 g_Wl[(size_t)3 * C_ * C_];
__device__ __align__(16) __nv_bfloat16 g_Wohi[(size_t)C_ * C_];
__device__ __align__(16) __nv_bfloat16 g_Wolo[(size_t)C_ * C_];
__device__ __align__(16) __nv_bfloat16 g_Yhi[(size_t)M_ * C_];
__device__ __align__(16) __nv_bfloat16 g_Ylo[(size_t)M_ * C_];
__device__ __align__(16) __nv_bfloat16 g_Qhi[(size_t)B_ * H_ * T_ * D_];
__device__ __align__(16) __nv_bfloat16 g_Qlo[(size_t)B_ * H_ * T_ * D_];
__device__ __align__(16) __nv_bfloat16 g_Khi[(size_t)B_ * H_ * T_ * D_];
__device__ __align__(16) __nv_bfloat16 g_Klo[(size_t)B_ * H_ * T_ * D_];
__device__ __align__(16) __nv_bfloat16 g_Vhi[(size_t)B_ * H_ * T_ * D_];
__device__ __align__(16) __nv_bfloat16 g_Vlo[(size_t)B_ * H_ * T_ * D_];

// ---------------------------------------------------------------------------
// Helpers
// ---------------------------------------------------------------------------
__device__ __forceinline__ uint32_t smem_u32(const void* p) {
    uint32_t a;
    asm("{ .reg .u64 t; cvta.to.shared.u64 t, %1; cvt.u32.u64 %0, t; }"
        : "=r"(a) : "l"(p));
    return a;
}

#define CP_ASYNC16(dst, src) \
    asm volatile("cp.async.cg.shared.global [%0], [%1], 16;" \
                 :: "r"(dst), "l"(src) : "memory")
#define CP_COMMIT()  asm volatile("cp.async.commit_group;" ::: "memory")
#define CP_WAIT(n)   asm volatile("cp.async.wait_group %0;" :: "n"(n) : "memory")

#define LDSM_X4(r0, r1, r2, r3, addr) \
    asm volatile("ldmatrix.sync.aligned.m8n8.x4.shared.b16 {%0,%1,%2,%3}, [%4];" \
                 : "=r"(r0), "=r"(r1), "=r"(r2), "=r"(r3) : "r"(addr))

#define LDSM_X4_T(r0, r1, r2, r3, addr) \
    asm volatile("ldmatrix.sync.aligned.m8n8.x4.trans.shared.b16 {%0,%1,%2,%3}, [%4];" \
                 : "=r"(r0), "=r"(r1), "=r"(r2), "=r"(r3) : "r"(addr))

#define MMA16816(d, a, b0, b1) \
    asm volatile("mma.sync.aligned.m16n8k16.row.col.f32.bf16.bf16.f32 " \
                 "{%0,%1,%2,%3}, {%4,%5,%6,%7}, {%8,%9}, {%0,%1,%2,%3};" \
                 : "+f"((d)[0]), "+f"((d)[1]), "+f"((d)[2]), "+f"((d)[3]) \
                 : "r"((a)[0]), "r"((a)[1]), "r"((a)[2]), "r"((a)[3]), \
                   "r"(b0), "r"(b1))

// Pack two fp32 -> bf16x2 in one instruction.
__device__ __forceinline__ uint32_t cvt2_bf16(float lo, float hi) {
    uint32_t r;
    asm("cvt.rn.bf16x2.f32 %0, %1, %2;" : "=r"(r) : "f"(hi), "f"(lo));
    return r;
}

__device__ __forceinline__ __nv_bfloat162 split_hi2(float x, float y,
                                                    __nv_bfloat162* lo) {
    uint32_t h = cvt2_bf16(x, y);
    __nv_bfloat162 hv = *reinterpret_cast<__nv_bfloat162*>(&h);
    float xr = x - __low2float(hv);
    float yr = y - __high2float(hv);
    uint32_t l = cvt2_bf16(xr, yr);
    *lo = *reinterpret_cast<__nv_bfloat162*>(&l);
    return hv;
}

// bf16x2 pair (hi, lo) as raw u32 for wide packing
__device__ __forceinline__ uint32_t split_u32(float x, float y, uint32_t* lo) {
    uint32_t h = cvt2_bf16(x, y);
    __nv_bfloat162 hv = *reinterpret_cast<__nv_bfloat162*>(&h);
    *lo = cvt2_bf16(x - __low2float(hv), y - __high2float(hv));
    return h;
}

// ---------------------------------------------------------------------------
// cvt v2: fp32 -> bf16 hi/lo, 8-float groups (2 float4 loads -> one 16B
// store each to hi and lo). 2 independent groups per thread (MLP=4 loads).
// Blocks [0, XB2): X.  [XB2, XB2+WB2): weights.  [.., +ZB2): zero d_out.
// ---------------------------------------------------------------------------
__device__ __forceinline__
void cvt8(const float* __restrict__ in, __nv_bfloat16* __restrict__ hi,
          __nv_bfloat16* __restrict__ lo, int g)   // g = 8-float group index
{
    float4 a = ((const float4*)in)[2 * g];
    float4 b = ((const float4*)in)[2 * g + 1];
    uint4 hv, lv;
    hv.x = split_u32(a.x, a.y, &lv.x);
    hv.y = split_u32(a.z, a.w, &lv.y);
    hv.z = split_u32(b.x, b.y, &lv.z);
    hv.w = split_u32(b.z, b.w, &lv.w);
    ((uint4*)hi)[g] = hv;
    ((uint4*)lo)[g] = lv;
}

#define XG    (M_ * C_ / 8)      // 1,048,576 groups in X
#define XGH   (XG / 2)
#define XB2   (XGH / 256)        // 2048 blocks
#define WGPW  (C_ * C_ / 8)      // 131,072 groups per weight
#define WGH   (WGPW / 2)
#define WB2   (4 * WGPW / 512)   // 1024 blocks (256 per weight)
#define ZF4   (M_ * C_ / 4)      // 2,097,152 float4 in d_out
#define ZH    (ZF4 / 2)
#define ZB2   (ZH / 256)         // 4096 blocks

__global__ __launch_bounds__(256)
void cvt_all_kernel(const float* __restrict__ X,
                    const float* __restrict__ Wq, const float* __restrict__ Wk,
                    const float* __restrict__ Wv, const float* __restrict__ Wo,
                    __nv_bfloat16* __restrict__ xh, __nv_bfloat16* __restrict__ xl,
                    __nv_bfloat16* __restrict__ Wh, __nv_bfloat16* __restrict__ Wl,
                    __nv_bfloat16* __restrict__ Woh, __nv_bfloat16* __restrict__ Wol,
                    float* __restrict__ outz)
{
    const int blk = blockIdx.x;
    const int tid = threadIdx.x;
    if (blk < XB2) {
        int g = blk * 256 + tid;
        cvt8(X, xh, xl, g);
        cvt8(X, xh, xl, g + XGH);
    } else if (blk < XB2 + WB2) {
        int r = blk - XB2;
        int z = r >> 8;                    // 256 blocks per weight
        int rb = r & 255;
        const float* in = (z == 0) ? Wq : (z == 1) ? Wk : (z == 2) ? Wv : Wo;
        __nv_bfloat16* hi = (z < 3) ? (Wh + (size_t)z * C_ * C_) : Woh;
        __nv_bfloat16* lo = (z < 3) ? (Wl + (size_t)z * C_ * C_) : Wol;
        int g = rb * 256 + tid;
        cvt8(in, hi, lo, g);
        cvt8(in, hi, lo, g + WGH);
    } else {
        int j = (blk - XB2 - WB2) * 256 + tid;
        float4 z4 = make_float4(0.f, 0.f, 0.f, 0.f);
        ((float4*)outz)[j]      = z4;
        ((float4*)outz)[j + ZH] = z4;
    }
}

// ---------------------------------------------------------------------------
// HMMA bf16 GEMM (extended-K hi/lo split), BM=128, BN=128, BK=64,
// 3-stage ring, one __syncthreads per chunk, 2 CTAs/SM.
// m0/n0 passed explicitly so callers can permute the grid.
// MODE 0: fp32 [M,N], atomicAdd epilogue (+ optional bias) — split-K capable.
// MODE 1: bf16 hi/lo split-head [b,h,t,d], full-K.
// ---------------------------------------------------------------------------
#define NKCH 48
#define STAGE_B 32768
#define G_SMEM (3 * STAGE_B)

__device__ __forceinline__
void issue_chunk(uint32_t sbase, const __nv_bfloat16* __restrict__ Aseg,
                 const __nv_bfloat16* __restrict__ Bseg,
                 int m0, int n0, int k_in, int t)
{
#pragma unroll
    for (int rep = 0; rep < 4; rep++) {
        int idx = t + rep * 256;
        int r = idx >> 3, s = idx & 7;
        uint32_t dstA = sbase + r * 128 + ((s ^ (r & 7)) << 4);
        CP_ASYNC16(dstA, (const void*)(Aseg + (size_t)(m0 + r) * C_ + k_in + s * 8));
        CP_ASYNC16(dstA + 16384,
                   (const void*)(Bseg + (size_t)(n0 + r) * C_ + k_in + s * 8));
    }
}

__device__ __forceinline__
void seg_sel(int kn, const __nv_bfloat16* Ahi, const __nv_bfloat16* Alo,
             const __nv_bfloat16* Whi, const __nv_bfloat16* Wlo,
             const __nv_bfloat16** Aseg, const __nv_bfloat16** Bseg)
{
    *Aseg = (kn < 32) ? Ahi : Alo;
    *Bseg = (kn < 16) ? Whi : (kn < 32 ? Wlo : Whi);
}

template <int MODE>
__device__ __forceinline__
void hmma_gemm_body(const __nv_bfloat16* __restrict__ Ahi,
                    const __nv_bfloat16* __restrict__ Alo,
                    const __nv_bfloat16* __restrict__ Whi,
                    const __nv_bfloat16* __restrict__ Wlo,
                    const float* __restrict__ bias, float* __restrict__ out,
                    __nv_bfloat16* __restrict__ ohi, __nv_bfloat16* __restrict__ olo,
                    int kn0, int nk, int m0, int n0)
{
    extern __shared__ __align__(128) char sm[];
    const uint32_t sm0 = smem_u32(sm);
    const int t    = threadIdx.x;
    const int lane = t & 31;
    const int w    = t >> 5;
    const int wm   = w & 3;             // m offset 32*wm
    const int wn   = w >> 2;            // n offset 64*wn

    const int l4 = lane >> 4;
    uint32_t baseA[2], baseB[4];
#pragma unroll
    for (int mt = 0; mt < 2; mt++) {
        int m_l = wm * 32 + mt * 16 + ((lane >> 3) & 1) * 8 + (lane & 7);
        baseA[mt] = m_l * 128 + (((m_l & 7) ^ l4) << 4);
    }
#pragma unroll
    for (int j = 0; j < 4; j++) {
        int n_l = wn * 64 + j * 16 + ((lane >> 3) & 1) * 8 + (lane & 7);
        baseB[j] = 16384 + n_l * 128 + (((n_l & 7) ^ l4) << 4);
    }

    float acc[2][8][4];
#pragma unroll
    for (int mt = 0; mt < 2; mt++)
#pragma unroll
        for (int nt = 0; nt < 8; nt++)
#pragma unroll
            for (int e = 0; e < 4; e++) acc[mt][nt][e] = 0.0f;

    // Prologue: chunks kn0, kn0+1 into stages 0, 1
    {
        const __nv_bfloat16 *As, *Bs;
        seg_sel(kn0, Ahi, Alo, Whi, Wlo, &As, &Bs);
        issue_chunk(sm0, As, Bs, m0, n0, (kn0 & 15) * 64, t);
        CP_COMMIT();
        seg_sel(kn0 + 1, Ahi, Alo, Whi, Wlo, &As, &Bs);
        issue_chunk(sm0 + STAGE_B, As, Bs, m0, n0, ((kn0 + 1) & 15) * 64, t);
        CP_COMMIT();
    }

    int st = 0;  // local chunk index % 3
    for (int kci = 0; kci < nk; kci++) {
        if (kci + 1 < nk) { CP_WAIT(1); } else { CP_WAIT(0); }
        __syncthreads();

        const uint32_t sbase = sm0 + st * STAGE_B;
#pragma unroll
        for (int kk = 0; kk < 4; kk++) {
            uint32_t a[2][4], b[4][4];
#pragma unroll
            for (int mt = 0; mt < 2; mt++)
                LDSM_X4(a[mt][0], a[mt][1], a[mt][2], a[mt][3],
                        sbase + (baseA[mt] ^ (kk << 5)));
#pragma unroll
            for (int j = 0; j < 4; j++)
                LDSM_X4(b[j][0], b[j][1], b[j][2], b[j][3],
                        sbase + (baseB[j] ^ (kk << 5)));
#pragma unroll
            for (int mt = 0; mt < 2; mt++)
#pragma unroll
                for (int nt = 0; nt < 8; nt++)
                    MMA16816(acc[mt][nt], a[mt],
                             b[nt >> 1][nt & 1], b[nt >> 1][(nt & 1) + 2]);
        }

        if (kci + 2 < nk) {
            const int kn = kn0 + kci + 2;
            int st2 = st + 2; if (st2 >= 3) st2 -= 3;
            const __nv_bfloat16 *As, *Bs;
            seg_sel(kn, Ahi, Alo, Whi, Wlo, &As, &Bs);
            issue_chunk(sm0 + st2 * STAGE_B, As, Bs, m0, n0, (kn & 15) * 64, t);
            CP_COMMIT();
        }
        if (++st == 3) st = 0;
    }

    // Epilogue
    const int qrow = lane >> 2;
    const int qcol = (lane & 3) * 2;
#pragma unroll
    for (int mt = 0; mt < 2; mt++) {
#pragma unroll
        for (int half = 0; half < 2; half++) {
            const int grow = m0 + wm * 32 + mt * 16 + half * 8 + qrow;
#pragma unroll
            for (int nt = 0; nt < 8; nt++) {
                const int gcol = n0 + wn * 64 + nt * 8 + qcol;
                float2 v = make_float2(acc[mt][nt][half * 2],
                                       acc[mt][nt][half * 2 + 1]);
                if (MODE == 0) {
                    if (bias) {
                        v.x += bias[gcol];
                        v.y += bias[gcol + 1];
                    }
                    float* po = &out[(size_t)grow * C_ + gcol];
                    atomicAdd(po,     v.x);
                    atomicAdd(po + 1, v.y);
                } else {
                    const int head = gcol >> 6, d = gcol & 63;
                    const int bb = grow >> 11, tt = grow & (T_ - 1);
                    size_t idx = (((size_t)bb * H_ + head) * T_ + tt) * D_ + d;
                    __nv_bfloat162 lo;
                    __nv_bfloat162 hi = split_hi2(v.x, v.y, &lo);
                    *(__nv_bfloat162*)&ohi[idx] = hi;
                    *(__nv_bfloat162*)&olo[idx] = lo;
                }
            }
        }
    }
}

// QKV: grid (3, N/128, M/128) — z-select on the FASTEST dim so the three
// CTAs sharing each X (A) tile are launch-adjacent and co-resident -> L2 hits.
__global__ __launch_bounds__(256, 2)
void tc_gemm_qkv(const __nv_bfloat16* __restrict__ Xhi,
                 const __nv_bfloat16* __restrict__ Xlo,
                 const __nv_bfloat16* __restrict__ Wh,
                 const __nv_bfloat16* __restrict__ Wl,
                 __nv_bfloat16* __restrict__ Qh, __nv_bfloat16* __restrict__ Ql,
                 __nv_bfloat16* __restrict__ Kh, __nv_bfloat16* __restrict__ Kl,
                 __nv_bfloat16* __restrict__ Vh, __nv_bfloat16* __restrict__ Vl)
{
    const int z = blockIdx.x;
    const __nv_bfloat16* wh = Wh + (size_t)z * C_ * C_;
    const __nv_bfloat16* wl = Wl + (size_t)z * C_ * C_;
    __nv_bfloat16* oh = (z == 0) ? Qh : (z == 1) ? Kh : Vh;
    __nv_bfloat16* ol = (z == 0) ? Ql : (z == 1) ? Kl : Vl;
    hmma_gemm_body<1>(Xhi, Xlo, wh, wl, nullptr, nullptr, oh, ol, 0, NKCH,
                      blockIdx.z * 128, blockIdx.y * 128);
}

// Split-K x2 output projection (atomicAdd epilogue; bias in split 0).
__global__ __launch_bounds__(256, 2)
void tc_gemm_out(const __nv_bfloat16* __restrict__ Yhi,
                 const __nv_bfloat16* __restrict__ Ylo,
                 const __nv_bfloat16* __restrict__ Wh,
                 const __nv_bfloat16* __restrict__ Wl,
                 const float* __restrict__ bias, float* __restrict__ out)
{
    const int z = blockIdx.z;
    hmma_gemm_body<0>(Yhi, Ylo, Wh, Wl, z == 0 ? bias : nullptr, out,
                      nullptr, nullptr, z * (NKCH / 2), NKCH / 2,
                      blockIdx.y * 128, blockIdx.x * 128);
}

// ---------------------------------------------------------------------------
// HMMA flash attention (causal). Unchanged from R16 (best measured config):
// 2 CTAs/SM, single-sync 2-stage KV loop, exp2 softmax, bf16x2 packing.
// ---------------------------------------------------------------------------
#define ATT_SMEM 98304
#define SCL 0.18033688f   // 0.125 * log2(e)

__device__ __forceinline__
void issue_kv(uint32_t dstbase,
              const __nv_bfloat16* __restrict__ Kh, const __nv_bfloat16* __restrict__ Kl,
              const __nv_bfloat16* __restrict__ Vh, const __nv_bfloat16* __restrict__ Vl,
              int kbase, int t)
{
#pragma unroll
    for (int rep = 0; rep < 2; rep++) {
        int idx = t + rep * 256;
        int r = idx >> 3, c = idx & 7;
        uint32_t dst = dstbase + r * 128 + ((c ^ (r & 7)) << 4);
        size_t g = (size_t)(kbase + r) * D_ + c * 8;
        CP_ASYNC16(dst,          (const void*)(Kh + g));
        CP_ASYNC16(dst + 8192,   (const void*)(Kl + g));
        CP_ASYNC16(dst + 16384,  (const void*)(Vh + g));
        CP_ASYNC16(dst + 24576,  (const void*)(Vl + g));
    }
}

__global__ __launch_bounds__(256, 2)
void attn_hmma(const __nv_bfloat16* __restrict__ Qhi, const __nv_bfloat16* __restrict__ Qlo,
               const __nv_bfloat16* __restrict__ Khi, const __nv_bfloat16* __restrict__ Klo,
               const __nv_bfloat16* __restrict__ Vhi, const __nv_bfloat16* __restrict__ Vlo,
               __nv_bfloat16* __restrict__ Yh, __nv_bfloat16* __restrict__ Yl)
{
    extern __shared__ __align__(128) char sm[];
    const uint32_t s0 = smem_u32(sm);
    const int t = threadIdx.x, lane = t & 31, w = t >> 5;
    const int bh = blockIdx.y;
    const int qi = (int)(gridDim.x - 1 - blockIdx.x);
    const int qbase = qi * 128;
    const size_t base = (size_t)bh * T_ * D_;
    const __nv_bfloat16* Qh = Qhi + base + (size_t)qbase * D_;
    const __nv_bfloat16* Ql = Qlo + base + (size_t)qbase * D_;
    const __nv_bfloat16* Kh = Khi + base;
    const __nv_bfloat16* Kl = Klo + base;
    const __nv_bfloat16* Vh = Vhi + base;
    const __nv_bfloat16* Vl = Vlo + base;

    // Prologue: Q tiles + KV chunk 0 (one group each)
#pragma unroll
    for (int rep = 0; rep < 4; rep++) {
        int idx = t + rep * 256;
        int r = idx >> 3, c = idx & 7;
        uint32_t dst = s0 + r * 128 + ((c ^ (r & 7)) << 4);
        size_t g = (size_t)r * D_ + c * 8;
        CP_ASYNC16(dst,          (const void*)(Qh + g));
        CP_ASYNC16(dst + 16384,  (const void*)(Ql + g));
    }
    CP_COMMIT();
    issue_kv(s0 + 32768, Kh, Kl, Vh, Vl, 0, t);
    CP_COMMIT();

    const int nch = 2 * qi + 2;

    float accO[8][4];
#pragma unroll
    for (int j = 0; j < 8; j++)
#pragma unroll
        for (int e = 0; e < 4; e++) accO[j][e] = 0.0f;

    float m0s = -1e30f, m1s = -1e30f, l0s = 0.0f, l1s = 0.0f;
    const int r0g = qbase + 16 * w + (lane >> 2);
    const int r1g = r0g + 8;

    for (int kc = 0; kc < nch; kc++) {
        const int kbase = kc * 64;
        const int stage = kc & 1;

        CP_WAIT(0);                 // g_kc landed (issued one iteration ago)
        __syncthreads();            // all warps done with buffer (kc+1)&1

        if (kc + 1 < nch) {         // prefetch next chunk, overlaps compute
            issue_kv(s0 + 32768 + (stage ^ 1) * 32768, Kh, Kl, Vh, Vl, kbase + 64, t);
            CP_COMMIT();
        }
        const uint32_t kvb = s0 + 32768 + stage * 32768;

        if (kbase <= qbase + 16 * w + 15) {
            // ---- S = Q @ K^T (16 x 64 per warp), 3-term split ----
            float sc[8][4];
#pragma unroll
            for (int j = 0; j < 8; j++)
#pragma unroll
                for (int e = 0; e < 4; e++) sc[j][e] = 0.0f;

#pragma unroll
            for (int s = 0; s < 4; s++) {
                uint32_t aQh[4], aQl[4];
                {
                    int row = 16 * w + (lane & 15);
                    int cb  = 2 * s + (lane >> 4);
                    uint32_t ad = s0 + row * 128 + ((cb ^ (row & 7)) << 4);
                    LDSM_X4(aQh[0], aQh[1], aQh[2], aQh[3], ad);
                    LDSM_X4(aQl[0], aQl[1], aQl[2], aQl[3], ad + 16384);
                }
#pragma unroll
                for (int hf = 0; hf < 2; hf++) {
                    uint32_t bKh[4][2], bKl[4][2];
#pragma unroll
                    for (int q = 0; q < 2; q++) {
                        int jp  = 2 * hf + q;
                        int row = 16 * jp + ((lane >> 4) << 3) + (lane & 7);
                        int cb  = 2 * s + ((lane >> 3) & 1);
                        uint32_t ad = kvb + row * 128 + ((cb ^ (row & 7)) << 4);
                        LDSM_X4(bKh[2*q][0], bKh[2*q][1], bKh[2*q+1][0], bKh[2*q+1][1], ad);
                        LDSM_X4(bKl[2*q][0], bKl[2*q][1], bKl[2*q+1][0], bKl[2*q+1][1], ad + 8192);
                    }
#pragma unroll
                    for (int jj = 0; jj < 4; jj++) {
                        int j = 4 * hf + jj;
                        MMA16816(sc[j], aQh, bKh[jj][0], bKh[jj][1]);
                        MMA16816(sc[j], aQh, bKl[jj][0], bKl[jj][1]);
                        MMA16816(sc[j], aQl, bKh[jj][0], bKh[jj][1]);
                    }
                }
            }

            // ---- scale into exp2 domain + causal mask ----
            const int c0b = kbase + 2 * (lane & 3);
#pragma unroll
            for (int j = 0; j < 8; j++) {
                int cc = c0b + 8 * j;
                sc[j][0] = (cc     > r0g) ? -1e30f : sc[j][0] * SCL;
                sc[j][1] = (cc + 1 > r0g) ? -1e30f : sc[j][1] * SCL;
                sc[j][2] = (cc     > r1g) ? -1e30f : sc[j][2] * SCL;
                sc[j][3] = (cc + 1 > r1g) ? -1e30f : sc[j][3] * SCL;
            }

            // ---- online softmax (warp-local quad reduction, exp2 domain) ----
            float mx0 = -1e30f, mx1 = -1e30f;
#pragma unroll
            for (int j = 0; j < 8; j++) {
                mx0 = fmaxf(mx0, fmaxf(sc[j][0], sc[j][1]));
                mx1 = fmaxf(mx1, fmaxf(sc[j][2], sc[j][3]));
            }
            mx0 = fmaxf(mx0, __shfl_xor_sync(0xffffffffu, mx0, 1));
            mx0 = fmaxf(mx0, __shfl_xor_sync(0xffffffffu, mx0, 2));
            mx1 = fmaxf(mx1, __shfl_xor_sync(0xffffffffu, mx1, 1));
            mx1 = fmaxf(mx1, __shfl_xor_sync(0xffffffffu, mx1, 2));
            float mn0 = fmaxf(m0s, mx0), mn1 = fmaxf(m1s, mx1);
            float cr0 = exp2f(m0s - mn0), cr1 = exp2f(m1s - mn1);
            m0s = mn0; m1s = mn1;

            float sum0 = 0.0f, sum1 = 0.0f;
            uint32_t aPh[4][4], aPl[4][4];
#pragma unroll
            for (int jp = 0; jp < 4; jp++) {
#pragma unroll
                for (int u = 0; u < 2; u++) {
                    int j = 2 * jp + u;
                    float p0 = exp2f(sc[j][0] - mn0);
                    float p1 = exp2f(sc[j][1] - mn0);
                    float p2 = exp2f(sc[j][2] - mn1);
                    float p3 = exp2f(sc[j][3] - mn1);
                    sum0 += p0 + p1;
                    sum1 += p2 + p3;
                    uint32_t hA = cvt2_bf16(p0, p1);
                    uint32_t hB = cvt2_bf16(p2, p3);
                    aPh[jp][2*u]     = hA;
                    aPh[jp][2*u + 1] = hB;
                    __nv_bfloat162 hA2 = *reinterpret_cast<__nv_bfloat162*>(&hA);
                    __nv_bfloat162 hB2 = *reinterpret_cast<__nv_bfloat162*>(&hB);
                    aPl[jp][2*u]     = cvt2_bf16(p0 - __low2float(hA2),
                                                 p1 - __high2float(hA2));
                    aPl[jp][2*u + 1] = cvt2_bf16(p2 - __low2float(hB2),
                                                 p3 - __high2float(hB2));
                }
            }
            sum0 += __shfl_xor_sync(0xffffffffu, sum0, 1);
            sum0 += __shfl_xor_sync(0xffffffffu, sum0, 2);
            sum1 += __shfl_xor_sync(0xffffffffu, sum1, 1);
            sum1 += __shfl_xor_sync(0xffffffffu, sum1, 2);
            l0s = l0s * cr0 + sum0;
            l1s = l1s * cr1 + sum1;

            // ---- rescale O, then O += P @ V (3-term split) ----
#pragma unroll
            for (int j = 0; j < 8; j++) {
                accO[j][0] *= cr0; accO[j][1] *= cr0;
                accO[j][2] *= cr1; accO[j][3] *= cr1;
            }

#pragma unroll
            for (int s = 0; s < 4; s++) {
#pragma unroll
                for (int hf = 0; hf < 2; hf++) {
                    uint32_t bVh[4][2], bVl[4][2];
#pragma unroll
                    for (int q = 0; q < 2; q++) {
                        int jp  = 2 * hf + q;
                        int row = 16 * s + ((lane >> 3) & 1) * 8 + (lane & 7);
                        int cb  = 2 * jp + (lane >> 4);
                        uint32_t ad = kvb + 16384 + row * 128 + ((cb ^ (row & 7)) << 4);
                        LDSM_X4_T(bVh[2*q][0], bVh[2*q][1], bVh[2*q+1][0], bVh[2*q+1][1], ad);
                        LDSM_X4_T(bVl[2*q][0], bVl[2*q][1], bVl[2*q+1][0], bVl[2*q+1][1], ad + 8192);
                    }
#pragma unroll
                    for (int jj = 0; jj < 4; jj++) {
                        int j = 4 * hf + jj;
                        MMA16816(accO[j], aPh[s], bVh[jj][0], bVh[jj][1]);
                        MMA16816(accO[j], aPh[s], bVl[jj][0], bVl[jj][1]);
                        MMA16816(accO[j], aPl[s], bVh[jj][0], bVh[jj][1]);
                    }
                }
            }
        }
    }

    // normalize + store as bf16 hi/lo
    const float i0 = 1.0f / l0s, i1 = 1.0f / l1s;
    const int b = bh >> 4, h = bh & 15;
    const size_t o0 = ((size_t)b * T_ + r0g) * C_ + h * 64 + 2 * (lane & 3);
    const size_t o1 = ((size_t)b * T_ + r1g) * C_ + h * 64 + 2 * (lane & 3);
#pragma unroll
    for (int j = 0; j < 8; j++) {
        __nv_bfloat162 lo;
        __nv_bfloat162 hi = split_hi2(accO[j][0] * i0, accO[j][1] * i0, &lo);
        *(__nv_bfloat162*)&Yh[o0 + 8 * j] = hi;
        *(__nv_bfloat162*)&Yl[o0 + 8 * j] = lo;
        hi = split_hi2(accO[j][2] * i1, accO[j][3] * i1, &lo);
        *(__nv_bfloat162*)&Yh[o1 + 8 * j] = hi;
        *(__nv_bfloat162*)&Yl[o1 + 8 * j] = lo;
    }
}

// ---------------------------------------------------------------------------
extern "C" void kernel_launch(void* const* d_in, const int* in_sizes, int n_in,
                              void* d_out, int out_size)
{
    const float* X  = (const float*)d_in[0];
    const float* Wq = (const float*)d_in[1];
    const float* Wk = (const float*)d_in[2];
    const float* Wv = (const float*)d_in[3];
    const float* Wo = (const float*)d_in[4];
    const float* bo = (const float*)d_in[5];
    float* out = (float*)d_out;

    __nv_bfloat16 *xh, *xl, *wh, *wl, *woh, *wol, *yh, *yl;
    __nv_bfloat16 *qh, *ql, *kh, *kl, *vh, *vl;
    cudaGetSymbolAddress((void**)&xh, g_Xhi);
    cudaGetSymbolAddress((void**)&xl, g_Xlo);
    cudaGetSymbolAddress((void**)&wh, g_Wh);
    cudaGetSymbolAddress((void**)&wl, g_Wl);
    cudaGetSymbolAddress((void**)&woh, g_Wohi);
    cudaGetSymbolAddress((void**)&wol, g_Wolo);
    cudaGetSymbolAddress((void**)&yh, g_Yhi);
    cudaGetSymbolAddress((void**)&yl, g_Ylo);
    cudaGetSymbolAddress((void**)&qh, g_Qhi);
    cudaGetSymbolAddress((void**)&ql, g_Qlo);
    cudaGetSymbolAddress((void**)&kh, g_Khi);
    cudaGetSymbolAddress((void**)&kl, g_Klo);
    cudaGetSymbolAddress((void**)&vh, g_Vhi);
    cudaGetSymbolAddress((void**)&vl, g_Vlo);

    // Converts + d_out zeroing in ONE launch (wide 8-float groups, MLP=4)
    cvt_all_kernel<<<XB2 + WB2 + ZB2, 256>>>(
        X, Wq, Wk, Wv, Wo, xh, xl, wh, wl, woh, wol, out);

    // QKV projections (HMMA, 2 CTAs/SM), z-select fastest for A-tile L2 reuse
    cudaFuncSetAttribute((const void*)tc_gemm_qkv,
                         cudaFuncAttributeMaxDynamicSharedMemorySize, G_SMEM);
    tc_gemm_qkv<<<dim3(3, C_ / 128, M_ / 128), 256, G_SMEM>>>(
        xh, xl, wh, wl, qh, ql, kh, kl, vh, vl);

    // Attention (HMMA flash, 2 CTAs/SM, single-sync loop) -> bf16 hi/lo Y
    cudaFuncSetAttribute((const void*)attn_hmma,
                         cudaFuncAttributeMaxDynamicSharedMemorySize, ATT_SMEM);
    attn_hmma<<<dim3(T_ / 128, B_ * H_), 256, ATT_SMEM>>>(qh, ql, kh, kl, vh, vl, yh, yl);

    // Output projection, split-K x2 (atomicAdd epilogue; bias in split 0)
    cudaFuncSetAttribute((const void*)tc_gemm_out,
                         cudaFuncAttributeMaxDynamicSharedMemorySize, G_SMEM);
    tc_gemm_out<<<dim3(C_ / 128, M_ / 128, 2), 256, G_SMEM>>>(
        yh, yl, woh, wol, bo, out);
}